// round 3
// baseline (speedup 1.0000x reference)
#include <cuda_runtime.h>

#define BB    32
#define NP    192
#define CC    128
#define NSS   36
#define MID   64
#define FCH   128
#define EPS   1e-5f
#define NTOT  (BB*NP)      // 6144
#define LL    250
#define KFC   (CC*NSS)     // 4608

typedef unsigned long long ull;

// ---------------- packed f32x2 helpers (FFMA2 only reachable via PTX) --------
__device__ __forceinline__ ull pk2dup(float v) {
    ull r; asm("mov.b64 %0, {%1,%1};" : "=l"(r) : "f"(v)); return r;
}
__device__ __forceinline__ void ffma2(ull& d, ull a, ull b) {
    asm("fma.rn.f32x2 %0, %1, %2, %0;" : "+l"(d) : "l"(a), "l"(b));
}
__device__ __forceinline__ float2 upk(ull v) {
    float2 r; asm("mov.b64 {%0,%1}, %2;" : "=f"(r.x), "=f"(r.y) : "l"(v)); return r;
}

// ---------------- scratch (device globals; no runtime allocation) -------------
__device__ float g_cat1[NTOT * 192 * NSS];   // level conv outputs, concatenated
__device__ float g_cat2[NTOT * CC * NSS];    // cat conv output
__device__ float g_roi [BB * NP * FCH];      // fc+LN+ReLU output
__device__ float g_k   [BB * CC * LL];       // keys   (b, f, l)
__device__ float g_v   [BB * LL * CC];       // values (b, l, f)
__device__ float g_fcwT[KFC * FCH];          // fc_w transposed (k, f)

// ---------------- fc_w transpose -------------------------------------------
__global__ void transpose_fcw(const float* __restrict__ w) {
    int idx = blockIdx.x * 256 + threadIdx.x;
    if (idx < FCH * KFC) {
        int f = idx % FCH, k = idx / FCH;
        g_fcwT[idx] = w[f * KFC + k];
    }
}

// ---------------- conv9 + folded BN + ReLU, packed f32x2 ---------------------
// out[n, c0+m, s] = relu( BN( sum_{ci,t} w[m,ci,t] * x[n,ci,s+t-4] ) )
// 512 threads. Block tile COUT x (NSAMP*36). Thread tile 4(M, as 2 pairs) x 9(N).
template<int CIN, int COUT, int NSAMP>
__global__ __launch_bounds__(512, 1)
void conv_bn_relu(const float* __restrict__ x, const float* __restrict__ w,
                  const float* __restrict__ bn_g, const float* __restrict__ bn_b,
                  const float* __restrict__ bn_m, const float* __restrict__ bn_v,
                  float* __restrict__ out, int out_cstride, int out_c0) {
    constexpr int TN  = NSAMP * 4;      // threads along N (32 or 16)
    constexpr int TM  = 512 / TN;       // threads along M (16 or 32)
    constexpr int MT  = COUT / TM;      // per-thread M tile
    static_assert(MT == 4, "tiling");
    constexpr int WST = COUT + 2;       // even pad -> 8B-aligned pairs, 2-way stage conflict

    __shared__ __align__(16) float w_s[72 * WST];    // [ci*9+t][m]
    __shared__ __align__(16) float x_s[NSAMP * 356]; // [samp][ci][44] padded window

    const int tid  = threadIdx.x;
    const int tn   = tid % TN, tm = tid / TN;
    const int samp = tn % NSAMP, sb = tn / NSAMP;    // sb in 0..3, 9 cols each
    const int n0   = blockIdx.x * NSAMP;

    for (int i = tid; i < NSAMP * 356; i += 512) x_s[i] = 0.f;   // pads stay zero

    ull acc[2][9];
#pragma unroll
    for (int p = 0; p < 2; p++)
#pragma unroll
        for (int j = 0; j < 9; j++) acc[p][j] = 0ull;

    const int xbase = samp * 356 + sb * 9;

    for (int kc = 0; kc < CIN / 8; kc++) {
        __syncthreads();
        // weights: global coalesced (inner fast), smem transposed [inner][m]
        for (int i = tid; i < COUT * 72; i += 512) {
            int m = i / 72, inner = i % 72;
            w_s[inner * WST + m] = w[m * CIN * 9 + kc * 72 + inner];
        }
        // inputs: data region only; +4 left pad offset
        for (int i = tid; i < NSAMP * 8 * 36; i += 512) {
            int s = i % 36, ci = (i / 36) % 8, sp = i / 288;
            x_s[sp * 356 + ci * 44 + s + 4] =
                x[((n0 + sp) * CIN + kc * 8 + ci) * 36 + s];
        }
        __syncthreads();

#pragma unroll 1
        for (int ci = 0; ci < 8; ci++) {
            ull wd[17];                  // sliding window, dup-packed once
#pragma unroll
            for (int k = 0; k < 17; k++) wd[k] = pk2dup(x_s[xbase + ci * 44 + k]);
#pragma unroll
            for (int t = 0; t < 9; t++) {
                const float* wp = &w_s[(ci * 9 + t) * WST + tm * MT];
                ull a0 = *(const ull*)(wp);       // m pair (broadcast LDS.64)
                ull a1 = *(const ull*)(wp + 2);
#pragma unroll
                for (int j = 0; j < 9; j++) {
                    ffma2(acc[0][j], a0, wd[t + j]);
                    ffma2(acc[1][j], a1, wd[t + j]);
                }
            }
        }
    }

    // epilogue: folded BN + ReLU
#pragma unroll
    for (int p = 0; p < 2; p++) {
        int mA = tm * MT + 2 * p, mB = mA + 1;
        float scA = bn_g[mA] * rsqrtf(bn_v[mA] + EPS);
        float biA = bn_b[mA] - bn_m[mA] * scA;
        float scB = bn_g[mB] * rsqrtf(bn_v[mB] + EPS);
        float biB = bn_b[mB] - bn_m[mB] * scB;
        float* oA = out + ((long)(n0 + samp) * out_cstride + out_c0 + mA) * 36 + sb * 9;
        float* oB = out + ((long)(n0 + samp) * out_cstride + out_c0 + mB) * 36 + sb * 9;
#pragma unroll
        for (int j = 0; j < 9; j++) {
            float2 v = upk(acc[p][j]);
            float a = fmaf(v.x, scA, biA);
            float b = fmaf(v.y, scB, biB);
            oA[j] = a > 0.f ? a : 0.f;
            oB[j] = b > 0.f ? b : 0.f;
        }
    }
}

// ---------------- FC (6144x128 <- K=4608) fused with LayerNorm + ReLU --------
__global__ __launch_bounds__(256, 2)
void fc_ln_relu(const float* __restrict__ fc_b, const float* __restrict__ ln_g,
                const float* __restrict__ ln_b) {
    __shared__ __align__(16) float A_s[32 * 66];   // [kk][m], even-pad stride
    __shared__ float B_s[32 * 128];                // [kk][f]
    const int tid = threadIdx.x;
    const int tn = tid % 16, tm = tid / 16;        // m = tm*4+mi, f = tn + 16*j
    const int n0 = blockIdx.x * 64;

    ull acc[2][8];
#pragma unroll
    for (int p = 0; p < 2; p++)
#pragma unroll
        for (int j = 0; j < 8; j++) acc[p][j] = 0ull;

    for (int k0 = 0; k0 < KFC; k0 += 32) {
        __syncthreads();
        for (int i = tid; i < 64 * 32; i += 256) {
            int kk = i % 32, mr = i / 32;
            A_s[kk * 66 + mr] = g_cat2[(n0 + mr) * KFC + k0 + kk];
        }
        for (int i = tid; i < 32 * 128; i += 256) {
            int f = i % 128, kk = i / 128;
            B_s[kk * 128 + f] = g_fcwT[(k0 + kk) * 128 + f];
        }
        __syncthreads();
#pragma unroll 4
        for (int kk = 0; kk < 32; kk++) {
            const float* ap = &A_s[kk * 66 + tm * 4];
            ull a0 = *(const ull*)(ap);
            ull a1 = *(const ull*)(ap + 2);
#pragma unroll
            for (int j = 0; j < 8; j++) {
                ull b = pk2dup(B_s[kk * 128 + tn + 16 * j]);
                ffma2(acc[0][j], a0, b);
                ffma2(acc[1][j], a1, b);
            }
        }
    }

    // unpack to per-row values
    float val[4][8];
#pragma unroll
    for (int p = 0; p < 2; p++)
#pragma unroll
        for (int j = 0; j < 8; j++) {
            float2 v = upk(acc[p][j]);
            val[2 * p][j] = v.x;
            val[2 * p + 1][j] = v.y;
        }

    // bias + LayerNorm (128 feats live in 16 lanes x 8 regs) + ReLU
#pragma unroll
    for (int mi = 0; mi < 4; mi++) {
        float sum = 0.f;
#pragma unroll
        for (int j = 0; j < 8; j++) {
            val[mi][j] += fc_b[tn + 16 * j];
            sum += val[mi][j];
        }
        for (int d = 8; d >= 1; d >>= 1) sum += __shfl_xor_sync(0xffffffffu, sum, d);
        float mean = sum * (1.f / 128.f);
        float sq = 0.f;
#pragma unroll
        for (int j = 0; j < 8; j++) {
            float dd = val[mi][j] - mean;
            sq += dd * dd;
        }
        for (int d = 8; d >= 1; d >>= 1) sq += __shfl_xor_sync(0xffffffffu, sq, d);
        float rstd = rsqrtf(sq * (1.f / 128.f) + EPS);
        int m = tm * 4 + mi;
#pragma unroll
        for (int j = 0; j < 8; j++) {
            int f = tn + 16 * j;
            float vv = (val[mi][j] - mean) * rstd * ln_g[f] + ln_b[f];
            g_roi[(n0 + m) * 128 + f] = fmaxf(vv, 0.f);
        }
    }
}

// ---------------- k/v at the 250 nearest-resize sample points ----------------
// sample (h,w) = (4r, 4c); l = r*25 + c.  k: BN+ReLU(key_w @ fmap), v: val_w@fmap+b
__global__ __launch_bounds__(256)
void kv_kernel(const float* __restrict__ fmap, const float* __restrict__ key_w,
               const float* __restrict__ key_g, const float* __restrict__ key_beta,
               const float* __restrict__ key_m, const float* __restrict__ key_v,
               const float* __restrict__ val_w, const float* __restrict__ val_b) {
    __shared__ float fc_s[25 * 129];
    const int b = blockIdx.x, r = blockIdx.y;
    const int tid = threadIdx.x;
    for (int i = tid; i < 25 * 128; i += 256) {
        int c = i / 25, pos = i % 25;
        fc_s[pos * 129 + c] = fmap[((b * 128 + c) * 40 + 4 * r) * 100 + 4 * pos];
    }
    __syncthreads();
    for (int i = tid; i < 25 * 128; i += 256) {
        int o = i % 128, pos = i / 128;
        const float* kw = key_w + o * 128;
        const float* vw = val_w + o * 128;
        float ka = 0.f, va = 0.f;
#pragma unroll 4
        for (int c = 0; c < 128; c++) {
            float xv = fc_s[pos * 129 + c];
            ka = fmaf(kw[c], xv, ka);
            va = fmaf(vw[c], xv, va);
        }
        float sc = key_g[o] * rsqrtf(key_v[o] + EPS);
        float kb = key_beta[o] - key_m[o] * sc;
        float kk = fmaf(ka, sc, kb);
        int l = r * 25 + pos;
        g_k[(b * 128 + o) * LL + l] = kk > 0.f ? kk : 0.f;
        g_v[(b * LL + l) * 128 + o] = va + val_b[o];
    }
}

// ---------------- attention: block = (b, 32 priors) --------------------------
__global__ __launch_bounds__(256)
void attn_kernel(const float* __restrict__ q_w, const float* __restrict__ q_b,
                 const float* __restrict__ gate_w, const float* __restrict__ gate_b,
                 float* __restrict__ out) {
    __shared__ float q_s[32 * 129];     // reused as v chunk later (needs 32*128)
    __shared__ float p_s[32 * 251];
    const int b = blockIdx.x, p0 = blockIdx.y * 32;
    const int tid = threadIdx.x;

    for (int i = tid; i < 32 * 128; i += 256) {
        int p = i / 128, f = i % 128;
        float qq = fmaf(g_roi[(b * NP + p0 + p) * 128 + f], q_w[p0 + p], q_b[p0 + p]);
        q_s[p * 129 + f] = qq > 0.f ? qq : 0.f;
    }
    __syncthreads();

    const float scale = 0.08838834764831845f;  // 128^-0.5
    for (int idx = tid; idx < 32 * LL; idx += 256) {
        int p = idx % 32, l = idx / 32;        // warp-uniform l -> broadcast k reads
        const float* krow = g_k + b * 128 * LL + l;
        float a = 0.f;
#pragma unroll 4
        for (int f = 0; f < 128; f++)
            a = fmaf(q_s[p * 129 + f], krow[f * LL], a);
        p_s[p * 251 + l] = a * scale;
    }
    __syncthreads();

    // softmax: each warp handles 4 rows
    const int warp = tid / 32, lane = tid % 32;
    for (int rr = 0; rr < 4; rr++) {
        int p = warp * 4 + rr;
        float mx = -1e30f;
        for (int l = lane; l < LL; l += 32) mx = fmaxf(mx, p_s[p * 251 + l]);
        for (int d = 16; d >= 1; d >>= 1) mx = fmaxf(mx, __shfl_xor_sync(~0u, mx, d));
        float sm = 0.f;
        for (int l = lane; l < LL; l += 32) {
            float e = __expf(p_s[p * 251 + l] - mx);
            p_s[p * 251 + l] = e;
            sm += e;
        }
        for (int d = 16; d >= 1; d >>= 1) sm += __shfl_xor_sync(~0u, sm, d);
        float inv = 1.f / sm;
        for (int l = lane; l < LL; l += 32) p_s[p * 251 + l] *= inv;
    }
    __syncthreads();

    // ctx = probs @ v  (v chunks staged in smem, reusing q_s area)
    float* v_s = q_s;
    float acc[16];
#pragma unroll
    for (int it = 0; it < 16; it++) acc[it] = 0.f;
    const int f = tid % 128, pb = tid / 128;   // p = pb + 2*it
    for (int lc = 0; lc < LL; lc += 32) {
        int lim = min(32, LL - lc);
        __syncthreads();
        for (int i = tid; i < lim * 128; i += 256)
            v_s[i] = g_v[(b * LL + lc + i / 128) * 128 + (i % 128)];
        __syncthreads();
#pragma unroll
        for (int it = 0; it < 16; it++) {
            int p = pb + 2 * it;
            float a = acc[it];
            for (int l = 0; l < lim; l++)
                a = fmaf(p_s[p * 251 + lc + l], v_s[l * 128 + f], a);
            acc[it] = a;
        }
    }
#pragma unroll
    for (int it = 0; it < 16; it++) {
        int gp = p0 + pb + 2 * it;
        float ctx = fmaf(acc[it], gate_w[gp], gate_b[gp]);
        out[(b * NP + gp) * 128 + f] = g_roi[(b * NP + gp) * 128 + f] + ctx;
    }
}

// ---------------- host launcher ---------------------------------------------
extern "C" void kernel_launch(void* const* d_in, const int* in_sizes, int n_in,
                              void* d_out, int out_size) {
    (void)in_sizes; (void)n_in; (void)out_size;
    const float* roi0   = (const float*)d_in[0];
    const float* roi1   = (const float*)d_in[1];
    const float* roi2   = (const float*)d_in[2];
    const float* fmap   = (const float*)d_in[3];
    const float* conv_w = (const float*)d_in[4];
    const float* conv_g = (const float*)d_in[5];
    const float* conv_b = (const float*)d_in[6];
    const float* conv_m = (const float*)d_in[7];
    const float* conv_v = (const float*)d_in[8];
    const float* cat_w  = (const float*)d_in[9];
    const float* cat_g  = (const float*)d_in[10];
    const float* cat_b  = (const float*)d_in[11];
    const float* cat_m  = (const float*)d_in[12];
    const float* cat_v  = (const float*)d_in[13];
    const float* fc_w   = (const float*)d_in[14];
    const float* fc_b   = (const float*)d_in[15];
    const float* ln_g   = (const float*)d_in[16];
    const float* ln_b   = (const float*)d_in[17];
    const float* key_w  = (const float*)d_in[18];
    const float* key_g  = (const float*)d_in[19];
    const float* key_bt = (const float*)d_in[20];
    const float* key_m  = (const float*)d_in[21];
    const float* key_v  = (const float*)d_in[22];
    const float* q_w    = (const float*)d_in[23];
    const float* q_b    = (const float*)d_in[24];
    const float* val_w  = (const float*)d_in[25];
    const float* val_b  = (const float*)d_in[26];
    const float* gate_w = (const float*)d_in[27];
    const float* gate_b = (const float*)d_in[28];
    float* out = (float*)d_out;

    float *cat1, *cat2;
    cudaGetSymbolAddress((void**)&cat1, g_cat1);
    cudaGetSymbolAddress((void**)&cat2, g_cat2);

    transpose_fcw<<<(FCH * KFC + 255) / 256, 256>>>(fc_w);

    // three level convs -> g_cat1 channels [lvl*64, lvl*64+64)
    for (int lvl = 0; lvl < 3; lvl++) {
        const float* x = (lvl == 0) ? roi0 : (lvl == 1) ? roi1 : roi2;
        conv_bn_relu<128, 64, 8><<<NTOT / 8, 512>>>(
            x, conv_w + lvl * 64 * 128 * 9,
            conv_g + lvl * 64, conv_b + lvl * 64, conv_m + lvl * 64, conv_v + lvl * 64,
            cat1, 192, lvl * 64);
    }
    // cat conv -> g_cat2
    conv_bn_relu<192, 128, 4><<<NTOT / 4, 512>>>(
        cat1, cat_w, cat_g, cat_b, cat_m, cat_v, cat2, 128, 0);

    fc_ln_relu<<<NTOT / 64, 256>>>(fc_b, ln_g, ln_b);

    kv_kernel<<<dim3(BB, 10), 256>>>(fmap, key_w, key_g, key_bt, key_m, key_v,
                                     val_w, val_b);

    attn_kernel<<<dim3(BB, NP / 32), 256>>>(q_w, q_b, gate_w, gate_b, out);
}

// round 5
// speedup vs baseline: 1.7956x; 1.7956x over previous
#include <cuda_runtime.h>
#include <cstdint>

#define BB    32
#define NP    192
#define CC    128
#define NSS   36
#define FCH   128
#define EPS   1e-5f
#define NTOT  (BB*NP)      // 6144
#define LL    250
#define KFC   (CC*NSS)     // 4608

// ---------------- scratch (device globals; no runtime allocation) -------------
__device__ float g_cat1[NTOT * 192 * NSS];   // level conv outputs, concatenated
__device__ float g_cat2[NTOT * CC * NSS];    // cat conv output
__device__ float g_roi [BB * NP * FCH];      // fc+LN+ReLU output
__device__ float g_k   [BB * CC * LL];       // keys   (b, f, l)
__device__ float g_v   [BB * LL * CC];       // values (b, l, f)
__device__ float g_fcwT[KFC * FCH];          // fc_w transposed (k, f)

// ---------------- helpers ----------------------------------------------------
__device__ __forceinline__ uint32_t cvt_tf32(float f) {
    uint32_t u; asm("cvt.rna.tf32.f32 %0, %1;" : "=r"(u) : "f"(f)); return u;
}
__device__ __forceinline__ void mma_tf32(float* c, const uint32_t* a,
                                         uint32_t b0, uint32_t b1) {
    asm volatile("mma.sync.aligned.m16n8k8.row.col.f32.tf32.tf32.f32 "
                 "{%0,%1,%2,%3}, {%4,%5,%6,%7}, {%8,%9}, {%0,%1,%2,%3};"
                 : "+f"(c[0]), "+f"(c[1]), "+f"(c[2]), "+f"(c[3])
                 : "r"(a[0]), "r"(a[1]), "r"(a[2]), "r"(a[3]), "r"(b0), "r"(b1));
}

// ---------------- conv9 + folded BN + ReLU via tf32 mma.sync ------------------
// GEMM: A = weights (M=COUT), B = im2col (N = NSAMP*36 padded to 40, K = CIN*9).
// K chunked by 72 (8 ci x 9 taps). Warp tile: 64 rows x 40 cols.
// Level: NSAMP=16, warp w -> sample w.  Cat: NSAMP=8, warp w -> (co-half, sample).
template<int CIN, int COUT, int NSAMP, int CSTRIDE>
__global__ __launch_bounds__(512, 1)
void conv_mma(const float* __restrict__ x0, const float* __restrict__ x1,
              const float* __restrict__ x2, const float* __restrict__ w_, int wstride,
              const float* __restrict__ bng, const float* __restrict__ bnb,
              const float* __restrict__ bnm, const float* __restrict__ bnv,
              float* __restrict__ out) {
    constexpr int NCH = CIN * 9 / 72;        // K chunks (16 or 24)
    constexpr int MT  = COUT / 16;           // m16 tiles in CTA (4 or 8)
    constexpr int NWM = MT / 4;              // warps along M (1 or 2)
    constexpr int SSTR = 8 * 44;             // sample stride in x_s (floats)

    __shared__ uint32_t w_s[MT * 9 * 32 * 4];   // fragment-major weights, one chunk
    __shared__ uint32_t x_s[NSAMP * SSTR];      // raw padded windows, 8-ci chunk

    const int tid  = threadIdx.x;
    const int wid  = tid >> 5, lane = tid & 31;
    const int lvl  = blockIdx.y;
    const float* x = (lvl == 0) ? x0 : (lvl == 1) ? x1 : x2;
    const float* w = w_ + (size_t)lvl * wstride;
    const int c0   = lvl * COUT;
    bng += lvl * COUT; bnb += lvl * COUT; bnm += lvl * COUT; bnv += lvl * COUT;

    const int samp = wid / NWM;                  // warp's sample
    const int mt0  = (wid % NWM) * 4;            // warp's first m16 tile
    const int n0   = blockIdx.x * NSAMP;
    const int sampbase = samp * SSTR;

    // zero x_s once (pads stay zero; data region overwritten per chunk)
    for (int i = tid; i < NSAMP * SSTR; i += 512) x_s[i] = 0u;

    // clamped column offsets (cols 36..39 are padding -> clamp inside window)
    int col[5];
#pragma unroll
    for (int nt = 0; nt < 5; nt++) {
        int cb = nt * 8 + (lane >> 2);
        col[nt] = cb < 36 ? cb : 35;
    }

    float acc[4][5][4];
#pragma unroll
    for (int mt = 0; mt < 4; mt++)
#pragma unroll
        for (int nt = 0; nt < 5; nt++)
#pragma unroll
            for (int j = 0; j < 4; j++) acc[mt][nt][j] = 0.f;

    for (int kc = 0; kc < NCH; kc++) {
        const int k0 = kc * 72, ci0 = kc * 8;
        __syncthreads();
        // stage weights, fragment-permuted: thread's LDS.128 slot layout
        for (int e = tid; e < COUT * 72; e += 512) {
            int m = e / 72, kk = e % 72;
            int mt = m >> 4, r = m & 15, k8 = kk >> 3, kcq = kk & 7;
            int ln = ((r & 7) << 2) | (kcq & 3);
            int j  = (r >> 3) | ((kcq >> 2) << 1);
            w_s[(((k8 * MT + mt) * 32 + ln) << 2) | j] =
                cvt_tf32(w[(size_t)m * (CIN * 9) + k0 + kk]);
        }
        // stage raw x windows (data region [4..39] of each 44-wide row)
        for (int e = tid; e < NSAMP * 8 * 36; e += 512) {
            int s = e % 36, ci = (e / 36) & 7, sp = e / 288;
            x_s[sp * SSTR + ci * 44 + 4 + s] =
                cvt_tf32(x[((size_t)(n0 + sp) * CIN + ci0 + ci) * 36 + s]);
        }
        __syncthreads();

#pragma unroll
        for (int k8 = 0; k8 < 9; k8++) {
            uint32_t a[4][4];
#pragma unroll
            for (int mt = 0; mt < 4; mt++)
                *(uint4*)a[mt] =
                    *(const uint4*)&w_s[((k8 * MT + mt0 + mt) * 32 + lane) << 2];
            int klo = k8 * 8 + (lane & 3), khi = klo + 4;
            int cilo = (klo * 57) >> 9, cihi = (khi * 57) >> 9;   // /9 for 0..71
            int blo = sampbase + cilo * 44 + (klo - cilo * 9);
            int bhi = sampbase + cihi * 44 + (khi - cihi * 9);
#pragma unroll
            for (int nt = 0; nt < 5; nt++) {
                uint32_t b0 = x_s[blo + col[nt]];
                uint32_t b1 = x_s[bhi + col[nt]];
#pragma unroll
                for (int mt = 0; mt < 4; mt++)
                    mma_tf32(acc[mt][nt], a[mt], b0, b1);
            }
        }
    }

    // epilogue: folded BN + ReLU; c layout row=lane/4(+8), col=2*(lane%3)+{0,1}
    const int nidx = n0 + samp;
#pragma unroll
    for (int mt = 0; mt < 4; mt++) {
        int cobase = (mt0 + mt) * 16 + (lane >> 2);
#pragma unroll
        for (int h = 0; h < 2; h++) {
            int co = cobase + 8 * h;
            float sc = bng[co] * rsqrtf(bnv[co] + EPS);
            float bi = bnb[co] - bnm[co] * sc;
            float* orow = out + ((size_t)nidx * CSTRIDE + c0 + co) * 36;
#pragma unroll
            for (int nt = 0; nt < 5; nt++) {
                int s0 = nt * 8 + 2 * (lane & 3);
                if (s0 < 36) {
                    float v0 = fmaf(acc[mt][nt][2 * h], sc, bi);
                    float v1 = fmaf(acc[mt][nt][2 * h + 1], sc, bi);
                    float2 vv = make_float2(v0 > 0.f ? v0 : 0.f, v1 > 0.f ? v1 : 0.f);
                    *(float2*)(orow + s0) = vv;
                }
            }
        }
    }
}

// ---------------- fc_w transpose ---------------------------------------------
__global__ void transpose_fcw(const float* __restrict__ w) {
    int idx = blockIdx.x * 256 + threadIdx.x;
    if (idx < FCH * KFC) {
        int f = idx % FCH, k = idx / FCH;
        g_fcwT[idx] = w[f * KFC + k];
    }
}

// ---------------- FC (6144x128 <- K=4608) fused with LayerNorm + ReLU --------
__global__ __launch_bounds__(256, 2)
void fc_ln_relu(const float* __restrict__ fc_b, const float* __restrict__ ln_g,
                const float* __restrict__ ln_b) {
    __shared__ float A_s[64 * 33];
    __shared__ float B_s[32 * 128];
    const int tid = threadIdx.x;
    const int tn = tid % 16, tm = tid / 16;
    const int n0 = blockIdx.x * 64;

    float acc[4][8];
#pragma unroll
    for (int a = 0; a < 4; a++)
#pragma unroll
        for (int j = 0; j < 8; j++) acc[a][j] = 0.f;

    for (int k0 = 0; k0 < KFC; k0 += 32) {
        __syncthreads();
        for (int i = tid; i < 64 * 32; i += 256) {
            int kk = i % 32, mr = i / 32;
            A_s[mr * 33 + kk] = g_cat2[(n0 + mr) * KFC + k0 + kk];
        }
        for (int i = tid; i < 32 * 128; i += 256) {
            int f = i % 128, kk = i / 128;
            B_s[kk * 128 + f] = g_fcwT[(k0 + kk) * 128 + f];
        }
        __syncthreads();
#pragma unroll 4
        for (int kk = 0; kk < 32; kk++) {
            float a[4], b[8];
#pragma unroll
            for (int mi = 0; mi < 4; mi++) a[mi] = A_s[(tm * 4 + mi) * 33 + kk];
#pragma unroll
            for (int j = 0; j < 8; j++) b[j] = B_s[kk * 128 + tn + 16 * j];
#pragma unroll
            for (int mi = 0; mi < 4; mi++)
#pragma unroll
                for (int j = 0; j < 8; j++)
                    acc[mi][j] = fmaf(a[mi], b[j], acc[mi][j]);
        }
    }

#pragma unroll
    for (int mi = 0; mi < 4; mi++) {
        float sum = 0.f;
#pragma unroll
        for (int j = 0; j < 8; j++) {
            acc[mi][j] += fc_b[tn + 16 * j];
            sum += acc[mi][j];
        }
        for (int d = 8; d >= 1; d >>= 1) sum += __shfl_xor_sync(0xffffffffu, sum, d);
        float mean = sum * (1.f / 128.f);
        float sq = 0.f;
#pragma unroll
        for (int j = 0; j < 8; j++) {
            float dd = acc[mi][j] - mean;
            sq += dd * dd;
        }
        for (int d = 8; d >= 1; d >>= 1) sq += __shfl_xor_sync(0xffffffffu, sq, d);
        float rstd = rsqrtf(sq * (1.f / 128.f) + EPS);
        int m = tm * 4 + mi;
#pragma unroll
        for (int j = 0; j < 8; j++) {
            int f = tn + 16 * j;
            float val = (acc[mi][j] - mean) * rstd * ln_g[f] + ln_b[f];
            g_roi[(n0 + m) * 128 + f] = fmaxf(val, 0.f);
        }
    }
}

// ---------------- k/v at the 250 nearest-resize sample points ----------------
__global__ __launch_bounds__(256)
void kv_kernel(const float* __restrict__ fmap, const float* __restrict__ key_w,
               const float* __restrict__ key_g, const float* __restrict__ key_beta,
               const float* __restrict__ key_m, const float* __restrict__ key_v,
               const float* __restrict__ val_w, const float* __restrict__ val_b) {
    __shared__ float fc_s[25 * 129];
    const int b = blockIdx.x, r = blockIdx.y;
    const int tid = threadIdx.x;
    for (int i = tid; i < 25 * 128; i += 256) {
        int c = i / 25, pos = i % 25;
        fc_s[pos * 129 + c] = fmap[((b * 128 + c) * 40 + 4 * r) * 100 + 4 * pos];
    }
    __syncthreads();
    for (int i = tid; i < 25 * 128; i += 256) {
        int o = i % 128, pos = i / 128;
        const float* kw = key_w + o * 128;
        const float* vw = val_w + o * 128;
        float ka = 0.f, va = 0.f;
#pragma unroll 4
        for (int c = 0; c < 128; c++) {
            float xv = fc_s[pos * 129 + c];
            ka = fmaf(kw[c], xv, ka);
            va = fmaf(vw[c], xv, va);
        }
        float sc = key_g[o] * rsqrtf(key_v[o] + EPS);
        float kb = key_beta[o] - key_m[o] * sc;
        float kk = fmaf(ka, sc, kb);
        int l = r * 25 + pos;
        g_k[(b * 128 + o) * LL + l] = kk > 0.f ? kk : 0.f;
        g_v[(b * LL + l) * 128 + o] = va + val_b[o];
    }
}

// ---------------- attention: block = (b, 32 priors) --------------------------
__global__ __launch_bounds__(256)
void attn_kernel(const float* __restrict__ q_w, const float* __restrict__ q_b,
                 const float* __restrict__ gate_w, const float* __restrict__ gate_b,
                 float* __restrict__ out) {
    __shared__ float q_s[32 * 129];
    __shared__ float p_s[32 * 251];
    const int b = blockIdx.x, p0 = blockIdx.y * 32;
    const int tid = threadIdx.x;

    for (int i = tid; i < 32 * 128; i += 256) {
        int p = i / 128, f = i % 128;
        float qq = fmaf(g_roi[(b * NP + p0 + p) * 128 + f], q_w[p0 + p], q_b[p0 + p]);
        q_s[p * 129 + f] = qq > 0.f ? qq : 0.f;
    }
    __syncthreads();

    const float scale = 0.08838834764831845f;
    for (int idx = tid; idx < 32 * LL; idx += 256) {
        int p = idx % 32, l = idx / 32;
        const float* krow = g_k + b * 128 * LL + l;
        float a = 0.f;
#pragma unroll 4
        for (int f = 0; f < 128; f++)
            a = fmaf(q_s[p * 129 + f], krow[f * LL], a);
        p_s[p * 251 + l] = a * scale;
    }
    __syncthreads();

    const int warp = tid / 32, lane = tid % 32;
    for (int rr = 0; rr < 4; rr++) {
        int p = warp * 4 + rr;
        float mx = -1e30f;
        for (int l = lane; l < LL; l += 32) mx = fmaxf(mx, p_s[p * 251 + l]);
        for (int d = 16; d >= 1; d >>= 1) mx = fmaxf(mx, __shfl_xor_sync(~0u, mx, d));
        float sm = 0.f;
        for (int l = lane; l < LL; l += 32) {
            float e = __expf(p_s[p * 251 + l] - mx);
            p_s[p * 251 + l] = e;
            sm += e;
        }
        for (int d = 16; d >= 1; d >>= 1) sm += __shfl_xor_sync(~0u, sm, d);
        float inv = 1.f / sm;
        for (int l = lane; l < LL; l += 32) p_s[p * 251 + l] *= inv;
    }
    __syncthreads();

    float* v_s = q_s;
    float acc[16];
#pragma unroll
    for (int it = 0; it < 16; it++) acc[it] = 0.f;
    const int f = tid % 128, pb = tid / 128;
    for (int lc = 0; lc < LL; lc += 32) {
        int lim = min(32, LL - lc);
        __syncthreads();
        for (int i = tid; i < lim * 128; i += 256)
            v_s[i] = g_v[(b * LL + lc + i / 128) * 128 + (i % 128)];
        __syncthreads();
#pragma unroll
        for (int it = 0; it < 16; it++) {
            int p = pb + 2 * it;
            float a = acc[it];
            for (int l = 0; l < lim; l++)
                a = fmaf(p_s[p * 251 + lc + l], v_s[l * 128 + f], a);
            acc[it] = a;
        }
    }
#pragma unroll
    for (int it = 0; it < 16; it++) {
        int gp = p0 + pb + 2 * it;
        float ctx = fmaf(acc[it], gate_w[gp], gate_b[gp]);
        out[(b * NP + gp) * 128 + f] = g_roi[(b * NP + gp) * 128 + f] + ctx;
    }
}

// ---------------- host launcher ----------------------------------------------
extern "C" void kernel_launch(void* const* d_in, const int* in_sizes, int n_in,
                              void* d_out, int out_size) {
    (void)in_sizes; (void)n_in; (void)out_size;
    const float* roi0   = (const float*)d_in[0];
    const float* roi1   = (const float*)d_in[1];
    const float* roi2   = (const float*)d_in[2];
    const float* fmap   = (const float*)d_in[3];
    const float* conv_w = (const float*)d_in[4];
    const float* conv_g = (const float*)d_in[5];
    const float* conv_b = (const float*)d_in[6];
    const float* conv_m = (const float*)d_in[7];
    const float* conv_v = (const float*)d_in[8];
    const float* cat_w  = (const float*)d_in[9];
    const float* cat_g  = (const float*)d_in[10];
    const float* cat_b  = (const float*)d_in[11];
    const float* cat_m  = (const float*)d_in[12];
    const float* cat_v  = (const float*)d_in[13];
    const float* fc_w   = (const float*)d_in[14];
    const float* fc_b   = (const float*)d_in[15];
    const float* ln_g   = (const float*)d_in[16];
    const float* ln_b   = (const float*)d_in[17];
    const float* key_w  = (const float*)d_in[18];
    const float* key_g  = (const float*)d_in[19];
    const float* key_bt = (const float*)d_in[20];
    const float* key_m  = (const float*)d_in[21];
    const float* key_v  = (const float*)d_in[22];
    const float* q_w    = (const float*)d_in[23];
    const float* q_b    = (const float*)d_in[24];
    const float* val_w  = (const float*)d_in[25];
    const float* val_b  = (const float*)d_in[26];
    const float* gate_w = (const float*)d_in[27];
    const float* gate_b = (const float*)d_in[28];
    float* out = (float*)d_out;

    float *cat1, *cat2;
    cudaGetSymbolAddress((void**)&cat1, g_cat1);
    cudaGetSymbolAddress((void**)&cat2, g_cat2);

    transpose_fcw<<<(FCH * KFC + 255) / 256, 256>>>(fc_w);

    // three level convs in one grid (y = level) -> g_cat1
    conv_mma<128, 64, 16, 192><<<dim3(NTOT / 16, 3), 512>>>(
        roi0, roi1, roi2, conv_w, 64 * 128 * 9,
        conv_g, conv_b, conv_m, conv_v, cat1);

    // cat conv -> g_cat2
    conv_mma<192, 128, 8, 128><<<dim3(NTOT / 8, 1), 512>>>(
        cat1, cat1, cat1, cat_w, 0,
        cat_g, cat_b, cat_m, cat_v, cat2);

    fc_ln_relu<<<NTOT / 64, 256>>>(fc_b, ln_g, ln_b);

    kv_kernel<<<dim3(BB, 10), 256>>>(fmap, key_w, key_g, key_bt, key_m, key_v,
                                     val_w, val_b);

    attn_kernel<<<dim3(BB, NP / 32), 256>>>(q_w, q_b, gate_w, gate_b, out);
}

// round 6
// speedup vs baseline: 2.0644x; 1.1497x over previous
#include <cuda_runtime.h>
#include <cstdint>

#define BB    32
#define NP    192
#define CC    128
#define NSS   36
#define FCH   128
#define EPS   1e-5f
#define NTOT  (BB*NP)      // 6144
#define LL    250
#define KFC   (CC*NSS)     // 4608

// ---------------- scratch (device globals; no runtime allocation) -------------
__device__ float g_cat1[NTOT * 192 * NSS];   // level conv outputs, concatenated
__device__ float g_cat2[NTOT * CC * NSS];    // cat conv output (tf32-rounded)
__device__ float g_roi [BB * NP * FCH];      // fc+LN+ReLU output
__device__ float g_k   [BB * CC * LL];       // keys   (b, f, l)
__device__ float g_v   [BB * LL * CC];       // values (b, l, f)
__device__ float g_fcw32[FCH * KFC];         // fc_w tf32-rounded, [f][k]

// ---------------- helpers ----------------------------------------------------
__device__ __forceinline__ uint32_t cvt_tf32(float f) {
    uint32_t u; asm("cvt.rna.tf32.f32 %0, %1;" : "=r"(u) : "f"(f)); return u;
}
__device__ __forceinline__ void mma_tf32(float* c, const uint32_t* a,
                                         uint32_t b0, uint32_t b1) {
    asm volatile("mma.sync.aligned.m16n8k8.row.col.f32.tf32.tf32.f32 "
                 "{%0,%1,%2,%3}, {%4,%5,%6,%7}, {%8,%9}, {%0,%1,%2,%3};"
                 : "+f"(c[0]), "+f"(c[1]), "+f"(c[2]), "+f"(c[3])
                 : "r"(a[0]), "r"(a[1]), "r"(a[2]), "r"(a[3]), "r"(b0), "r"(b1));
}

// ---------------- conv9 + folded BN + ReLU via tf32 mma.sync ------------------
// GEMM: A = weights (M=COUT), B = im2col (N = NSAMP*36 padded to 40, K = CIN*9).
// K chunked by 72 (8 ci x 9 taps). Warp tile: 64 rows x 40 cols.
template<int CIN, int COUT, int NSAMP, int CSTRIDE, bool CVTOUT>
__global__ __launch_bounds__(512, 1)
void conv_mma(const float* __restrict__ x0, const float* __restrict__ x1,
              const float* __restrict__ x2, const float* __restrict__ w_, int wstride,
              const float* __restrict__ bng, const float* __restrict__ bnb,
              const float* __restrict__ bnm, const float* __restrict__ bnv,
              float* __restrict__ out) {
    constexpr int NCH = CIN * 9 / 72;        // K chunks (16 or 24)
    constexpr int MT  = COUT / 16;           // m16 tiles in CTA (4 or 8)
    constexpr int NWM = MT / 4;              // warps along M (1 or 2)
    constexpr int SSTR = 8 * 44;             // sample stride in x_s (floats)

    __shared__ uint32_t w_s[MT * 9 * 32 * 4];   // fragment-major weights, one chunk
    __shared__ uint32_t x_s[NSAMP * SSTR];      // raw padded windows, 8-ci chunk

    const int tid  = threadIdx.x;
    const int wid  = tid >> 5, lane = tid & 31;
    const int lvl  = blockIdx.y;
    const float* x = (lvl == 0) ? x0 : (lvl == 1) ? x1 : x2;
    const float* w = w_ + (size_t)lvl * wstride;
    const int c0   = lvl * COUT;
    bng += lvl * COUT; bnb += lvl * COUT; bnm += lvl * COUT; bnv += lvl * COUT;

    const int samp = wid / NWM;
    const int mt0  = (wid % NWM) * 4;
    const int n0   = blockIdx.x * NSAMP;
    const int sampbase = samp * SSTR;

    for (int i = tid; i < NSAMP * SSTR; i += 512) x_s[i] = 0u;

    int col[5];
#pragma unroll
    for (int nt = 0; nt < 5; nt++) {
        int cb = nt * 8 + (lane >> 2);
        col[nt] = cb < 36 ? cb : 35;
    }

    float acc[4][5][4];
#pragma unroll
    for (int mt = 0; mt < 4; mt++)
#pragma unroll
        for (int nt = 0; nt < 5; nt++)
#pragma unroll
            for (int j = 0; j < 4; j++) acc[mt][nt][j] = 0.f;

    for (int kc = 0; kc < NCH; kc++) {
        const int k0 = kc * 72, ci0 = kc * 8;
        __syncthreads();
        for (int e = tid; e < COUT * 72; e += 512) {
            int m = e / 72, kk = e % 72;
            int mt = m >> 4, r = m & 15, k8 = kk >> 3, kcq = kk & 7;
            int ln = ((r & 7) << 2) | (kcq & 3);
            int j  = (r >> 3) | ((kcq >> 2) << 1);
            w_s[(((k8 * MT + mt) * 32 + ln) << 2) | j] =
                cvt_tf32(w[(size_t)m * (CIN * 9) + k0 + kk]);
        }
        for (int e = tid; e < NSAMP * 8 * 36; e += 512) {
            int s = e % 36, ci = (e / 36) & 7, sp = e / 288;
            x_s[sp * SSTR + ci * 44 + 4 + s] =
                cvt_tf32(x[((size_t)(n0 + sp) * CIN + ci0 + ci) * 36 + s]);
        }
        __syncthreads();

#pragma unroll
        for (int k8 = 0; k8 < 9; k8++) {
            uint32_t a[4][4];
#pragma unroll
            for (int mt = 0; mt < 4; mt++)
                *(uint4*)a[mt] =
                    *(const uint4*)&w_s[((k8 * MT + mt0 + mt) * 32 + lane) << 2];
            int klo = k8 * 8 + (lane & 3), khi = klo + 4;
            int cilo = (klo * 57) >> 9, cihi = (khi * 57) >> 9;
            int blo = sampbase + cilo * 44 + (klo - cilo * 9);
            int bhi = sampbase + cihi * 44 + (khi - cihi * 9);
#pragma unroll
            for (int nt = 0; nt < 5; nt++) {
                uint32_t b0 = x_s[blo + col[nt]];
                uint32_t b1 = x_s[bhi + col[nt]];
#pragma unroll
                for (int mt = 0; mt < 4; mt++)
                    mma_tf32(acc[mt][nt], a[mt], b0, b1);
            }
        }
    }

    const int nidx = n0 + samp;
#pragma unroll
    for (int mt = 0; mt < 4; mt++) {
        int cobase = (mt0 + mt) * 16 + (lane >> 2);
#pragma unroll
        for (int h = 0; h < 2; h++) {
            int co = cobase + 8 * h;
            float sc = bng[co] * rsqrtf(bnv[co] + EPS);
            float bi = bnb[co] - bnm[co] * sc;
            float* orow = out + ((size_t)nidx * CSTRIDE + c0 + co) * 36;
#pragma unroll
            for (int nt = 0; nt < 5; nt++) {
                int s0 = nt * 8 + 2 * (lane & 3);
                if (s0 < 36) {
                    float v0 = fmaf(acc[mt][nt][2 * h], sc, bi);
                    float v1 = fmaf(acc[mt][nt][2 * h + 1], sc, bi);
                    v0 = v0 > 0.f ? v0 : 0.f;
                    v1 = v1 > 0.f ? v1 : 0.f;
                    if (CVTOUT) {    // pre-round for tf32 FC consumer
                        v0 = __uint_as_float(cvt_tf32(v0));
                        v1 = __uint_as_float(cvt_tf32(v1));
                    }
                    *(float2*)(orow + s0) = make_float2(v0, v1);
                }
            }
        }
    }
}

// ---------------- fc_w tf32 pre-convert (layout kept [f][k]) -----------------
__global__ void cvt_fcw(const float* __restrict__ w) {
    int idx = blockIdx.x * 256 + threadIdx.x;
    if (idx < FCH * KFC)
        g_fcw32[idx] = __uint_as_float(cvt_tf32(w[idx]));
}

// ---------------- FC via tf32 mma.sync, fused LayerNorm + ReLU ---------------
// CTA: 128 thr / 4 warps = (mw in {0,1} x 16 rows, kw in {0,1} x K-half).
// Warp tile: 16 rows x 128 cols (16 n8 tiles). Grid 192 x 32 rows.
__global__ __launch_bounds__(128, 1)
void fc_ln_relu(const float* __restrict__ fc_b, const float* __restrict__ ln_g,
                const float* __restrict__ ln_b) {
    __shared__ float A_s[2][32 * 36];
    __shared__ float B_s[2][128 * 36];

    const int tid = threadIdx.x, lane = tid & 31, wid = tid >> 5;
    const int mw = wid & 1, kw = wid >> 1;
    const int n0 = blockIdx.x * 32;

    float acc[16][4];
#pragma unroll
    for (int nt = 0; nt < 16; nt++)
#pragma unroll
        for (int j = 0; j < 4; j++) acc[nt][j] = 0.f;

    const float* As = A_s[kw];
    const float* Bs = B_s[kw];

    for (int ch = 0; ch < 72; ch++) {
        __syncthreads();
        // stage A: 2 slabs x 32 rows x 32 k (float4 copies; values pre-tf32)
#pragma unroll
        for (int it = 0; it < 4; it++) {
            int i = tid + it * 128;
            int s = i >> 8, r = (i >> 3) & 31, q = i & 7;
            *(float4*)&A_s[s][r * 36 + q * 4] =
                *(const float4*)(g_cat2 + (size_t)(n0 + r) * KFC + s * 2304 + ch * 32 + q * 4);
        }
        // stage B: 2 slabs x 128 f x 32 k
#pragma unroll
        for (int it = 0; it < 16; it++) {
            int i = tid + it * 128;
            int s = i >> 10, f = (i >> 3) & 127, q = i & 7;
            *(float4*)&B_s[s][f * 36 + q * 4] =
                *(const float4*)(g_fcw32 + (size_t)f * KFC + s * 2304 + ch * 32 + q * 4);
        }
        __syncthreads();

#pragma unroll
        for (int k8 = 0; k8 < 4; k8++) {
            int r0 = mw * 16 + (lane >> 2), c0 = k8 * 8 + (lane & 3);
            uint32_t a[4];
            a[0] = __float_as_uint(As[r0 * 36 + c0]);
            a[1] = __float_as_uint(As[(r0 + 8) * 36 + c0]);
            a[2] = __float_as_uint(As[r0 * 36 + c0 + 4]);
            a[3] = __float_as_uint(As[(r0 + 8) * 36 + c0 + 4]);
#pragma unroll
            for (int nt = 0; nt < 16; nt++) {
                uint32_t b0 = __float_as_uint(Bs[(nt * 8 + (lane >> 2)) * 36 + c0]);
                uint32_t b1 = __float_as_uint(Bs[(nt * 8 + (lane >> 2)) * 36 + c0 + 4]);
                mma_tf32(acc[nt], a, b0, b1);
            }
        }
    }

    // cross-kw reduce through smem (reuse B_s area)
    __syncthreads();
    float* red = &B_s[0][0];            // 32 x 130
    if (kw == 1) {
#pragma unroll
        for (int nt = 0; nt < 16; nt++)
#pragma unroll
            for (int j = 0; j < 4; j++) {
                int r = mw * 16 + (lane >> 2) + 8 * (j >> 1);
                int c = nt * 8 + 2 * (lane & 3) + (j & 1);
                red[r * 130 + c] = acc[nt][j];
            }
    }
    __syncthreads();
    if (kw == 0) {
#pragma unroll
        for (int nt = 0; nt < 16; nt++) {
            int cb = nt * 8 + 2 * (lane & 3);
            int rA = mw * 16 + (lane >> 2), rB = rA + 8;
            acc[nt][0] += red[rA * 130 + cb]     + fc_b[cb];
            acc[nt][1] += red[rA * 130 + cb + 1] + fc_b[cb + 1];
            acc[nt][2] += red[rB * 130 + cb]     + fc_b[cb];
            acc[nt][3] += red[rB * 130 + cb + 1] + fc_b[cb + 1];
        }
        // LayerNorm: rows rA, rB; each row's 128 feats = 4-lane quad x 16 nt x 2
        float s0 = 0.f, s1 = 0.f;
#pragma unroll
        for (int nt = 0; nt < 16; nt++) {
            s0 += acc[nt][0] + acc[nt][1];
            s1 += acc[nt][2] + acc[nt][3];
        }
        s0 += __shfl_xor_sync(~0u, s0, 1); s0 += __shfl_xor_sync(~0u, s0, 2);
        s1 += __shfl_xor_sync(~0u, s1, 1); s1 += __shfl_xor_sync(~0u, s1, 2);
        float m0 = s0 * (1.f / 128.f), m1 = s1 * (1.f / 128.f);
        float q0 = 0.f, q1 = 0.f;
#pragma unroll
        for (int nt = 0; nt < 16; nt++) {
            float d0 = acc[nt][0] - m0, d1 = acc[nt][1] - m0;
            float d2 = acc[nt][2] - m1, d3 = acc[nt][3] - m1;
            q0 += d0 * d0 + d1 * d1;
            q1 += d2 * d2 + d3 * d3;
        }
        q0 += __shfl_xor_sync(~0u, q0, 1); q0 += __shfl_xor_sync(~0u, q0, 2);
        q1 += __shfl_xor_sync(~0u, q1, 1); q1 += __shfl_xor_sync(~0u, q1, 2);
        float rs0 = rsqrtf(q0 * (1.f / 128.f) + EPS);
        float rs1 = rsqrtf(q1 * (1.f / 128.f) + EPS);
        int gr0 = n0 + mw * 16 + (lane >> 2), gr1 = gr0 + 8;
#pragma unroll
        for (int nt = 0; nt < 16; nt++) {
            int c = nt * 8 + 2 * (lane & 3);
            float g0 = ln_g[c], g1 = ln_g[c + 1], bb0 = ln_b[c], bb1 = ln_b[c + 1];
            float v0 = fmaxf((acc[nt][0] - m0) * rs0 * g0 + bb0, 0.f);
            float v1 = fmaxf((acc[nt][1] - m0) * rs0 * g1 + bb1, 0.f);
            float v2 = fmaxf((acc[nt][2] - m1) * rs1 * g0 + bb0, 0.f);
            float v3 = fmaxf((acc[nt][3] - m1) * rs1 * g1 + bb1, 0.f);
            *(float2*)(g_roi + (size_t)gr0 * 128 + c) = make_float2(v0, v1);
            *(float2*)(g_roi + (size_t)gr1 * 128 + c) = make_float2(v2, v3);
        }
    }
}

// ---------------- k/v at the 250 nearest-resize sample points ----------------
__global__ __launch_bounds__(256)
void kv_kernel(const float* __restrict__ fmap, const float* __restrict__ key_w,
               const float* __restrict__ key_g, const float* __restrict__ key_beta,
               const float* __restrict__ key_m, const float* __restrict__ key_v,
               const float* __restrict__ val_w, const float* __restrict__ val_b) {
    __shared__ float fc_s[25 * 129];
    const int b = blockIdx.x, r = blockIdx.y;
    const int tid = threadIdx.x;
    for (int i = tid; i < 25 * 128; i += 256) {
        int c = i / 25, pos = i % 25;
        fc_s[pos * 129 + c] = fmap[((b * 128 + c) * 40 + 4 * r) * 100 + 4 * pos];
    }
    __syncthreads();
    for (int i = tid; i < 25 * 128; i += 256) {
        int o = i % 128, pos = i / 128;
        const float* kw = key_w + o * 128;
        const float* vw = val_w + o * 128;
        float ka = 0.f, va = 0.f;
#pragma unroll 4
        for (int c = 0; c < 128; c++) {
            float xv = fc_s[pos * 129 + c];
            ka = fmaf(kw[c], xv, ka);
            va = fmaf(vw[c], xv, va);
        }
        float sc = key_g[o] * rsqrtf(key_v[o] + EPS);
        float kb = key_beta[o] - key_m[o] * sc;
        float kk = fmaf(ka, sc, kb);
        int l = r * 25 + pos;
        g_k[(b * 128 + o) * LL + l] = kk > 0.f ? kk : 0.f;
        g_v[(b * LL + l) * 128 + o] = va + val_b[o];
    }
}

// ---------------- attention: block = (b, 32 priors) --------------------------
__global__ __launch_bounds__(256)
void attn_kernel(const float* __restrict__ q_w, const float* __restrict__ q_b,
                 const float* __restrict__ gate_w, const float* __restrict__ gate_b,
                 float* __restrict__ out) {
    __shared__ float q_s[32 * 129];
    __shared__ float p_s[32 * 251];
    const int b = blockIdx.x, p0 = blockIdx.y * 32;
    const int tid = threadIdx.x;

    for (int i = tid; i < 32 * 128; i += 256) {
        int p = i / 128, f = i % 128;
        float qq = fmaf(g_roi[(b * NP + p0 + p) * 128 + f], q_w[p0 + p], q_b[p0 + p]);
        q_s[p * 129 + f] = qq > 0.f ? qq : 0.f;
    }
    __syncthreads();

    const float scale = 0.08838834764831845f;
    for (int idx = tid; idx < 32 * LL; idx += 256) {
        int p = idx % 32, l = idx / 32;
        const float* krow = g_k + b * 128 * LL + l;
        float a = 0.f;
#pragma unroll 4
        for (int f = 0; f < 128; f++)
            a = fmaf(q_s[p * 129 + f], krow[f * LL], a);
        p_s[p * 251 + l] = a * scale;
    }
    __syncthreads();

    const int warp = tid / 32, lane = tid % 32;
    for (int rr = 0; rr < 4; rr++) {
        int p = warp * 4 + rr;
        float mx = -1e30f;
        for (int l = lane; l < LL; l += 32) mx = fmaxf(mx, p_s[p * 251 + l]);
        for (int d = 16; d >= 1; d >>= 1) mx = fmaxf(mx, __shfl_xor_sync(~0u, mx, d));
        float sm = 0.f;
        for (int l = lane; l < LL; l += 32) {
            float e = __expf(p_s[p * 251 + l] - mx);
            p_s[p * 251 + l] = e;
            sm += e;
        }
        for (int d = 16; d >= 1; d >>= 1) sm += __shfl_xor_sync(~0u, sm, d);
        float inv = 1.f / sm;
        for (int l = lane; l < LL; l += 32) p_s[p * 251 + l] *= inv;
    }
    __syncthreads();

    float* v_s = q_s;
    float acc[16];
#pragma unroll
    for (int it = 0; it < 16; it++) acc[it] = 0.f;
    const int f = tid % 128, pb = tid / 128;
    for (int lc = 0; lc < LL; lc += 32) {
        int lim = min(32, LL - lc);
        __syncthreads();
        for (int i = tid; i < lim * 128; i += 256)
            v_s[i] = g_v[(b * LL + lc + i / 128) * 128 + (i % 128)];
        __syncthreads();
#pragma unroll
        for (int it = 0; it < 16; it++) {
            int p = pb + 2 * it;
            float a = acc[it];
            for (int l = 0; l < lim; l++)
                a = fmaf(p_s[p * 251 + lc + l], v_s[l * 128 + f], a);
            acc[it] = a;
        }
    }
#pragma unroll
    for (int it = 0; it < 16; it++) {
        int gp = p0 + pb + 2 * it;
        float ctx = fmaf(acc[it], gate_w[gp], gate_b[gp]);
        out[(b * NP + gp) * 128 + f] = g_roi[(b * NP + gp) * 128 + f] + ctx;
    }
}

// ---------------- host launcher ----------------------------------------------
extern "C" void kernel_launch(void* const* d_in, const int* in_sizes, int n_in,
                              void* d_out, int out_size) {
    (void)in_sizes; (void)n_in; (void)out_size;
    const float* roi0   = (const float*)d_in[0];
    const float* roi1   = (const float*)d_in[1];
    const float* roi2   = (const float*)d_in[2];
    const float* fmap   = (const float*)d_in[3];
    const float* conv_w = (const float*)d_in[4];
    const float* conv_g = (const float*)d_in[5];
    const float* conv_b = (const float*)d_in[6];
    const float* conv_m = (const float*)d_in[7];
    const float* conv_v = (const float*)d_in[8];
    const float* cat_w  = (const float*)d_in[9];
    const float* cat_g  = (const float*)d_in[10];
    const float* cat_b  = (const float*)d_in[11];
    const float* cat_m  = (const float*)d_in[12];
    const float* cat_v  = (const float*)d_in[13];
    const float* fc_w   = (const float*)d_in[14];
    const float* fc_b   = (const float*)d_in[15];
    const float* ln_g   = (const float*)d_in[16];
    const float* ln_b   = (const float*)d_in[17];
    const float* key_w  = (const float*)d_in[18];
    const float* key_g  = (const float*)d_in[19];
    const float* key_bt = (const float*)d_in[20];
    const float* key_m  = (const float*)d_in[21];
    const float* key_v  = (const float*)d_in[22];
    const float* q_w    = (const float*)d_in[23];
    const float* q_b    = (const float*)d_in[24];
    const float* val_w  = (const float*)d_in[25];
    const float* val_b  = (const float*)d_in[26];
    const float* gate_w = (const float*)d_in[27];
    const float* gate_b = (const float*)d_in[28];
    float* out = (float*)d_out;

    float *cat1, *cat2;
    cudaGetSymbolAddress((void**)&cat1, g_cat1);
    cudaGetSymbolAddress((void**)&cat2, g_cat2);

    cvt_fcw<<<(FCH * KFC + 255) / 256, 256>>>(fc_w);

    // three level convs in one grid (y = level) -> g_cat1
    conv_mma<128, 64, 16, 192, false><<<dim3(NTOT / 16, 3), 512>>>(
        roi0, roi1, roi2, conv_w, 64 * 128 * 9,
        conv_g, conv_b, conv_m, conv_v, cat1);

    // cat conv -> g_cat2 (tf32-rounded output for FC)
    conv_mma<192, 128, 8, 128, true><<<dim3(NTOT / 8, 1), 512>>>(
        cat1, cat1, cat1, cat_w, 0,
        cat_g, cat_b, cat_m, cat_v, cat2);

    fc_ln_relu<<<192, 128>>>(fc_b, ln_g, ln_b);

    kv_kernel<<<dim3(BB, 10), 256>>>(fmap, key_w, key_g, key_bt, key_m, key_v,
                                     val_w, val_b);

    attn_kernel<<<dim3(BB, NP / 32), 256>>>(q_w, q_b, gate_w, gate_b, out);
}

// round 7
// speedup vs baseline: 2.4701x; 1.1965x over previous
#include <cuda_runtime.h>
#include <cstdint>

#define BB    32
#define NP    192
#define CC    128
#define NSS   36
#define FCH   128
#define EPS   1e-5f
#define NTOT  (BB*NP)      // 6144
#define LL    250
#define KFC   (CC*NSS)     // 4608

// ---------------- scratch (device globals; no runtime allocation) -------------
__device__ float g_x32 [3 * NTOT * CC * NSS]; // tf32-rounded roi inputs
__device__ float g_cat1[NTOT * 192 * NSS];    // level conv outputs (tf32-rounded)
__device__ float g_cat2[NTOT * CC * NSS];     // cat conv output (tf32-rounded)
__device__ float g_roi [BB * NP * FCH];       // fc+LN+ReLU output
__device__ float g_k   [BB * CC * LL];        // keys   (b, f, l)
__device__ float g_v   [BB * LL * CC];        // values (b, l, f)
__device__ float g_fcw32[FCH * KFC];          // fc_w tf32-rounded, [f][k]
__device__ float g_wfL [3 * 16 * 64 * 72];    // level weights, fragment-major
__device__ float g_wfC [24 * 128 * 72];       // cat weights, fragment-major

// ---------------- helpers ----------------------------------------------------
__device__ __forceinline__ uint32_t cvt_tf32(float f) {
    uint32_t u; asm("cvt.rna.tf32.f32 %0, %1;" : "=r"(u) : "f"(f)); return u;
}
__device__ __forceinline__ uint32_t smem_u32(const void* p) {
    uint32_t a;
    asm("{ .reg .u64 t; cvta.to.shared.u64 t, %1; cvt.u32.u64 %0, t; }"
        : "=r"(a) : "l"(p));
    return a;
}
__device__ __forceinline__ void cp16(uint32_t s, const void* g) {
    asm volatile("cp.async.cg.shared.global [%0], [%1], 16;" :: "r"(s), "l"(g));
}
__device__ __forceinline__ void mma_tf32(float* c, const uint32_t* a,
                                         uint32_t b0, uint32_t b1) {
    asm volatile("mma.sync.aligned.m16n8k8.row.col.f32.tf32.tf32.f32 "
                 "{%0,%1,%2,%3}, {%4,%5,%6,%7}, {%8,%9}, {%0,%1,%2,%3};"
                 : "+f"(c[0]), "+f"(c[1]), "+f"(c[2]), "+f"(c[3])
                 : "r"(a[0]), "r"(a[1]), "r"(a[2]), "r"(a[3]), "r"(b0), "r"(b1));
}

// ---------------- input tf32 pre-round ---------------------------------------
__global__ void cvt_roi(const float* __restrict__ r0, const float* __restrict__ r1,
                        const float* __restrict__ r2) {
    const size_t n4 = (size_t)NTOT * CC * NSS / 4;      // 7077888
    const float* s = (blockIdx.y == 0) ? r0 : (blockIdx.y == 1) ? r1 : r2;
    float4* d = (float4*)(g_x32 + (size_t)blockIdx.y * NTOT * CC * NSS);
    size_t i = (size_t)blockIdx.x * 256 + threadIdx.x;
    if (i < n4) {
        float4 v = ((const float4*)s)[i];
        v.x = __uint_as_float(cvt_tf32(v.x));
        v.y = __uint_as_float(cvt_tf32(v.y));
        v.z = __uint_as_float(cvt_tf32(v.z));
        v.w = __uint_as_float(cvt_tf32(v.w));
        d[i] = v;
    }
}

// ---------------- weight fragment pre-permute --------------------------------
// dst chunk layout: ((k8*MT+mt)*32 + ln)*4 + j  (tf32-rounded)
template<int CIN, int COUT>
__global__ void prep_w(const float* __restrict__ w, float* __restrict__ dst,
                       int wstride) {
    constexpr int CHW = COUT * 72;
    constexpr int NCH = CIN * 9 / 72;
    constexpr int MT  = COUT / 16;
    const int lvl = blockIdx.y;
    const int idx = blockIdx.x * 256 + threadIdx.x;
    if (idx >= NCH * CHW) return;
    int kc = idx / CHW, c = idx % CHW;
    int j = c & 3, ln = (c >> 2) & 31, t = c >> 7;
    int mt = t % MT, k8 = t / MT;
    int r  = ((ln >> 2) & 7) | ((j & 1) << 3);
    int kq = (ln & 3) | ((j >> 1) << 2);
    int m  = mt * 16 + r, kk = k8 * 8 + kq;
    dst[(size_t)lvl * NCH * CHW + idx] =
        __uint_as_float(cvt_tf32(w[(size_t)lvl * wstride + (size_t)m * (CIN * 9) + kc * 72 + kk]));
}

// ---------------- conv9 + folded BN + ReLU via tf32 mma.sync -----------------
// B = im2col from tf32-pre-rounded x, staged with cp.async (2-stage pipeline).
// A = pre-permuted weight fragments, read directly via LDG.128 (L2-resident).
template<int CIN, int COUT, int NSAMP, int CSTRIDE>
__global__ __launch_bounds__(512, 1)
void conv_mma(const float* __restrict__ xg, const float* __restrict__ wfrag_,
              const float* __restrict__ bng, const float* __restrict__ bnb,
              const float* __restrict__ bnm, const float* __restrict__ bnv,
              float* __restrict__ out) {
    constexpr int NCH = CIN * 9 / 72;
    constexpr int MT  = COUT / 16;
    constexpr int NWM = MT / 4;
    constexpr int SSTR = 8 * 44;
    constexpr int CHW = COUT * 72;

    __shared__ __align__(16) float x_s[2][NSAMP * SSTR];

    const int tid  = threadIdx.x;
    const int wid  = tid >> 5, lane = tid & 31;
    const int lvl  = blockIdx.y;
    const float* x = xg + (size_t)lvl * NTOT * CIN * NSS;
    const float* wfrag = wfrag_ + (size_t)lvl * NCH * CHW;
    const int c0   = lvl * COUT;
    bng += lvl * COUT; bnb += lvl * COUT; bnm += lvl * COUT; bnv += lvl * COUT;

    const int samp = wid / NWM;
    const int mt0  = (wid % NWM) * 4;
    const int n0   = blockIdx.x * NSAMP;
    const int sampbase = samp * SSTR;

    const uint32_t xs0 = smem_u32(&x_s[0][0]), xs1 = smem_u32(&x_s[1][0]);

    // zero both buffers (pads stay zero; data region rewritten by cp.async)
    for (int i = tid; i < 2 * NSAMP * SSTR; i += 512) ((float*)x_s)[i] = 0.f;
    __syncthreads();

    int col[5];
#pragma unroll
    for (int nt = 0; nt < 5; nt++) {
        int cb = nt * 8 + (lane >> 2);
        col[nt] = cb < 36 ? cb : 35;
    }

    float acc[4][5][4];
#pragma unroll
    for (int mt = 0; mt < 4; mt++)
#pragma unroll
        for (int nt = 0; nt < 5; nt++)
#pragma unroll
            for (int j = 0; j < 4; j++) acc[mt][nt][j] = 0.f;

    // ---- stage chunk kc into buffer buf (cp.async, one commit group) ----
    auto stage = [&](int kc, int buf) {
        const uint32_t base = buf ? xs1 : xs0;
        for (int i = tid; i < NSAMP * 72; i += 512) {
            int q = i % 9, ci = (i / 9) & 7, sp = i / 72;
            cp16(base + (uint32_t)(sp * SSTR + ci * 44 + 4 + q * 4) * 4,
                 x + ((size_t)(n0 + sp) * CIN + kc * 8 + ci) * 36 + q * 4);
        }
        asm volatile("cp.async.commit_group;");
    };

    stage(0, 0);

    for (int kc = 0; kc < NCH; kc++) {
        if (kc + 1 < NCH) {
            stage(kc + 1, (kc + 1) & 1);
            asm volatile("cp.async.wait_group 1;");
        } else {
            asm volatile("cp.async.wait_group 0;");
        }
        __syncthreads();

        const uint32_t* xs = (const uint32_t*)x_s[kc & 1];
        const uint4* wf4 = (const uint4*)(wfrag + (size_t)kc * CHW);
#pragma unroll
        for (int k8 = 0; k8 < 9; k8++) {
            uint4 af[4];
#pragma unroll
            for (int mt = 0; mt < 4; mt++)
                af[mt] = __ldg(&wf4[(k8 * MT + mt0 + mt) * 32 + lane]);
            int klo = k8 * 8 + (lane & 3), khi = klo + 4;
            int cilo = (klo * 57) >> 9, cihi = (khi * 57) >> 9;
            int blo = sampbase + cilo * 44 + (klo - cilo * 9);
            int bhi = sampbase + cihi * 44 + (khi - cihi * 9);
#pragma unroll
            for (int nt = 0; nt < 5; nt++) {
                uint32_t b0 = xs[blo + col[nt]];
                uint32_t b1 = xs[bhi + col[nt]];
#pragma unroll
                for (int mt = 0; mt < 4; mt++)
                    mma_tf32(acc[mt][nt], (const uint32_t*)&af[mt], b0, b1);
            }
        }
        __syncthreads();
    }

    // epilogue: folded BN + ReLU, tf32-round for next tf32 consumer
    const int nidx = n0 + samp;
#pragma unroll
    for (int mt = 0; mt < 4; mt++) {
        int cobase = (mt0 + mt) * 16 + (lane >> 2);
#pragma unroll
        for (int h = 0; h < 2; h++) {
            int co = cobase + 8 * h;
            float sc = bng[co] * rsqrtf(bnv[co] + EPS);
            float bi = bnb[co] - bnm[co] * sc;
            float* orow = out + ((size_t)nidx * CSTRIDE + c0 + co) * 36;
#pragma unroll
            for (int nt = 0; nt < 5; nt++) {
                int s0 = nt * 8 + 2 * (lane & 3);
                if (s0 < 36) {
                    float v0 = fmaf(acc[mt][nt][2 * h], sc, bi);
                    float v1 = fmaf(acc[mt][nt][2 * h + 1], sc, bi);
                    v0 = v0 > 0.f ? __uint_as_float(cvt_tf32(v0)) : 0.f;
                    v1 = v1 > 0.f ? __uint_as_float(cvt_tf32(v1)) : 0.f;
                    *(float2*)(orow + s0) = make_float2(v0, v1);
                }
            }
        }
    }
}

// ---------------- fc_w tf32 pre-convert (layout kept [f][k]) -----------------
__global__ void cvt_fcw(const float* __restrict__ w) {
    int idx = blockIdx.x * 256 + threadIdx.x;
    if (idx < FCH * KFC)
        g_fcw32[idx] = __uint_as_float(cvt_tf32(w[idx]));
}

// ---------------- FC via tf32 mma.sync, fused LayerNorm + ReLU ---------------
__global__ __launch_bounds__(128, 1)
void fc_ln_relu(const float* __restrict__ fc_b, const float* __restrict__ ln_g,
                const float* __restrict__ ln_b) {
    __shared__ float A_s[2][32 * 36];
    __shared__ float B_s[2][128 * 36];

    const int tid = threadIdx.x, lane = tid & 31, wid = tid >> 5;
    const int mw = wid & 1, kw = wid >> 1;
    const int n0 = blockIdx.x * 32;

    float acc[16][4];
#pragma unroll
    for (int nt = 0; nt < 16; nt++)
#pragma unroll
        for (int j = 0; j < 4; j++) acc[nt][j] = 0.f;

    const float* As = A_s[kw];
    const float* Bs = B_s[kw];

    for (int ch = 0; ch < 72; ch++) {
        __syncthreads();
#pragma unroll
        for (int it = 0; it < 4; it++) {
            int i = tid + it * 128;
            int s = i >> 8, r = (i >> 3) & 31, q = i & 7;
            *(float4*)&A_s[s][r * 36 + q * 4] =
                *(const float4*)(g_cat2 + (size_t)(n0 + r) * KFC + s * 2304 + ch * 32 + q * 4);
        }
#pragma unroll
        for (int it = 0; it < 16; it++) {
            int i = tid + it * 128;
            int s = i >> 10, f = (i >> 3) & 127, q = i & 7;
            *(float4*)&B_s[s][f * 36 + q * 4] =
                *(const float4*)(g_fcw32 + (size_t)f * KFC + s * 2304 + ch * 32 + q * 4);
        }
        __syncthreads();

#pragma unroll
        for (int k8 = 0; k8 < 4; k8++) {
            int r0 = mw * 16 + (lane >> 2), c0 = k8 * 8 + (lane & 3);
            uint32_t a[4];
            a[0] = __float_as_uint(As[r0 * 36 + c0]);
            a[1] = __float_as_uint(As[(r0 + 8) * 36 + c0]);
            a[2] = __float_as_uint(As[r0 * 36 + c0 + 4]);
            a[3] = __float_as_uint(As[(r0 + 8) * 36 + c0 + 4]);
#pragma unroll
            for (int nt = 0; nt < 16; nt++) {
                uint32_t b0 = __float_as_uint(Bs[(nt * 8 + (lane >> 2)) * 36 + c0]);
                uint32_t b1 = __float_as_uint(Bs[(nt * 8 + (lane >> 2)) * 36 + c0 + 4]);
                mma_tf32(acc[nt], a, b0, b1);
            }
        }
    }

    __syncthreads();
    float* red = &B_s[0][0];
    if (kw == 1) {
#pragma unroll
        for (int nt = 0; nt < 16; nt++)
#pragma unroll
            for (int j = 0; j < 4; j++) {
                int r = mw * 16 + (lane >> 2) + 8 * (j >> 1);
                int c = nt * 8 + 2 * (lane & 3) + (j & 1);
                red[r * 130 + c] = acc[nt][j];
            }
    }
    __syncthreads();
    if (kw == 0) {
#pragma unroll
        for (int nt = 0; nt < 16; nt++) {
            int cb = nt * 8 + 2 * (lane & 3);
            int rA = mw * 16 + (lane >> 2), rB = rA + 8;
            acc[nt][0] += red[rA * 130 + cb]     + fc_b[cb];
            acc[nt][1] += red[rA * 130 + cb + 1] + fc_b[cb + 1];
            acc[nt][2] += red[rB * 130 + cb]     + fc_b[cb];
            acc[nt][3] += red[rB * 130 + cb + 1] + fc_b[cb + 1];
        }
        float s0 = 0.f, s1 = 0.f;
#pragma unroll
        for (int nt = 0; nt < 16; nt++) {
            s0 += acc[nt][0] + acc[nt][1];
            s1 += acc[nt][2] + acc[nt][3];
        }
        s0 += __shfl_xor_sync(~0u, s0, 1); s0 += __shfl_xor_sync(~0u, s0, 2);
        s1 += __shfl_xor_sync(~0u, s1, 1); s1 += __shfl_xor_sync(~0u, s1, 2);
        float m0 = s0 * (1.f / 128.f), m1 = s1 * (1.f / 128.f);
        float q0 = 0.f, q1 = 0.f;
#pragma unroll
        for (int nt = 0; nt < 16; nt++) {
            float d0 = acc[nt][0] - m0, d1 = acc[nt][1] - m0;
            float d2 = acc[nt][2] - m1, d3 = acc[nt][3] - m1;
            q0 += d0 * d0 + d1 * d1;
            q1 += d2 * d2 + d3 * d3;
        }
        q0 += __shfl_xor_sync(~0u, q0, 1); q0 += __shfl_xor_sync(~0u, q0, 2);
        q1 += __shfl_xor_sync(~0u, q1, 1); q1 += __shfl_xor_sync(~0u, q1, 2);
        float rs0 = rsqrtf(q0 * (1.f / 128.f) + EPS);
        float rs1 = rsqrtf(q1 * (1.f / 128.f) + EPS);
        int gr0 = n0 + mw * 16 + (lane >> 2), gr1 = gr0 + 8;
#pragma unroll
        for (int nt = 0; nt < 16; nt++) {
            int c = nt * 8 + 2 * (lane & 3);
            float g0 = ln_g[c], g1 = ln_g[c + 1], bb0 = ln_b[c], bb1 = ln_b[c + 1];
            float v0 = fmaxf((acc[nt][0] - m0) * rs0 * g0 + bb0, 0.f);
            float v1 = fmaxf((acc[nt][1] - m0) * rs0 * g1 + bb1, 0.f);
            float v2 = fmaxf((acc[nt][2] - m1) * rs1 * g0 + bb0, 0.f);
            float v3 = fmaxf((acc[nt][3] - m1) * rs1 * g1 + bb1, 0.f);
            *(float2*)(g_roi + (size_t)gr0 * 128 + c) = make_float2(v0, v1);
            *(float2*)(g_roi + (size_t)gr1 * 128 + c) = make_float2(v2, v3);
        }
    }
}

// ---------------- k/v at the 250 nearest-resize sample points ----------------
__global__ __launch_bounds__(256)
void kv_kernel(const float* __restrict__ fmap, const float* __restrict__ key_w,
               const float* __restrict__ key_g, const float* __restrict__ key_beta,
               const float* __restrict__ key_m, const float* __restrict__ key_v,
               const float* __restrict__ val_w, const float* __restrict__ val_b) {
    __shared__ float fc_s[25 * 129];
    const int b = blockIdx.x, r = blockIdx.y;
    const int tid = threadIdx.x;
    for (int i = tid; i < 25 * 128; i += 256) {
        int c = i / 25, pos = i % 25;
        fc_s[pos * 129 + c] = fmap[((b * 128 + c) * 40 + 4 * r) * 100 + 4 * pos];
    }
    __syncthreads();
    for (int i = tid; i < 25 * 128; i += 256) {
        int o = i % 128, pos = i / 128;
        const float* kw = key_w + o * 128;
        const float* vw = val_w + o * 128;
        float ka = 0.f, va = 0.f;
#pragma unroll 4
        for (int c = 0; c < 128; c++) {
            float xv = fc_s[pos * 129 + c];
            ka = fmaf(kw[c], xv, ka);
            va = fmaf(vw[c], xv, va);
        }
        float sc = key_g[o] * rsqrtf(key_v[o] + EPS);
        float kb = key_beta[o] - key_m[o] * sc;
        float kk = fmaf(ka, sc, kb);
        int l = r * 25 + pos;
        g_k[(b * 128 + o) * LL + l] = kk > 0.f ? kk : 0.f;
        g_v[(b * LL + l) * 128 + o] = va + val_b[o];
    }
}

// ---------------- attention: block = (b, 32 priors) --------------------------
__global__ __launch_bounds__(256)
void attn_kernel(const float* __restrict__ q_w, const float* __restrict__ q_b,
                 const float* __restrict__ gate_w, const float* __restrict__ gate_b,
                 float* __restrict__ out) {
    __shared__ float q_s[32 * 129];
    __shared__ float p_s[32 * 251];
    const int b = blockIdx.x, p0 = blockIdx.y * 32;
    const int tid = threadIdx.x;

    for (int i = tid; i < 32 * 128; i += 256) {
        int p = i / 128, f = i % 128;
        float qq = fmaf(g_roi[(b * NP + p0 + p) * 128 + f], q_w[p0 + p], q_b[p0 + p]);
        q_s[p * 129 + f] = qq > 0.f ? qq : 0.f;
    }
    __syncthreads();

    const float scale = 0.08838834764831845f;
    for (int idx = tid; idx < 32 * LL; idx += 256) {
        int p = idx % 32, l = idx / 32;
        const float* krow = g_k + b * 128 * LL + l;
        float a = 0.f;
#pragma unroll 4
        for (int f = 0; f < 128; f++)
            a = fmaf(q_s[p * 129 + f], krow[f * LL], a);
        p_s[p * 251 + l] = a * scale;
    }
    __syncthreads();

    const int warp = tid / 32, lane = tid % 32;
    for (int rr = 0; rr < 4; rr++) {
        int p = warp * 4 + rr;
        float mx = -1e30f;
        for (int l = lane; l < LL; l += 32) mx = fmaxf(mx, p_s[p * 251 + l]);
        for (int d = 16; d >= 1; d >>= 1) mx = fmaxf(mx, __shfl_xor_sync(~0u, mx, d));
        float sm = 0.f;
        for (int l = lane; l < LL; l += 32) {
            float e = __expf(p_s[p * 251 + l] - mx);
            p_s[p * 251 + l] = e;
            sm += e;
        }
        for (int d = 16; d >= 1; d >>= 1) sm += __shfl_xor_sync(~0u, sm, d);
        float inv = 1.f / sm;
        for (int l = lane; l < LL; l += 32) p_s[p * 251 + l] *= inv;
    }
    __syncthreads();

    float* v_s = q_s;
    float acc[16];
#pragma unroll
    for (int it = 0; it < 16; it++) acc[it] = 0.f;
    const int f = tid % 128, pb = tid / 128;
    for (int lc = 0; lc < LL; lc += 32) {
        int lim = min(32, LL - lc);
        __syncthreads();
        for (int i = tid; i < lim * 128; i += 256)
            v_s[i] = g_v[(b * LL + lc + i / 128) * 128 + (i % 128)];
        __syncthreads();
#pragma unroll
        for (int it = 0; it < 16; it++) {
            int p = pb + 2 * it;
            float a = acc[it];
            for (int l = 0; l < lim; l++)
                a = fmaf(p_s[p * 251 + lc + l], v_s[l * 128 + f], a);
            acc[it] = a;
        }
    }
#pragma unroll
    for (int it = 0; it < 16; it++) {
        int gp = p0 + pb + 2 * it;
        float ctx = fmaf(acc[it], gate_w[gp], gate_b[gp]);
        out[(b * NP + gp) * 128 + f] = g_roi[(b * NP + gp) * 128 + f] + ctx;
    }
}

// ---------------- host launcher ----------------------------------------------
extern "C" void kernel_launch(void* const* d_in, const int* in_sizes, int n_in,
                              void* d_out, int out_size) {
    (void)in_sizes; (void)n_in; (void)out_size;
    const float* roi0   = (const float*)d_in[0];
    const float* roi1   = (const float*)d_in[1];
    const float* roi2   = (const float*)d_in[2];
    const float* fmap   = (const float*)d_in[3];
    const float* conv_w = (const float*)d_in[4];
    const float* conv_g = (const float*)d_in[5];
    const float* conv_b = (const float*)d_in[6];
    const float* conv_m = (const float*)d_in[7];
    const float* conv_v = (const float*)d_in[8];
    const float* cat_w  = (const float*)d_in[9];
    const float* cat_g  = (const float*)d_in[10];
    const float* cat_b  = (const float*)d_in[11];
    const float* cat_m  = (const float*)d_in[12];
    const float* cat_v  = (const float*)d_in[13];
    const float* fc_w   = (const float*)d_in[14];
    const float* fc_b   = (const float*)d_in[15];
    const float* ln_g   = (const float*)d_in[16];
    const float* ln_b   = (const float*)d_in[17];
    const float* key_w  = (const float*)d_in[18];
    const float* key_g  = (const float*)d_in[19];
    const float* key_bt = (const float*)d_in[20];
    const float* key_m  = (const float*)d_in[21];
    const float* key_v  = (const float*)d_in[22];
    const float* q_w    = (const float*)d_in[23];
    const float* q_b    = (const float*)d_in[24];
    const float* val_w  = (const float*)d_in[25];
    const float* val_b  = (const float*)d_in[26];
    const float* gate_w = (const float*)d_in[27];
    const float* gate_b = (const float*)d_in[28];
    float* out = (float*)d_out;

    float *x32, *cat1, *cat2, *wfL, *wfC;
    cudaGetSymbolAddress((void**)&x32,  g_x32);
    cudaGetSymbolAddress((void**)&cat1, g_cat1);
    cudaGetSymbolAddress((void**)&cat2, g_cat2);
    cudaGetSymbolAddress((void**)&wfL,  g_wfL);
    cudaGetSymbolAddress((void**)&wfC,  g_wfC);

    // prep passes
    cvt_roi<<<dim3(27648, 3), 256>>>(roi0, roi1, roi2);
    prep_w<128, 64><<<dim3(288, 3), 256>>>(conv_w, wfL, 64 * 128 * 9);
    prep_w<192, 128><<<dim3(864, 1), 256>>>(cat_w, wfC, 0);
    cvt_fcw<<<(FCH * KFC + 255) / 256, 256>>>(fc_w);

    // three level convs (y = level) -> g_cat1
    conv_mma<128, 64, 16, 192><<<dim3(NTOT / 16, 3), 512>>>(
        x32, wfL, conv_g, conv_b, conv_m, conv_v, cat1);

    // cat conv -> g_cat2
    conv_mma<192, 128, 8, 128><<<dim3(NTOT / 8, 1), 512>>>(
        cat1, wfC, cat_g, cat_b, cat_m, cat_v, cat2);

    fc_ln_relu<<<192, 128>>>(fc_b, ln_g, ln_b);

    kv_kernel<<<dim3(BB, 10), 256>>>(fmap, key_w, key_g, key_bt, key_m, key_v,
                                     val_w, val_b);

    attn_kernel<<<dim3(BB, NP / 32), 256>>>(q_w, q_b, gate_w, gate_b, out);
}

// round 9
// speedup vs baseline: 3.0103x; 1.2187x over previous
#include <cuda_runtime.h>
#include <cuda_fp16.h>
#include <cstdint>

#define BB    32
#define NP    192
#define CC    128
#define NSS   36
#define FCH   128
#define EPS   1e-5f
#define NTOT  (BB*NP)      // 6144
#define LL    250
#define KFC   (CC*NSS)     // 4608

// ---------------- scratch (device globals; no runtime allocation) -------------
__device__ __align__(16) __half g_x16 [3 * NTOT * CC * NSS];  // fp16 roi, [n][s][ci]
__device__ __align__(16) __half g_cat1[NTOT * NSS * 192];     // level out, [n][s][c]
__device__ __align__(16) __half g_cat2[NTOT * NSS * CC];      // cat out,  [n][s][c]
__device__ float  g_roi [BB * NP * FCH];        // fc+LN+ReLU output (fp32)
__device__ float  g_k   [BB * CC * LL];         // keys   (b, f, l)
__device__ float  g_v   [BB * LL * CC];         // values (b, l, f)
__device__ __align__(16) __half g_fcw16[FCH * KFC];           // fc_w fp16, [f][k'], k'=s*128+c
__device__ __align__(16) __half g_wfL [3 * 8 * 9 * 4 * 32 * 8];   // level weight frags
__device__ __align__(16) __half g_wfC [12 * 9 * 8 * 32 * 8];      // cat weight frags

// ---------------- helpers ----------------------------------------------------
__device__ __forceinline__ uint32_t smem_u32(const void* p) {
    uint32_t a;
    asm("{ .reg .u64 t; cvta.to.shared.u64 t, %1; cvt.u32.u64 %0, t; }"
        : "=r"(a) : "l"(p));
    return a;
}
__device__ __forceinline__ void cp16(uint32_t s, const void* g) {
    asm volatile("cp.async.cg.shared.global [%0], [%1], 16;" :: "r"(s), "l"(g));
}
__device__ __forceinline__ void mma_f16(float* c, const uint4& a,
                                        uint32_t b0, uint32_t b1) {
    asm volatile("mma.sync.aligned.m16n8k16.row.col.f32.f16.f16.f32 "
                 "{%0,%1,%2,%3}, {%4,%5,%6,%7}, {%8,%9}, {%0,%1,%2,%3};"
                 : "+f"(c[0]), "+f"(c[1]), "+f"(c[2]), "+f"(c[3])
                 : "r"(a.x), "r"(a.y), "r"(a.z), "r"(a.w), "r"(b0), "r"(b1));
}
__device__ __forceinline__ __half relu_h(float v) {
    return __float2half_rn(v > 0.f ? v : 0.f);
}

// ---------------- input transpose + fp16: x[n][ci][s] -> g_x16[n][s][ci] ------
__global__ __launch_bounds__(256)
void cvt_roi(const float* __restrict__ r0, const float* __restrict__ r1,
             const float* __restrict__ r2) {
    __shared__ float t_s[128 * 37];
    const int n = blockIdx.x, lvl = blockIdx.y, tid = threadIdx.x;
    const float* src = ((lvl == 0) ? r0 : (lvl == 1) ? r1 : r2) + (size_t)n * CC * NSS;
    __half* dst = g_x16 + ((size_t)lvl * NTOT + n) * NSS * CC;
    for (int i = tid; i < 128 * 36; i += 256) {
        int ci = i / 36, s = i % 36;
        t_s[ci * 37 + s] = src[i];
    }
    __syncthreads();
    for (int i = tid; i < 128 * 36; i += 256) {
        int s = i >> 7, ci = i & 127;
        dst[i] = __float2half_rn(t_s[ci * 37 + s]);
    }
}

// ---------------- weight fragment pre-permute (fp16, m16n8k16) ----------------
template<int CIN, int COUT>
__global__ void prep_w(const float* __restrict__ w, __half* __restrict__ dst,
                       int wstride) {
    constexpr int NCH = CIN / 16;
    constexpr int MT  = COUT / 16;
    const int lvl = blockIdx.y;
    const int idx = blockIdx.x * 256 + threadIdx.x;
    const int total = NCH * 9 * MT * 32 * 8;
    if (idx >= total) return;
    int hh = idx & 7, lane = (idx >> 3) & 31;
    int t3 = idx >> 8;
    int mt = t3 % MT, g = (t3 / MT) % 9, cb = t3 / (MT * 9);
    int j = hh >> 1, inner = hh & 1;
    int r  = (lane >> 2) + 8 * (j & 1);
    int kk = 2 * (lane & 3) + inner + 8 * (j >> 1);
    int m  = mt * 16 + r;
    int ci = cb * 16 + kk;
    dst[(size_t)lvl * total + idx] =
        __float2half_rn(w[(size_t)lvl * wstride + (size_t)m * (CIN * 9) + ci * 9 + g]);
}

// ---------------- fc_w fp16 + K-permute: k' = s*128 + c ----------------------
__global__ void cvt_fcw(const float* __restrict__ w) {
    int idx = blockIdx.x * 256 + threadIdx.x;
    if (idx < FCH * KFC) {
        int f = idx / KFC, kp = idx % KFC;
        int s = kp >> 7, c = kp & 127;
        g_fcw16[idx] = __float2half_rn(w[(size_t)f * KFC + c * NSS + s]);
    }
}

// ---------------- conv9 + folded BN + ReLU via fp16 mma.sync -----------------
// A = weight fragments (LDG.128), B = im2col windows [samp][pos][16ci] fp16.
// pos stride 24 halves (48B): cp.async dst 16B-aligned; frag LDS conflict-free.
template<int CIN, int COUT, int NSAMP, int CSTRIDE, int THREADS>
__global__ __launch_bounds__(THREADS, 512 / THREADS)
void conv_mma(const __half* __restrict__ xg, const __half* __restrict__ wfrag_,
              const float* __restrict__ bng, const float* __restrict__ bnb,
              const float* __restrict__ bnm, const float* __restrict__ bnv,
              __half* __restrict__ out) {
    constexpr int NCH  = CIN / 16;
    constexpr int MT   = COUT / 16;
    constexpr int NWM  = (THREADS / 32) / NSAMP;     // 1 (level) or 2 (cat)
    constexpr int SSTR = 44 * 24;                    // halves per sample
    constexpr int CHF  = 9 * MT * 32;                // uint4 frags per chunk

    __shared__ __align__(16) __half x_s[2][NSAMP * SSTR];

    const int tid  = threadIdx.x;
    const int wid  = tid >> 5, lane = tid & 31;
    const int lvl  = blockIdx.y;
    const __half* x = xg + (size_t)lvl * NTOT * NSS * CIN;
    const uint4* wf4 = (const uint4*)(wfrag_ + (size_t)lvl * NCH * CHF * 8);
    const int c0   = lvl * COUT;
    bng += lvl * COUT; bnb += lvl * COUT; bnm += lvl * COUT; bnv += lvl * COUT;

    const int samp = wid / NWM;
    const int mt0  = (wid % NWM) * 4;
    const int n0   = blockIdx.x * NSAMP;
    const int sampbase = samp * SSTR;

    const uint32_t xs0 = smem_u32(&x_s[0][0]), xs1 = smem_u32(&x_s[1][0]);

    for (int i = tid; i < 2 * NSAMP * SSTR; i += THREADS) ((__half*)x_s)[i] = __half(0.f);
    __syncthreads();

    int col[5];
#pragma unroll
    for (int nt = 0; nt < 5; nt++) {
        int cb = nt * 8 + (lane >> 2);
        col[nt] = cb < 36 ? cb : 35;
    }

    float acc[4][5][4];
#pragma unroll
    for (int mt = 0; mt < 4; mt++)
#pragma unroll
        for (int nt = 0; nt < 5; nt++)
#pragma unroll
            for (int j = 0; j < 4; j++) acc[mt][nt][j] = 0.f;

    // stage ci-block cb into buffer buf: per samp, 36 pos x 16 halves (2x 16B)
    auto stage = [&](int cb, int buf) {
        const uint32_t base = buf ? xs1 : xs0;
        for (int i = tid; i < NSAMP * 72; i += THREADS) {
            int hh = i & 1, s = (i >> 1) % 36, sp = i / 72;
            cp16(base + (uint32_t)(sp * SSTR + (s + 4) * 24 + hh * 8) * 2,
                 x + ((size_t)(n0 + sp) * 36 + s) * CIN + cb * 16 + hh * 8);
        }
        asm volatile("cp.async.commit_group;");
    };

    stage(0, 0);

    for (int cb = 0; cb < NCH; cb++) {
        if (cb + 1 < NCH) {
            stage(cb + 1, (cb + 1) & 1);
            asm volatile("cp.async.wait_group 1;");
        } else {
            asm volatile("cp.async.wait_group 0;");
        }
        __syncthreads();

        const __half* xs = x_s[cb & 1] + sampbase;
        const uint4* wfc = wf4 + (size_t)cb * CHF;
#pragma unroll
        for (int g = 0; g < 9; g++) {
            uint4 af[4];
#pragma unroll
            for (int mt = 0; mt < 4; mt++)
                af[mt] = __ldg(&wfc[(g * MT + mt0 + mt) * 32 + lane]);
#pragma unroll
            for (int nt = 0; nt < 5; nt++) {
                int off = (col[nt] + g) * 24 + 2 * (lane & 3);
                uint32_t b0 = *(const uint32_t*)&xs[off];
                uint32_t b1 = *(const uint32_t*)&xs[off + 8];
#pragma unroll
                for (int mt = 0; mt < 4; mt++)
                    mma_f16(acc[mt][nt], af[mt], b0, b1);
            }
        }
        __syncthreads();
    }

    // epilogue: folded BN + ReLU -> fp16 [n][s][c]
    const int nidx = n0 + samp;
#pragma unroll
    for (int mt = 0; mt < 4; mt++) {
        int cobase = (mt0 + mt) * 16 + (lane >> 2);
#pragma unroll
        for (int h = 0; h < 2; h++) {
            int co = cobase + 8 * h;
            float sc = bng[co] * rsqrtf(bnv[co] + EPS);
            float bi = bnb[co] - bnm[co] * sc;
#pragma unroll
            for (int nt = 0; nt < 5; nt++) {
                int s0 = nt * 8 + 2 * (lane & 3);
                if (s0 < 36) {
                    out[((size_t)nidx * 36 + s0) * CSTRIDE + c0 + co] =
                        relu_h(fmaf(acc[mt][nt][2 * h], sc, bi));
                    out[((size_t)nidx * 36 + s0 + 1) * CSTRIDE + c0 + co] =
                        relu_h(fmaf(acc[mt][nt][2 * h + 1], sc, bi));
                }
            }
        }
    }
}

// ---------------- FC via fp16 mma.sync, fused LayerNorm + ReLU ---------------
__global__ __launch_bounds__(128, 1)
void fc_ln_relu(const float* __restrict__ fc_b, const float* __restrict__ ln_g,
                const float* __restrict__ ln_b) {
    __shared__ __align__(16) __half A_s[2][32][40];
    __shared__ __align__(16) __half B_s[2][128][40];

    const int tid = threadIdx.x, lane = tid & 31, wid = tid >> 5;
    const int mw = wid & 1, kw = wid >> 1;
    const int n0 = blockIdx.x * 32;
    const int r0 = mw * 16 + (lane >> 2);
    const int q2 = 2 * (lane & 3);

    float acc[16][4];
#pragma unroll
    for (int nt = 0; nt < 16; nt++)
#pragma unroll
        for (int j = 0; j < 4; j++) acc[nt][j] = 0.f;

    for (int ch = 0; ch < 72; ch++) {
        const int k0 = ch * 64;
        __syncthreads();
#pragma unroll
        for (int it = 0; it < 2; it++) {
            int i = tid + it * 128;
            int q = i & 3, r = (i >> 2) & 31, s = i >> 7;
            *(uint4*)&A_s[s][r][q * 8] =
                *(const uint4*)(g_cat2 + (size_t)(n0 + r) * KFC + k0 + s * 32 + q * 8);
        }
#pragma unroll
        for (int it = 0; it < 8; it++) {
            int i = tid + it * 128;
            int q = i & 3, f = (i >> 2) & 127, s = i >> 9;
            *(uint4*)&B_s[s][f][q * 8] =
                *(const uint4*)(g_fcw16 + (size_t)f * KFC + k0 + s * 32 + q * 8);
        }
        __syncthreads();

#pragma unroll
        for (int g = 0; g < 2; g++) {
            int kk = g * 16 + q2;
            uint4 a;
            a.x = *(const uint32_t*)&A_s[kw][r0][kk];
            a.y = *(const uint32_t*)&A_s[kw][r0 + 8][kk];
            a.z = *(const uint32_t*)&A_s[kw][r0][kk + 8];
            a.w = *(const uint32_t*)&A_s[kw][r0 + 8][kk + 8];
#pragma unroll
            for (int nt = 0; nt < 16; nt++) {
                int f = nt * 8 + (lane >> 2);
                uint32_t b0 = *(const uint32_t*)&B_s[kw][f][kk];
                uint32_t b1 = *(const uint32_t*)&B_s[kw][f][kk + 8];
                mma_f16(acc[nt], a, b0, b1);
            }
        }
    }

    __syncthreads();
    float* red = (float*)&B_s[0][0][0];     // 32 x 130 fp32 = 16.6KB < 20.5KB
    if (kw == 1) {
#pragma unroll
        for (int nt = 0; nt < 16; nt++)
#pragma unroll
            for (int j = 0; j < 4; j++) {
                int r = mw * 16 + (lane >> 2) + 8 * (j >> 1);
                int c = nt * 8 + 2 * (lane & 3) + (j & 1);
                red[r * 130 + c] = acc[nt][j];
            }
    }
    __syncthreads();
    if (kw == 0) {
#pragma unroll
        for (int nt = 0; nt < 16; nt++) {
            int cb = nt * 8 + 2 * (lane & 3);
            int rA = mw * 16 + (lane >> 2), rB = rA + 8;
            acc[nt][0] += red[rA * 130 + cb]     + fc_b[cb];
            acc[nt][1] += red[rA * 130 + cb + 1] + fc_b[cb + 1];
            acc[nt][2] += red[rB * 130 + cb]     + fc_b[cb];
            acc[nt][3] += red[rB * 130 + cb + 1] + fc_b[cb + 1];
        }
        float s0 = 0.f, s1 = 0.f;
#pragma unroll
        for (int nt = 0; nt < 16; nt++) {
            s0 += acc[nt][0] + acc[nt][1];
            s1 += acc[nt][2] + acc[nt][3];
        }
        s0 += __shfl_xor_sync(~0u, s0, 1); s0 += __shfl_xor_sync(~0u, s0, 2);
        s1 += __shfl_xor_sync(~0u, s1, 1); s1 += __shfl_xor_sync(~0u, s1, 2);
        float m0 = s0 * (1.f / 128.f), m1 = s1 * (1.f / 128.f);
        float q0 = 0.f, q1 = 0.f;
#pragma unroll
        for (int nt = 0; nt < 16; nt++) {
            float d0 = acc[nt][0] - m0, d1 = acc[nt][1] - m0;
            float d2 = acc[nt][2] - m1, d3 = acc[nt][3] - m1;
            q0 += d0 * d0 + d1 * d1;
            q1 += d2 * d2 + d3 * d3;
        }
        q0 += __shfl_xor_sync(~0u, q0, 1); q0 += __shfl_xor_sync(~0u, q0, 2);
        q1 += __shfl_xor_sync(~0u, q1, 1); q1 += __shfl_xor_sync(~0u, q1, 2);
        float rs0 = rsqrtf(q0 * (1.f / 128.f) + EPS);
        float rs1 = rsqrtf(q1 * (1.f / 128.f) + EPS);
        int gr0 = n0 + mw * 16 + (lane >> 2), gr1 = gr0 + 8;
#pragma unroll
        for (int nt = 0; nt < 16; nt++) {
            int c = nt * 8 + 2 * (lane & 3);
            float g0 = ln_g[c], g1 = ln_g[c + 1], bb0 = ln_b[c], bb1 = ln_b[c + 1];
            float v0 = fmaxf((acc[nt][0] - m0) * rs0 * g0 + bb0, 0.f);
            float v1 = fmaxf((acc[nt][1] - m0) * rs0 * g1 + bb1, 0.f);
            float v2 = fmaxf((acc[nt][2] - m1) * rs1 * g0 + bb0, 0.f);
            float v3 = fmaxf((acc[nt][3] - m1) * rs1 * g1 + bb1, 0.f);
            *(float2*)(g_roi + (size_t)gr0 * 128 + c) = make_float2(v0, v1);
            *(float2*)(g_roi + (size_t)gr1 * 128 + c) = make_float2(v2, v3);
        }
    }
}

// ---------------- k/v at the 250 nearest-resize sample points ----------------
__global__ __launch_bounds__(256)
void kv_kernel(const float* __restrict__ fmap, const float* __restrict__ key_w,
               const float* __restrict__ key_g, const float* __restrict__ key_beta,
               const float* __restrict__ key_m, const float* __restrict__ key_v,
               const float* __restrict__ val_w, const float* __restrict__ val_b) {
    __shared__ float fc_s[25 * 129];
    const int b = blockIdx.x, r = blockIdx.y;
    const int tid = threadIdx.x;
    for (int i = tid; i < 25 * 128; i += 256) {
        int c = i / 25, pos = i % 25;
        fc_s[pos * 129 + c] = fmap[((b * 128 + c) * 40 + 4 * r) * 100 + 4 * pos];
    }
    __syncthreads();
    for (int i = tid; i < 25 * 128; i += 256) {
        int o = i % 128, pos = i / 128;
        const float* kw = key_w + o * 128;
        const float* vw = val_w + o * 128;
        float ka = 0.f, va = 0.f;
#pragma unroll 4
        for (int c = 0; c < 128; c++) {
            float xv = fc_s[pos * 129 + c];
            ka = fmaf(kw[c], xv, ka);
            va = fmaf(vw[c], xv, va);
        }
        float sc = key_g[o] * rsqrtf(key_v[o] + EPS);
        float kb = key_beta[o] - key_m[o] * sc;
        float kk = fmaf(ka, sc, kb);
        int l = r * 25 + pos;
        g_k[(b * 128 + o) * LL + l] = kk > 0.f ? kk : 0.f;
        g_v[(b * LL + l) * 128 + o] = va + val_b[o];
    }
}

// ---------------- attention: block = (b, 32 priors) --------------------------
__global__ __launch_bounds__(256)
void attn_kernel(const float* __restrict__ q_w, const float* __restrict__ q_b,
                 const float* __restrict__ gate_w, const float* __restrict__ gate_b,
                 float* __restrict__ out) {
    __shared__ float q_s[32 * 129];
    __shared__ float p_s[32 * 251];
    const int b = blockIdx.x, p0 = blockIdx.y * 32;
    const int tid = threadIdx.x;

    for (int i = tid; i < 32 * 128; i += 256) {
        int p = i / 128, f = i % 128;
        float qq = fmaf(g_roi[(b * NP + p0 + p) * 128 + f], q_w[p0 + p], q_b[p0 + p]);
        q_s[p * 129 + f] = qq > 0.f ? qq : 0.f;
    }
    __syncthreads();

    const float scale = 0.08838834764831845f;
    for (int idx = tid; idx < 32 * LL; idx += 256) {
        int p = idx % 32, l = idx / 32;
        const float* krow = g_k + b * 128 * LL + l;
        float a = 0.f;
#pragma unroll 4
        for (int f = 0; f < 128; f++)
            a = fmaf(q_s[p * 129 + f], krow[f * LL], a);
        p_s[p * 251 + l] = a * scale;
    }
    __syncthreads();

    const int warp = tid / 32, lane = tid % 32;
    for (int rr = 0; rr < 4; rr++) {
        int p = warp * 4 + rr;
        float mx = -1e30f;
        for (int l = lane; l < LL; l += 32) mx = fmaxf(mx, p_s[p * 251 + l]);
        for (int d = 16; d >= 1; d >>= 1) mx = fmaxf(mx, __shfl_xor_sync(~0u, mx, d));
        float sm = 0.f;
        for (int l = lane; l < LL; l += 32) {
            float e = __expf(p_s[p * 251 + l] - mx);
            p_s[p * 251 + l] = e;
            sm += e;
        }
        for (int d = 16; d >= 1; d >>= 1) sm += __shfl_xor_sync(~0u, sm, d);
        float inv = 1.f / sm;
        for (int l = lane; l < LL; l += 32) p_s[p * 251 + l] *= inv;
    }
    __syncthreads();

    float* v_s = q_s;
    float acc[16];
#pragma unroll
    for (int it = 0; it < 16; it++) acc[it] = 0.f;
    const int f = tid % 128, pb = tid / 128;
    for (int lc = 0; lc < LL; lc += 32) {
        int lim = min(32, LL - lc);
        __syncthreads();
        for (int i = tid; i < lim * 128; i += 256)
            v_s[i] = g_v[(b * LL + lc + i / 128) * 128 + (i % 128)];
        __syncthreads();
#pragma unroll
        for (int it = 0; it < 16; it++) {
            int p = pb + 2 * it;
            float a = acc[it];
            for (int l = 0; l < lim; l++)
                a = fmaf(p_s[p * 251 + lc + l], v_s[l * 128 + f], a);
            acc[it] = a;
        }
    }
#pragma unroll
    for (int it = 0; it < 16; it++) {
        int gp = p0 + pb + 2 * it;
        float ctx = fmaf(acc[it], gate_w[gp], gate_b[gp]);
        out[(b * NP + gp) * 128 + f] = g_roi[(b * NP + gp) * 128 + f] + ctx;
    }
}

// ---------------- host launcher ----------------------------------------------
extern "C" void kernel_launch(void* const* d_in, const int* in_sizes, int n_in,
                              void* d_out, int out_size) {
    (void)in_sizes; (void)n_in; (void)out_size;
    const float* roi0   = (const float*)d_in[0];
    const float* roi1   = (const float*)d_in[1];
    const float* roi2   = (const float*)d_in[2];
    const float* fmap   = (const float*)d_in[3];
    const float* conv_w = (const float*)d_in[4];
    const float* conv_g = (const float*)d_in[5];
    const float* conv_b = (const float*)d_in[6];
    const float* conv_m = (const float*)d_in[7];
    const float* conv_v = (const float*)d_in[8];
    const float* cat_w  = (const float*)d_in[9];
    const float* cat_g  = (const float*)d_in[10];
    const float* cat_b  = (const float*)d_in[11];
    const float* cat_m  = (const float*)d_in[12];
    const float* cat_v  = (const float*)d_in[13];
    const float* fc_w   = (const float*)d_in[14];
    const float* fc_b   = (const float*)d_in[15];
    const float* ln_g   = (const float*)d_in[16];
    const float* ln_b   = (const float*)d_in[17];
    const float* key_w  = (const float*)d_in[18];
    const float* key_g  = (const float*)d_in[19];
    const float* key_bt = (const float*)d_in[20];
    const float* key_m  = (const float*)d_in[21];
    const float* key_v  = (const float*)d_in[22];
    const float* q_w    = (const float*)d_in[23];
    const float* q_b    = (const float*)d_in[24];
    const float* val_w  = (const float*)d_in[25];
    const float* val_b  = (const float*)d_in[26];
    const float* gate_w = (const float*)d_in[27];
    const float* gate_b = (const float*)d_in[28];
    float* out = (float*)d_out;

    __half *x16, *cat1, *cat2, *wfL, *wfC;
    cudaGetSymbolAddress((void**)&x16,  g_x16);
    cudaGetSymbolAddress((void**)&cat1, g_cat1);
    cudaGetSymbolAddress((void**)&cat2, g_cat2);
    cudaGetSymbolAddress((void**)&wfL,  g_wfL);
    cudaGetSymbolAddress((void**)&wfC,  g_wfC);

    // prep passes
    cvt_roi<<<dim3(NTOT, 3), 256>>>(roi0, roi1, roi2);
    prep_w<128, 64><<<dim3(288, 3), 256>>>(conv_w, wfL, 64 * 128 * 9);
    prep_w<192, 128><<<dim3(864, 1), 256>>>(cat_w, wfC, 0);
    cvt_fcw<<<(FCH * KFC + 255) / 256, 256>>>(fc_w);

    // three level convs (y = level) -> g_cat1
    conv_mma<128, 64, 8, 192, 256><<<dim3(NTOT / 8, 3), 256>>>(
        x16, wfL, conv_g, conv_b, conv_m, conv_v, cat1);

    // cat conv -> g_cat2
    conv_mma<192, 128, 8, 128, 512><<<dim3(NTOT / 8, 1), 512>>>(
        cat1, wfC, cat_g, cat_b, cat_m, cat_v, cat2);

    fc_ln_relu<<<192, 128>>>(fc_b, ln_g, ln_b);

    kv_kernel<<<dim3(BB, 10), 256>>>(fmap, key_w, key_g, key_bt, key_m, key_v,
                                     val_w, val_b);

    attn_kernel<<<dim3(BB, NP / 32), 256>>>(q_w, q_b, gate_w, gate_b, out);
}

// round 11
// speedup vs baseline: 3.3335x; 1.1074x over previous
#include <cuda_runtime.h>
#include <cuda_fp16.h>
#include <cstdint>

#define BB    32
#define NP    192
#define CC    128
#define NSS   36
#define FCH   128
#define EPS   1e-5f
#define NTOT  (BB*NP)      // 6144
#define LL    250
#define LPAD  256
#define KFC   (CC*NSS)     // 4608

// ---------------- scratch (device globals; no runtime allocation) -------------
__device__ __align__(16) __half g_x16 [3 * NTOT * CC * NSS];  // fp16 roi, [n][s][ci]
__device__ __align__(16) __half g_cat1[NTOT * NSS * 192];     // level out, [n][s][c]
__device__ __align__(16) __half g_cat2[NTOT * NSS * CC];      // cat out,  [n][s][c]
__device__ float  g_roi [BB * NP * FCH];                      // fc+LN+ReLU (fp32)
__device__ __align__(16) __half g_k16[BB * LPAD * CC];        // keys  [b][l][f], l>=250 zero
__device__ __align__(16) __half g_v16[BB * CC * LPAD];        // vals  [b][f][l], l>=250 zero
__device__ __align__(16) __half g_fcw16[FCH * KFC];           // fc_w fp16 [f][k'], k'=s*128+c
__device__ __align__(16) __half g_wfL [3 * 8 * 9 * 4 * 32 * 8];   // level weight frags
__device__ __align__(16) __half g_wfC [12 * 9 * 8 * 32 * 8];      // cat weight frags

// ---------------- helpers ----------------------------------------------------
__device__ __forceinline__ uint32_t smem_u32(const void* p) {
    uint32_t a;
    asm("{ .reg .u64 t; cvta.to.shared.u64 t, %1; cvt.u32.u64 %0, t; }"
        : "=r"(a) : "l"(p));
    return a;
}
__device__ __forceinline__ void cp16(uint32_t s, const void* g) {
    asm volatile("cp.async.cg.shared.global [%0], [%1], 16;" :: "r"(s), "l"(g));
}
__device__ __forceinline__ void mma_f16(float* c, const uint4& a,
                                        uint32_t b0, uint32_t b1) {
    asm volatile("mma.sync.aligned.m16n8k16.row.col.f32.f16.f16.f32 "
                 "{%0,%1,%2,%3}, {%4,%5,%6,%7}, {%8,%9}, {%0,%1,%2,%3};"
                 : "+f"(c[0]), "+f"(c[1]), "+f"(c[2]), "+f"(c[3])
                 : "r"(a.x), "r"(a.y), "r"(a.z), "r"(a.w), "r"(b0), "r"(b1));
}
__device__ __forceinline__ __half relu_h(float v) {
    return __float2half_rn(v > 0.f ? v : 0.f);
}

// ---------------- input transpose + fp16: x[n][ci][s] -> g_x16[n][s][ci] ------
__global__ __launch_bounds__(256)
void cvt_roi(const float* __restrict__ r0, const float* __restrict__ r1,
             const float* __restrict__ r2) {
    __shared__ float t_s[128 * 37];
    const int n = blockIdx.x, lvl = blockIdx.y, tid = threadIdx.x;
    const float* src = ((lvl == 0) ? r0 : (lvl == 1) ? r1 : r2) + (size_t)n * CC * NSS;
    __half* dst = g_x16 + ((size_t)lvl * NTOT + n) * NSS * CC;
    for (int i = tid; i < 128 * 36; i += 256) {
        int ci = i / 36, s = i % 36;
        t_s[ci * 37 + s] = src[i];
    }
    __syncthreads();
    for (int i = tid; i < 128 * 36; i += 256) {
        int s = i >> 7, ci = i & 127;
        dst[i] = __float2half_rn(t_s[ci * 37 + s]);
    }
}

// ---------------- merged prep: weight fragments + fc_w -----------------------
__device__ __forceinline__ void prep_w_elem(const float* __restrict__ w,
                                            __half* __restrict__ dst,
                                            int idx, int CIN, int COUT,
                                            int lvl, int wstride, int total) {
    const int MT = COUT / 16;
    int hh = idx & 7, lane = (idx >> 3) & 31;
    int t3 = idx >> 8;
    int mt = t3 % MT, g = (t3 / MT) % 9, cb = t3 / (MT * 9);
    int j = hh >> 1, inner = hh & 1;
    int r  = (lane >> 2) + 8 * (j & 1);
    int kk = 2 * (lane & 3) + inner + 8 * (j >> 1);
    int m  = mt * 16 + r;
    int ci = cb * 16 + kk;
    dst[(size_t)lvl * total + idx] =
        __float2half_rn(w[(size_t)lvl * wstride + (size_t)m * (CIN * 9) + ci * 9 + g]);
}

#define TL (8*9*4*32*8)      // 73728 per level
#define TC (12*9*8*32*8)     // 221184

__global__ void prep_all(const float* __restrict__ conv_w,
                         const float* __restrict__ cat_w,
                         const float* __restrict__ fc_w) {
    int idx = blockIdx.x * 256 + threadIdx.x;
    if (idx < 3 * TL) {
        prep_w_elem(conv_w, g_wfL, idx % TL, 128, 64, idx / TL, 64 * 128 * 9, TL);
    } else if (idx < 3 * TL + TC) {
        prep_w_elem(cat_w, g_wfC, idx - 3 * TL, 192, 128, 0, 0, TC);
    } else if (idx < 3 * TL + TC + FCH * KFC) {
        int i = idx - 3 * TL - TC;
        int f = i / KFC, kp = i % KFC;
        int s = kp >> 7, c = kp & 127;
        g_fcw16[i] = __float2half_rn(fc_w[(size_t)f * KFC + c * NSS + s]);
    }
}

// ---------------- conv9 + folded BN + ReLU via fp16 mma.sync -----------------
template<int CIN, int COUT, int NSAMP, int CSTRIDE, int THREADS>
__global__ __launch_bounds__(THREADS, 512 / THREADS)
void conv_mma(const __half* __restrict__ xg, const __half* __restrict__ wfrag_,
              const float* __restrict__ bng, const float* __restrict__ bnb,
              const float* __restrict__ bnm, const float* __restrict__ bnv,
              __half* __restrict__ out) {
    constexpr int NCH  = CIN / 16;
    constexpr int MT   = COUT / 16;
    constexpr int NWM  = (THREADS / 32) / NSAMP;
    constexpr int SSTR = 44 * 24;
    constexpr int CHF  = 9 * MT * 32;

    __shared__ __align__(16) __half x_s[2][NSAMP * SSTR];

    const int tid  = threadIdx.x;
    const int wid  = tid >> 5, lane = tid & 31;
    const int lvl  = blockIdx.y;
    const __half* x = xg + (size_t)lvl * NTOT * NSS * CIN;
    const uint4* wf4 = (const uint4*)(wfrag_ + (size_t)lvl * NCH * CHF * 8);
    const int c0   = lvl * COUT;
    bng += lvl * COUT; bnb += lvl * COUT; bnm += lvl * COUT; bnv += lvl * COUT;

    const int samp = wid / NWM;
    const int mt0  = (wid % NWM) * 4;
    const int n0   = blockIdx.x * NSAMP;
    const int sampbase = samp * SSTR;

    const uint32_t xs0 = smem_u32(&x_s[0][0]), xs1 = smem_u32(&x_s[1][0]);

    for (int i = tid; i < 2 * NSAMP * SSTR; i += THREADS) ((__half*)x_s)[i] = __half(0.f);
    __syncthreads();

    int col[5];
#pragma unroll
    for (int nt = 0; nt < 5; nt++) {
        int cb = nt * 8 + (lane >> 2);
        col[nt] = cb < 36 ? cb : 35;
    }

    float acc[4][5][4];
#pragma unroll
    for (int mt = 0; mt < 4; mt++)
#pragma unroll
        for (int nt = 0; nt < 5; nt++)
#pragma unroll
            for (int j = 0; j < 4; j++) acc[mt][nt][j] = 0.f;

    auto stage = [&](int cb, int buf) {
        const uint32_t base = buf ? xs1 : xs0;
        for (int i = tid; i < NSAMP * 72; i += THREADS) {
            int hh = i & 1, s = (i >> 1) % 36, sp = i / 72;
            cp16(base + (uint32_t)(sp * SSTR + (s + 4) * 24 + hh * 8) * 2,
                 x + ((size_t)(n0 + sp) * 36 + s) * CIN + cb * 16 + hh * 8);
        }
        asm volatile("cp.async.commit_group;");
    };

    stage(0, 0);

    for (int cb = 0; cb < NCH; cb++) {
        if (cb + 1 < NCH) {
            stage(cb + 1, (cb + 1) & 1);
            asm volatile("cp.async.wait_group 1;");
        } else {
            asm volatile("cp.async.wait_group 0;");
        }
        __syncthreads();

        const __half* xs = x_s[cb & 1] + sampbase;
        const uint4* wfc = wf4 + (size_t)cb * CHF;
#pragma unroll
        for (int g = 0; g < 9; g++) {
            uint4 af[4];
#pragma unroll
            for (int mt = 0; mt < 4; mt++)
                af[mt] = __ldg(&wfc[(g * MT + mt0 + mt) * 32 + lane]);
#pragma unroll
            for (int nt = 0; nt < 5; nt++) {
                int off = (col[nt] + g) * 24 + 2 * (lane & 3);
                uint32_t b0 = *(const uint32_t*)&xs[off];
                uint32_t b1 = *(const uint32_t*)&xs[off + 8];
#pragma unroll
                for (int mt = 0; mt < 4; mt++)
                    mma_f16(acc[mt][nt], af[mt], b0, b1);
            }
        }
        __syncthreads();
    }

    const int nidx = n0 + samp;
#pragma unroll
    for (int mt = 0; mt < 4; mt++) {
        int cobase = (mt0 + mt) * 16 + (lane >> 2);
#pragma unroll
        for (int h = 0; h < 2; h++) {
            int co = cobase + 8 * h;
            float sc = bng[co] * rsqrtf(bnv[co] + EPS);
            float bi = bnb[co] - bnm[co] * sc;
#pragma unroll
            for (int nt = 0; nt < 5; nt++) {
                int s0 = nt * 8 + 2 * (lane & 3);
                if (s0 < 36) {
                    out[((size_t)nidx * 36 + s0) * CSTRIDE + c0 + co] =
                        relu_h(fmaf(acc[mt][nt][2 * h], sc, bi));
                    out[((size_t)nidx * 36 + s0 + 1) * CSTRIDE + c0 + co] =
                        relu_h(fmaf(acc[mt][nt][2 * h + 1], sc, bi));
                }
            }
        }
    }
}

// ---------------- FC via fp16 mma.sync, fused LayerNorm + ReLU ---------------
__global__ __launch_bounds__(128, 1)
void fc_ln_relu(const float* __restrict__ fc_b, const float* __restrict__ ln_g,
                const float* __restrict__ ln_b) {
    __shared__ __align__(16) __half A_s[2][32][40];
    __shared__ __align__(16) __half B_s[2][128][40];

    const int tid = threadIdx.x, lane = tid & 31, wid = tid >> 5;
    const int mw = wid & 1, kw = wid >> 1;
    const int n0 = blockIdx.x * 32;
    const int r0 = mw * 16 + (lane >> 2);
    const int q2 = 2 * (lane & 3);

    float acc[16][4];
#pragma unroll
    for (int nt = 0; nt < 16; nt++)
#pragma unroll
        for (int j = 0; j < 4; j++) acc[nt][j] = 0.f;

    for (int ch = 0; ch < 72; ch++) {
        const int k0 = ch * 64;
        __syncthreads();
#pragma unroll
        for (int it = 0; it < 2; it++) {
            int i = tid + it * 128;
            int q = i & 3, r = (i >> 2) & 31, s = i >> 7;
            *(uint4*)&A_s[s][r][q * 8] =
                *(const uint4*)(g_cat2 + (size_t)(n0 + r) * KFC + k0 + s * 32 + q * 8);
        }
#pragma unroll
        for (int it = 0; it < 8; it++) {
            int i = tid + it * 128;
            int q = i & 3, f = (i >> 2) & 127, s = i >> 9;
            *(uint4*)&B_s[s][f][q * 8] =
                *(const uint4*)(g_fcw16 + (size_t)f * KFC + k0 + s * 32 + q * 8);
        }
        __syncthreads();

#pragma unroll
        for (int g = 0; g < 2; g++) {
            int kk = g * 16 + q2;
            uint4 a;
            a.x = *(const uint32_t*)&A_s[kw][r0][kk];
            a.y = *(const uint32_t*)&A_s[kw][r0 + 8][kk];
            a.z = *(const uint32_t*)&A_s[kw][r0][kk + 8];
            a.w = *(const uint32_t*)&A_s[kw][r0 + 8][kk + 8];
#pragma unroll
            for (int nt = 0; nt < 16; nt++) {
                int f = nt * 8 + (lane >> 2);
                uint32_t b0 = *(const uint32_t*)&B_s[kw][f][kk];
                uint32_t b1 = *(const uint32_t*)&B_s[kw][f][kk + 8];
                mma_f16(acc[nt], a, b0, b1);
            }
        }
    }

    __syncthreads();
    float* red = (float*)&B_s[0][0][0];
    if (kw == 1) {
#pragma unroll
        for (int nt = 0; nt < 16; nt++)
#pragma unroll
            for (int j = 0; j < 4; j++) {
                int r = mw * 16 + (lane >> 2) + 8 * (j >> 1);
                int c = nt * 8 + 2 * (lane & 3) + (j & 1);
                red[r * 130 + c] = acc[nt][j];
            }
    }
    __syncthreads();
    if (kw == 0) {
#pragma unroll
        for (int nt = 0; nt < 16; nt++) {
            int cb = nt * 8 + 2 * (lane & 3);
            int rA = mw * 16 + (lane >> 2), rB = rA + 8;
            acc[nt][0] += red[rA * 130 + cb]     + fc_b[cb];
            acc[nt][1] += red[rA * 130 + cb + 1] + fc_b[cb + 1];
            acc[nt][2] += red[rB * 130 + cb]     + fc_b[cb];
            acc[nt][3] += red[rB * 130 + cb + 1] + fc_b[cb + 1];
        }
        float s0 = 0.f, s1 = 0.f;
#pragma unroll
        for (int nt = 0; nt < 16; nt++) {
            s0 += acc[nt][0] + acc[nt][1];
            s1 += acc[nt][2] + acc[nt][3];
        }
        s0 += __shfl_xor_sync(~0u, s0, 1); s0 += __shfl_xor_sync(~0u, s0, 2);
        s1 += __shfl_xor_sync(~0u, s1, 1); s1 += __shfl_xor_sync(~0u, s1, 2);
        float m0 = s0 * (1.f / 128.f), m1 = s1 * (1.f / 128.f);
        float q0 = 0.f, q1 = 0.f;
#pragma unroll
        for (int nt = 0; nt < 16; nt++) {
            float d0 = acc[nt][0] - m0, d1 = acc[nt][1] - m0;
            float d2 = acc[nt][2] - m1, d3 = acc[nt][3] - m1;
            q0 += d0 * d0 + d1 * d1;
            q1 += d2 * d2 + d3 * d3;
        }
        q0 += __shfl_xor_sync(~0u, q0, 1); q0 += __shfl_xor_sync(~0u, q0, 2);
        q1 += __shfl_xor_sync(~0u, q1, 1); q1 += __shfl_xor_sync(~0u, q1, 2);
        float rs0 = rsqrtf(q0 * (1.f / 128.f) + EPS);
        float rs1 = rsqrtf(q1 * (1.f / 128.f) + EPS);
        int gr0 = n0 + mw * 16 + (lane >> 2), gr1 = gr0 + 8;
#pragma unroll
        for (int nt = 0; nt < 16; nt++) {
            int c = nt * 8 + 2 * (lane & 3);
            float g0 = ln_g[c], g1 = ln_g[c + 1], bb0 = ln_b[c], bb1 = ln_b[c + 1];
            float v0 = fmaxf((acc[nt][0] - m0) * rs0 * g0 + bb0, 0.f);
            float v1 = fmaxf((acc[nt][1] - m0) * rs0 * g1 + bb1, 0.f);
            float v2 = fmaxf((acc[nt][2] - m1) * rs1 * g0 + bb0, 0.f);
            float v3 = fmaxf((acc[nt][3] - m1) * rs1 * g1 + bb1, 0.f);
            *(float2*)(g_roi + (size_t)gr0 * 128 + c) = make_float2(v0, v1);
            *(float2*)(g_roi + (size_t)gr1 * 128 + c) = make_float2(v2, v3);
        }
    }
}

// ---------------- k/v at the 250 sample points (fp16 outputs) -----------------
__global__ __launch_bounds__(256)
void kv_kernel(const float* __restrict__ fmap, const float* __restrict__ key_w,
               const float* __restrict__ key_g, const float* __restrict__ key_beta,
               const float* __restrict__ key_m, const float* __restrict__ key_v,
               const float* __restrict__ val_w, const float* __restrict__ val_b) {
    __shared__ float fc_s[25 * 129];
    const int b = blockIdx.x, r = blockIdx.y;
    const int tid = threadIdx.x;
    for (int i = tid; i < 25 * 128; i += 256) {
        int c = i / 25, pos = i % 25;
        fc_s[pos * 129 + c] = fmap[((b * 128 + c) * 40 + 4 * r) * 100 + 4 * pos];
    }
    __syncthreads();
    for (int i = tid; i < 25 * 128; i += 256) {
        int o = i % 128, pos = i / 128;
        const float* kw = key_w + o * 128;
        const float* vw = val_w + o * 128;
        float ka = 0.f, va = 0.f;
#pragma unroll 4
        for (int c = 0; c < 128; c++) {
            float xv = fc_s[pos * 129 + c];
            ka = fmaf(kw[c], xv, ka);
            va = fmaf(vw[c], xv, va);
        }
        float sc = key_g[o] * rsqrtf(key_v[o] + EPS);
        float kb = key_beta[o] - key_m[o] * sc;
        float kk = fmaf(ka, sc, kb);
        int l = r * 25 + pos;
        g_k16[((size_t)b * LPAD + l) * CC + o] = relu_h(kk);
        g_v16[((size_t)b * CC + o) * LPAD + l] = __float2half_rn(va + val_b[o]);
    }
}

// ---------------- attention via fp16 mma: CTA = (b, 32 priors) ----------------
// 4 warps: wm = row half (16 priors), wn = col half. Softmax in fragments,
// unnormalized exp -> fp16 P smem; PV mma; normalize+gate in epilogue.
__global__ __launch_bounds__(128)
void attn_mma(const float* __restrict__ q_w, const float* __restrict__ q_b,
              const float* __restrict__ gate_w, const float* __restrict__ gate_b,
              float* __restrict__ out) {
    __shared__ __align__(16) __half q_s[32 * 136];
    __shared__ __align__(16) __half ph_s[32 * 264];
    __shared__ float mx_s[2][32];
    __shared__ float sm_s[2][32];

    const int b = blockIdx.x, p0g = blockIdx.y * 32;
    const int tid = threadIdx.x, lane = tid & 31, wid = tid >> 5;
    const int wm = wid & 1, wn = wid >> 1;
    const int row = wm * 16 + (lane >> 2);

    // stage q = relu(roi*qw+qb) as fp16
    for (int i = tid; i < 32 * 128; i += 128) {
        int p = i >> 7, f = i & 127;
        float qq = fmaf(g_roi[((size_t)b * NP + p0g + p) * 128 + f],
                        q_w[p0g + p], q_b[p0g + p]);
        q_s[p * 136 + f] = relu_h(qq);
    }
    __syncthreads();

    // ---- QK^T: logits fragments (16 n8-tiles per warp over l) ----
    float acc[16][4];
#pragma unroll
    for (int nt = 0; nt < 16; nt++)
#pragma unroll
        for (int j = 0; j < 4; j++) acc[nt][j] = 0.f;

    const __half* kg = g_k16 + (size_t)b * LPAD * CC;
#pragma unroll
    for (int k8 = 0; k8 < 8; k8++) {
        int k0 = k8 * 16;
        uint4 a;
        a.x = *(const uint32_t*)&q_s[row * 136 + k0 + 2 * (lane & 3)];
        a.y = *(const uint32_t*)&q_s[(row + 8) * 136 + k0 + 2 * (lane & 3)];
        a.z = *(const uint32_t*)&q_s[row * 136 + k0 + 8 + 2 * (lane & 3)];
        a.w = *(const uint32_t*)&q_s[(row + 8) * 136 + k0 + 8 + 2 * (lane & 3)];
#pragma unroll
        for (int nt = 0; nt < 16; nt++) {
            int l = wn * 128 + nt * 8 + (lane >> 2);
            const __half* kr = kg + (size_t)l * CC + k0 + 2 * (lane & 3);
            uint32_t b0 = *(const uint32_t*)kr;
            uint32_t b1 = *(const uint32_t*)(kr + 8);
            mma_f16(acc[nt], a, b0, b1);
        }
    }

    // scale + row max (lane rows: row, row+8)
    const float scale = 0.08838834764831845f;
    float m0 = -1e30f, m1 = -1e30f;
#pragma unroll
    for (int nt = 0; nt < 16; nt++) {
#pragma unroll
        for (int j = 0; j < 4; j++) acc[nt][j] *= scale;
        m0 = fmaxf(m0, fmaxf(acc[nt][0], acc[nt][1]));
        m1 = fmaxf(m1, fmaxf(acc[nt][2], acc[nt][3]));
    }
    m0 = fmaxf(m0, __shfl_xor_sync(~0u, m0, 1)); m0 = fmaxf(m0, __shfl_xor_sync(~0u, m0, 2));
    m1 = fmaxf(m1, __shfl_xor_sync(~0u, m1, 1)); m1 = fmaxf(m1, __shfl_xor_sync(~0u, m1, 2));
    if ((lane & 3) == 0) {
        mx_s[wn][row] = m0;
        mx_s[wn][row + 8] = m1;
    }
    __syncthreads();
    float M0 = fmaxf(mx_s[0][row], mx_s[1][row]);
    float M1 = fmaxf(mx_s[0][row + 8], mx_s[1][row + 8]);

    // exp (unnormalized, masked at l>=250) -> fp16 smem; accumulate row sums
    float s0 = 0.f, s1 = 0.f;
#pragma unroll
    for (int nt = 0; nt < 16; nt++) {
        int lb = wn * 128 + nt * 8 + 2 * (lane & 3);
        float e0 = (lb     < LL) ? __expf(acc[nt][0] - M0) : 0.f;
        float e1 = (lb + 1 < LL) ? __expf(acc[nt][1] - M0) : 0.f;
        float e2 = (lb     < LL) ? __expf(acc[nt][2] - M1) : 0.f;
        float e3 = (lb + 1 < LL) ? __expf(acc[nt][3] - M1) : 0.f;
        s0 += e0 + e1; s1 += e2 + e3;
        __half2 h01 = __floats2half2_rn(e0, e1);
        __half2 h23 = __floats2half2_rn(e2, e3);
        *(__half2*)&ph_s[row * 264 + lb]       = h01;
        *(__half2*)&ph_s[(row + 8) * 264 + lb] = h23;
    }
    s0 += __shfl_xor_sync(~0u, s0, 1); s0 += __shfl_xor_sync(~0u, s0, 2);
    s1 += __shfl_xor_sync(~0u, s1, 1); s1 += __shfl_xor_sync(~0u, s1, 2);
    if ((lane & 3) == 0) {
        sm_s[wn][row] = s0;
        sm_s[wn][row + 8] = s1;
    }
    __syncthreads();
    float inv0 = 1.f / (sm_s[0][row] + sm_s[1][row]);
    float inv1 = 1.f / (sm_s[0][row + 8] + sm_s[1][row + 8]);

    // ---- P @ V: 8 f-tiles per warp (wn splits f), K = 256 l ----
    float acc2[8][4];
#pragma unroll
    for (int ft = 0; ft < 8; ft++)
#pragma unroll
        for (int j = 0; j < 4; j++) acc2[ft][j] = 0.f;

    const __half* vg = g_v16 + (size_t)b * CC * LPAD;
#pragma unroll
    for (int ks = 0; ks < 16; ks++) {
        int k0 = ks * 16;
        uint4 a;
        a.x = *(const uint32_t*)&ph_s[row * 264 + k0 + 2 * (lane & 3)];
        a.y = *(const uint32_t*)&ph_s[(row + 8) * 264 + k0 + 2 * (lane & 3)];
        a.z = *(const uint32_t*)&ph_s[row * 264 + k0 + 8 + 2 * (lane & 3)];
        a.w = *(const uint32_t*)&ph_s[(row + 8) * 264 + k0 + 8 + 2 * (lane & 3)];
#pragma unroll
        for (int ft = 0; ft < 8; ft++) {
            int f = wn * 64 + ft * 8 + (lane >> 2);
            const __half* vr = vg + (size_t)f * LPAD + k0 + 2 * (lane & 3);
            uint32_t b0 = *(const uint32_t*)vr;
            uint32_t b1 = *(const uint32_t*)(vr + 8);
            mma_f16(acc2[ft], a, b0, b1);
        }
    }

    // epilogue: normalize, gate, add roi
    int gp0 = p0g + row, gp1 = gp0 + 8;
    float gw0 = gate_w[gp0], gb0 = gate_b[gp0];
    float gw1 = gate_w[gp1], gb1 = gate_b[gp1];
#pragma unroll
    for (int ft = 0; ft < 8; ft++) {
        int fb = wn * 64 + ft * 8 + 2 * (lane & 3);
        size_t o0 = ((size_t)b * NP + gp0) * 128 + fb;
        size_t o1 = ((size_t)b * NP + gp1) * 128 + fb;
        float c00 = g_roi[o0]     + fmaf(acc2[ft][0] * inv0, gw0, gb0);
        float c01 = g_roi[o0 + 1] + fmaf(acc2[ft][1] * inv0, gw0, gb0);
        float c10 = g_roi[o1]     + fmaf(acc2[ft][2] * inv1, gw1, gb1);
        float c11 = g_roi[o1 + 1] + fmaf(acc2[ft][3] * inv1, gw1, gb1);
        *(float2*)(out + o0) = make_float2(c00, c01);
        *(float2*)(out + o1) = make_float2(c10, c11);
    }
}

// ---------------- host launcher ----------------------------------------------
extern "C" void kernel_launch(void* const* d_in, const int* in_sizes, int n_in,
                              void* d_out, int out_size) {
    (void)in_sizes; (void)n_in; (void)out_size;
    const float* roi0   = (const float*)d_in[0];
    const float* roi1   = (const float*)d_in[1];
    const float* roi2   = (const float*)d_in[2];
    const float* fmap   = (const float*)d_in[3];
    const float* conv_w = (const float*)d_in[4];
    const float* conv_g = (const float*)d_in[5];
    const float* conv_b = (const float*)d_in[6];
    const float* conv_m = (const float*)d_in[7];
    const float* conv_v = (const float*)d_in[8];
    const float* cat_w  = (const float*)d_in[9];
    const float* cat_g  = (const float*)d_in[10];
    const float* cat_b  = (const float*)d_in[11];
    const float* cat_m  = (const float*)d_in[12];
    const float* cat_v  = (const float*)d_in[13];
    const float* fc_w   = (const float*)d_in[14];
    const float* fc_b   = (const float*)d_in[15];
    const float* ln_g   = (const float*)d_in[16];
    const float* ln_b   = (const float*)d_in[17];
    const float* key_w  = (const float*)d_in[18];
    const float* key_g  = (const float*)d_in[19];
    const float* key_bt = (const float*)d_in[20];
    const float* key_m  = (const float*)d_in[21];
    const float* key_v  = (const float*)d_in[22];
    const float* q_w    = (const float*)d_in[23];
    const float* q_b    = (const float*)d_in[24];
    const float* val_w  = (const float*)d_in[25];
    const float* val_b  = (const float*)d_in[26];
    const float* gate_w = (const float*)d_in[27];
    const float* gate_b = (const float*)d_in[28];
    float* out = (float*)d_out;

    __half *x16, *cat1, *cat2, *wfL, *wfC;
    cudaGetSymbolAddress((void**)&x16,  g_x16);
    cudaGetSymbolAddress((void**)&cat1, g_cat1);
    cudaGetSymbolAddress((void**)&cat2, g_cat2);
    cudaGetSymbolAddress((void**)&wfL,  g_wfL);
    cudaGetSymbolAddress((void**)&wfC,  g_wfC);

    // (1) input transpose+fp16, (2) merged weight prep
    cvt_roi<<<dim3(NTOT, 3), 256>>>(roi0, roi1, roi2);
    const int PREP_TOTAL = 3 * TL + TC + FCH * KFC;
    prep_all<<<(PREP_TOTAL + 255) / 256, 256>>>(conv_w, cat_w, fc_w);

    // (3) level convs, (4) cat conv  <- profiled slot
    conv_mma<128, 64, 8, 192, 256><<<dim3(NTOT / 8, 3), 256>>>(
        x16, wfL, conv_g, conv_b, conv_m, conv_v, cat1);
    conv_mma<192, 128, 4, 128, 256><<<dim3(NTOT / 4, 1), 256>>>(
        cat1, wfC, cat_g, cat_b, cat_m, cat_v, cat2);

    // (5) FC+LN, (6) kv, (7) attention
    fc_ln_relu<<<192, 128>>>(fc_b, ln_g, ln_b);
    kv_kernel<<<dim3(BB, 10), 256>>>(fmap, key_w, key_g, key_bt, key_m, key_v,
                                     val_w, val_b);
    attn_mma<<<dim3(BB, NP / 32), 128>>>(q_w, q_b, gate_w, gate_b, out);
}

// round 12
// speedup vs baseline: 6.7431x; 2.0228x over previous
#include <cuda_runtime.h>
#include <cuda_fp16.h>
#include <cstdint>

#define BB    32
#define NP    192
#define CC    128
#define NSS   36
#define FCH   128
#define EPS   1e-5f
#define NTOT  (BB*NP)      // 6144
#define LL    250
#define LPAD  256
#define KFC   (CC*NSS)     // 4608

// ---------------- scratch (device globals; no runtime allocation) -------------
__device__ __align__(16) __half g_x16 [3 * NTOT * CC * NSS];  // fp16 roi, [n][s][ci]
__device__ __align__(16) __half g_cat1[NTOT * NSS * 192];     // level out, [n][s][c]
__device__ __align__(16) __half g_cat2[NTOT * NSS * CC];      // cat out,  [n][s][c]
__device__ float  g_roi [BB * NP * FCH];                      // fc+LN+ReLU (fp32)
__device__ __align__(16) __half g_k16[BB * LPAD * CC];        // keys  [b][l][f], l>=250 zero
__device__ __align__(16) __half g_v16[BB * CC * LPAD];        // vals  [b][f][l], l>=250 zero
__device__ __align__(16) __half g_fcw16[FCH * KFC];           // fc_w fp16 [f][k'], k'=s*128+c
__device__ __align__(16) __half g_wfL [3 * 8 * 9 * 4 * 32 * 8];   // level weight frags
__device__ __align__(16) __half g_wfC [12 * 9 * 8 * 32 * 8];      // cat weight frags
__device__ float g_kwT[CC * CC];                              // key_w transposed [c][o]
__device__ float g_vwT[CC * CC];                              // val_w transposed [c][o]

// ---------------- helpers ----------------------------------------------------
__device__ __forceinline__ uint32_t smem_u32(const void* p) {
    uint32_t a;
    asm("{ .reg .u64 t; cvta.to.shared.u64 t, %1; cvt.u32.u64 %0, t; }"
        : "=r"(a) : "l"(p));
    return a;
}
__device__ __forceinline__ void cp16(uint32_t s, const void* g) {
    asm volatile("cp.async.cg.shared.global [%0], [%1], 16;" :: "r"(s), "l"(g));
}
__device__ __forceinline__ void mma_f16(float* c, const uint4& a,
                                        uint32_t b0, uint32_t b1) {
    asm volatile("mma.sync.aligned.m16n8k16.row.col.f32.f16.f16.f32 "
                 "{%0,%1,%2,%3}, {%4,%5,%6,%7}, {%8,%9}, {%0,%1,%2,%3};"
                 : "+f"(c[0]), "+f"(c[1]), "+f"(c[2]), "+f"(c[3])
                 : "r"(a.x), "r"(a.y), "r"(a.z), "r"(a.w), "r"(b0), "r"(b1));
}
__device__ __forceinline__ void ldsm_x2(uint32_t& b0, uint32_t& b1, uint32_t addr) {
    asm volatile("ldmatrix.sync.aligned.m8n8.x2.shared.b16 {%0,%1}, [%2];"
                 : "=r"(b0), "=r"(b1) : "r"(addr));
}
__device__ __forceinline__ __half relu_h(float v) {
    return __float2half_rn(v > 0.f ? v : 0.f);
}

// ---------------- input transpose + fp16: x[n][ci][s] -> g_x16[n][s][ci] ------
__global__ __launch_bounds__(256)
void cvt_roi(const float* __restrict__ r0, const float* __restrict__ r1,
             const float* __restrict__ r2) {
    __shared__ float t_s[128 * 37];
    const int n = blockIdx.x, lvl = blockIdx.y, tid = threadIdx.x;
    const float* src = ((lvl == 0) ? r0 : (lvl == 1) ? r1 : r2) + (size_t)n * CC * NSS;
    __half* dst = g_x16 + ((size_t)lvl * NTOT + n) * NSS * CC;
    for (int i = tid; i < 128 * 36; i += 256) {
        int ci = i / 36, s = i % 36;
        t_s[ci * 37 + s] = src[i];
    }
    __syncthreads();
    for (int i = tid; i < 128 * 36; i += 256) {
        int s = i >> 7, ci = i & 127;
        dst[i] = __float2half_rn(t_s[ci * 37 + s]);
    }
}

// ---------------- merged prep: weight frags + fc_w + kv weight transpose -----
__device__ __forceinline__ void prep_w_elem(const float* __restrict__ w,
                                            __half* __restrict__ dst,
                                            int idx, int CIN, int COUT,
                                            int lvl, int wstride, int total) {
    const int MT = COUT / 16;
    int hh = idx & 7, lane = (idx >> 3) & 31;
    int t3 = idx >> 8;
    int mt = t3 % MT, g = (t3 / MT) % 9, cb = t3 / (MT * 9);
    int j = hh >> 1, inner = hh & 1;
    int r  = (lane >> 2) + 8 * (j & 1);
    int kk = 2 * (lane & 3) + inner + 8 * (j >> 1);
    int m  = mt * 16 + r;
    int ci = cb * 16 + kk;
    dst[(size_t)lvl * total + idx] =
        __float2half_rn(w[(size_t)lvl * wstride + (size_t)m * (CIN * 9) + ci * 9 + g]);
}

#define TL (8*9*4*32*8)      // 73728 per level
#define TC (12*9*8*32*8)     // 221184
#define TFC (FCH*KFC)
#define TKV (CC*CC)

__global__ void prep_all(const float* __restrict__ conv_w,
                         const float* __restrict__ cat_w,
                         const float* __restrict__ fc_w,
                         const float* __restrict__ key_w,
                         const float* __restrict__ val_w) {
    int idx = blockIdx.x * 256 + threadIdx.x;
    if (idx < 3 * TL) {
        prep_w_elem(conv_w, g_wfL, idx % TL, 128, 64, idx / TL, 64 * 128 * 9, TL);
    } else if (idx < 3 * TL + TC) {
        prep_w_elem(cat_w, g_wfC, idx - 3 * TL, 192, 128, 0, 0, TC);
    } else if (idx < 3 * TL + TC + TFC) {
        int i = idx - 3 * TL - TC;
        int f = i / KFC, kp = i % KFC;
        int s = kp >> 7, c = kp & 127;
        g_fcw16[i] = __float2half_rn(fc_w[(size_t)f * KFC + c * NSS + s]);
    } else if (idx < 3 * TL + TC + TFC + 2 * TKV) {
        int i = idx - 3 * TL - TC - TFC;
        int which = i / TKV; i %= TKV;
        int c = i >> 7, o = i & 127;
        if (which == 0) g_kwT[i] = key_w[o * 128 + c];
        else            g_vwT[i] = val_w[o * 128 + c];
    }
}

// ---------------- conv9 + folded BN + ReLU via fp16 mma.sync -----------------
// 3-stage cp.async pipeline, single barrier per chunk; B frags via ldmatrix.x2.
template<int CIN, int COUT, int NSAMP, int CSTRIDE, int THREADS>
__global__ __launch_bounds__(THREADS, 512 / THREADS)
void conv_mma(const __half* __restrict__ xg, const __half* __restrict__ wfrag_,
              const float* __restrict__ bng, const float* __restrict__ bnb,
              const float* __restrict__ bnm, const float* __restrict__ bnv,
              __half* __restrict__ out) {
    constexpr int NCH  = CIN / 16;
    constexpr int MT   = COUT / 16;
    constexpr int NWM  = (THREADS / 32) / NSAMP;
    constexpr int SSTR = 44 * 24;                    // halves per sample
    constexpr int CHF  = 9 * MT * 32;

    __shared__ __align__(16) __half x_s[3][NSAMP * SSTR];

    const int tid  = threadIdx.x;
    const int wid  = tid >> 5, lane = tid & 31;
    const int lvl  = blockIdx.y;
    const __half* x = xg + (size_t)lvl * NTOT * NSS * CIN;
    const uint4* wf4 = (const uint4*)(wfrag_ + (size_t)lvl * NCH * CHF * 8);
    const int c0   = lvl * COUT;
    bng += lvl * COUT; bnb += lvl * COUT; bnm += lvl * COUT; bnv += lvl * COUT;

    const int samp = wid / NWM;
    const int mt0  = (wid % NWM) * 4;
    const int n0   = blockIdx.x * NSAMP;

    uint32_t xsu[3];
#pragma unroll
    for (int s = 0; s < 3; s++) xsu[s] = smem_u32(&x_s[s][0]) + samp * SSTR * 2;

    for (int i = tid; i < 3 * NSAMP * SSTR; i += THREADS) ((__half*)x_s)[i] = __half(0.f);

    // ldmatrix per-lane row address offsets (bytes): row n = nt*8 + (lane&7)
    uint32_t aoff[5];
#pragma unroll
    for (int nt = 0; nt < 5; nt++) {
        int n = nt * 8 + (lane & 7);
        if (n > 35) n = 35;
        aoff[nt] = (uint32_t)n * 48 + (((lane >> 3) & 1) ? 16u : 0u);
    }

    float acc[4][5][4];
#pragma unroll
    for (int mt = 0; mt < 4; mt++)
#pragma unroll
        for (int nt = 0; nt < 5; nt++)
#pragma unroll
            for (int j = 0; j < 4; j++) acc[mt][nt][j] = 0.f;

    auto stage = [&](int cb) {
        const uint32_t base = smem_u32(&x_s[cb % 3][0]);
        for (int i = tid; i < NSAMP * 72; i += THREADS) {
            int hh = i & 1, s = (i >> 1) % 36, sp = i / 72;
            cp16(base + (uint32_t)(sp * SSTR + (s + 4) * 24 + hh * 8) * 2,
                 x + ((size_t)(n0 + sp) * 36 + s) * CIN + cb * 16 + hh * 8);
        }
        asm volatile("cp.async.commit_group;");
    };

    __syncthreads();                 // zero-fill visible before cp.async writes
    stage(0);
    stage(1);
    asm volatile("cp.async.wait_group 1;");
    __syncthreads();                 // buf 0 ready for all threads

    for (int cb = 0; cb < NCH; cb++) {
        if (cb + 2 < NCH) stage(cb + 2);

        const uint32_t xb = xsu[cb % 3];
        const uint4* wfc = wf4 + (size_t)cb * CHF;
#pragma unroll
        for (int g = 0; g < 9; g++) {
            uint4 af[4];
#pragma unroll
            for (int mt = 0; mt < 4; mt++)
                af[mt] = __ldg(&wfc[(g * MT + mt0 + mt) * 32 + lane]);
#pragma unroll
            for (int nt = 0; nt < 5; nt++) {
                uint32_t b0, b1;
                ldsm_x2(b0, b1, xb + aoff[nt] + g * 48);
#pragma unroll
                for (int mt = 0; mt < 4; mt++)
                    mma_f16(acc[mt][nt], af[mt], b0, b1);
            }
        }

        asm volatile("cp.async.wait_group 1;");   // next buffer complete
        __syncthreads();                          // visibility + reuse safety
    }

    // epilogue: folded BN + ReLU -> fp16 [n][s][c]
    const int nidx = n0 + samp;
#pragma unroll
    for (int mt = 0; mt < 4; mt++) {
        int cobase = (mt0 + mt) * 16 + (lane >> 2);
#pragma unroll
        for (int h = 0; h < 2; h++) {
            int co = cobase + 8 * h;
            float sc = bng[co] * rsqrtf(bnv[co] + EPS);
            float bi = bnb[co] - bnm[co] * sc;
#pragma unroll
            for (int nt = 0; nt < 5; nt++) {
                int s0 = nt * 8 + 2 * (lane & 3);
                if (s0 < 36) {
                    out[((size_t)nidx * 36 + s0) * CSTRIDE + c0 + co] =
                        relu_h(fmaf(acc[mt][nt][2 * h], sc, bi));
                    out[((size_t)nidx * 36 + s0 + 1) * CSTRIDE + c0 + co] =
                        relu_h(fmaf(acc[mt][nt][2 * h + 1], sc, bi));
                }
            }
        }
    }
}

// ---------------- FC via fp16 mma.sync, fused LayerNorm + ReLU ---------------
__global__ __launch_bounds__(128, 1)
void fc_ln_relu(const float* __restrict__ fc_b, const float* __restrict__ ln_g,
                const float* __restrict__ ln_b) {
    __shared__ __align__(16) __half A_s[2][32][40];
    __shared__ __align__(16) __half B_s[2][128][40];

    const int tid = threadIdx.x, lane = tid & 31, wid = tid >> 5;
    const int mw = wid & 1, kw = wid >> 1;
    const int n0 = blockIdx.x * 32;
    const int r0 = mw * 16 + (lane >> 2);
    const int q2 = 2 * (lane & 3);

    float acc[16][4];
#pragma unroll
    for (int nt = 0; nt < 16; nt++)
#pragma unroll
        for (int j = 0; j < 4; j++) acc[nt][j] = 0.f;

    for (int ch = 0; ch < 72; ch++) {
        const int k0 = ch * 64;
        __syncthreads();
#pragma unroll
        for (int it = 0; it < 2; it++) {
            int i = tid + it * 128;
            int q = i & 3, r = (i >> 2) & 31, s = i >> 7;
            *(uint4*)&A_s[s][r][q * 8] =
                *(const uint4*)(g_cat2 + (size_t)(n0 + r) * KFC + k0 + s * 32 + q * 8);
        }
#pragma unroll
        for (int it = 0; it < 8; it++) {
            int i = tid + it * 128;
            int q = i & 3, f = (i >> 2) & 127, s = i >> 9;
            *(uint4*)&B_s[s][f][q * 8] =
                *(const uint4*)(g_fcw16 + (size_t)f * KFC + k0 + s * 32 + q * 8);
        }
        __syncthreads();

#pragma unroll
        for (int g = 0; g < 2; g++) {
            int kk = g * 16 + q2;
            uint4 a;
            a.x = *(const uint32_t*)&A_s[kw][r0][kk];
            a.y = *(const uint32_t*)&A_s[kw][r0 + 8][kk];
            a.z = *(const uint32_t*)&A_s[kw][r0][kk + 8];
            a.w = *(const uint32_t*)&A_s[kw][r0 + 8][kk + 8];
#pragma unroll
            for (int nt = 0; nt < 16; nt++) {
                int f = nt * 8 + (lane >> 2);
                uint32_t b0 = *(const uint32_t*)&B_s[kw][f][kk];
                uint32_t b1 = *(const uint32_t*)&B_s[kw][f][kk + 8];
                mma_f16(acc[nt], a, b0, b1);
            }
        }
    }

    __syncthreads();
    float* red = (float*)&B_s[0][0][0];
    if (kw == 1) {
#pragma unroll
        for (int nt = 0; nt < 16; nt++)
#pragma unroll
            for (int j = 0; j < 4; j++) {
                int r = mw * 16 + (lane >> 2) + 8 * (j >> 1);
                int c = nt * 8 + 2 * (lane & 3) + (j & 1);
                red[r * 130 + c] = acc[nt][j];
            }
    }
    __syncthreads();
    if (kw == 0) {
#pragma unroll
        for (int nt = 0; nt < 16; nt++) {
            int cb = nt * 8 + 2 * (lane & 3);
            int rA = mw * 16 + (lane >> 2), rB = rA + 8;
            acc[nt][0] += red[rA * 130 + cb]     + fc_b[cb];
            acc[nt][1] += red[rA * 130 + cb + 1] + fc_b[cb + 1];
            acc[nt][2] += red[rB * 130 + cb]     + fc_b[cb];
            acc[nt][3] += red[rB * 130 + cb + 1] + fc_b[cb + 1];
        }
        float s0 = 0.f, s1 = 0.f;
#pragma unroll
        for (int nt = 0; nt < 16; nt++) {
            s0 += acc[nt][0] + acc[nt][1];
            s1 += acc[nt][2] + acc[nt][3];
        }
        s0 += __shfl_xor_sync(~0u, s0, 1); s0 += __shfl_xor_sync(~0u, s0, 2);
        s1 += __shfl_xor_sync(~0u, s1, 1); s1 += __shfl_xor_sync(~0u, s1, 2);
        float m0 = s0 * (1.f / 128.f), m1 = s1 * (1.f / 128.f);
        float q0 = 0.f, q1 = 0.f;
#pragma unroll
        for (int nt = 0; nt < 16; nt++) {
            float d0 = acc[nt][0] - m0, d1 = acc[nt][1] - m0;
            float d2 = acc[nt][2] - m1, d3 = acc[nt][3] - m1;
            q0 += d0 * d0 + d1 * d1;
            q1 += d2 * d2 + d3 * d3;
        }
        q0 += __shfl_xor_sync(~0u, q0, 1); q0 += __shfl_xor_sync(~0u, q0, 2);
        q1 += __shfl_xor_sync(~0u, q1, 1); q1 += __shfl_xor_sync(~0u, q1, 2);
        float rs0 = rsqrtf(q0 * (1.f / 128.f) + EPS);
        float rs1 = rsqrtf(q1 * (1.f / 128.f) + EPS);
        int gr0 = n0 + mw * 16 + (lane >> 2), gr1 = gr0 + 8;
#pragma unroll
        for (int nt = 0; nt < 16; nt++) {
            int c = nt * 8 + 2 * (lane & 3);
            float g0 = ln_g[c], g1 = ln_g[c + 1], bb0 = ln_b[c], bb1 = ln_b[c + 1];
            float v0 = fmaxf((acc[nt][0] - m0) * rs0 * g0 + bb0, 0.f);
            float v1 = fmaxf((acc[nt][1] - m0) * rs0 * g1 + bb1, 0.f);
            float v2 = fmaxf((acc[nt][2] - m1) * rs1 * g0 + bb0, 0.f);
            float v3 = fmaxf((acc[nt][3] - m1) * rs1 * g1 + bb1, 0.f);
            *(float2*)(g_roi + (size_t)gr0 * 128 + c) = make_float2(v0, v1);
            *(float2*)(g_roi + (size_t)gr1 * 128 + c) = make_float2(v2, v3);
        }
    }
}

// ---------------- k/v at the 250 sample points (coalesced weights) ------------
__global__ __launch_bounds__(256)
void kv_kernel(const float* __restrict__ fmap,
               const float* __restrict__ key_g, const float* __restrict__ key_beta,
               const float* __restrict__ key_m, const float* __restrict__ key_v,
               const float* __restrict__ val_b) {
    __shared__ float fc_s[25 * 129];
    const int b = blockIdx.x, r = blockIdx.y;
    const int tid = threadIdx.x;
    for (int i = tid; i < 25 * 128; i += 256) {
        int c = i / 25, pos = i % 25;
        fc_s[pos * 129 + c] = fmap[((b * 128 + c) * 40 + 4 * r) * 100 + 4 * pos];
    }
    __syncthreads();
    for (int i = tid; i < 25 * 128; i += 256) {
        int o = i & 127, pos = i >> 7;            // lanes -> consecutive o
        float ka = 0.f, va = 0.f;
#pragma unroll 4
        for (int c = 0; c < 128; c++) {
            float xv = fc_s[pos * 129 + c];       // broadcast within warp
            ka = fmaf(g_kwT[c * 128 + o], xv, ka);   // coalesced, L1-resident
            va = fmaf(g_vwT[c * 128 + o], xv, va);
        }
        float sc = key_g[o] * rsqrtf(key_v[o] + EPS);
        float kb = key_beta[o] - key_m[o] * sc;
        float kk = fmaf(ka, sc, kb);
        int l = r * 25 + pos;
        g_k16[((size_t)b * LPAD + l) * CC + o] = relu_h(kk);
        g_v16[((size_t)b * CC + o) * LPAD + l] = __float2half_rn(va + val_b[o]);
    }
}

// ---------------- attention via fp16 mma: CTA = (b, 32 priors) ----------------
__global__ __launch_bounds__(128)
void attn_mma(const float* __restrict__ q_w, const float* __restrict__ q_b,
              const float* __restrict__ gate_w, const float* __restrict__ gate_b,
              float* __restrict__ out) {
    __shared__ __align__(16) __half q_s[32 * 136];
    __shared__ __align__(16) __half ph_s[32 * 264];
    __shared__ float mx_s[2][32];
    __shared__ float sm_s[2][32];

    const int b = blockIdx.x, p0g = blockIdx.y * 32;
    const int tid = threadIdx.x, lane = tid & 31, wid = tid >> 5;
    const int wm = wid & 1, wn = wid >> 1;
    const int row = wm * 16 + (lane >> 2);

    for (int i = tid; i < 32 * 128; i += 128) {
        int p = i >> 7, f = i & 127;
        float qq = fmaf(g_roi[((size_t)b * NP + p0g + p) * 128 + f],
                        q_w[p0g + p], q_b[p0g + p]);
        q_s[p * 136 + f] = relu_h(qq);
    }
    __syncthreads();

    float acc[16][4];
#pragma unroll
    for (int nt = 0; nt < 16; nt++)
#pragma unroll
        for (int j = 0; j < 4; j++) acc[nt][j] = 0.f;

    const __half* kg = g_k16 + (size_t)b * LPAD * CC;
#pragma unroll
    for (int k8 = 0; k8 < 8; k8++) {
        int k0 = k8 * 16;
        uint4 a;
        a.x = *(const uint32_t*)&q_s[row * 136 + k0 + 2 * (lane & 3)];
        a.y = *(const uint32_t*)&q_s[(row + 8) * 136 + k0 + 2 * (lane & 3)];
        a.z = *(const uint32_t*)&q_s[row * 136 + k0 + 8 + 2 * (lane & 3)];
        a.w = *(const uint32_t*)&q_s[(row + 8) * 136 + k0 + 8 + 2 * (lane & 3)];
#pragma unroll
        for (int nt = 0; nt < 16; nt++) {
            int l = wn * 128 + nt * 8 + (lane >> 2);
            const __half* kr = kg + (size_t)l * CC + k0 + 2 * (lane & 3);
            uint32_t b0 = *(const uint32_t*)kr;
            uint32_t b1 = *(const uint32_t*)(kr + 8);
            mma_f16(acc[nt], a, b0, b1);
        }
    }

    const float scale = 0.08838834764831845f;
    float m0 = -1e30f, m1 = -1e30f;
#pragma unroll
    for (int nt = 0; nt < 16; nt++) {
#pragma unroll
        for (int j = 0; j < 4; j++) acc[nt][j] *= scale;
        m0 = fmaxf(m0, fmaxf(acc[nt][0], acc[nt][1]));
        m1 = fmaxf(m1, fmaxf(acc[nt][2], acc[nt][3]));
    }
    m0 = fmaxf(m0, __shfl_xor_sync(~0u, m0, 1)); m0 = fmaxf(m0, __shfl_xor_sync(~0u, m0, 2));
    m1 = fmaxf(m1, __shfl_xor_sync(~0u, m1, 1)); m1 = fmaxf(m1, __shfl_xor_sync(~0u, m1, 2));
    if ((lane & 3) == 0) {
        mx_s[wn][row] = m0;
        mx_s[wn][row + 8] = m1;
    }
    __syncthreads();
    float M0 = fmaxf(mx_s[0][row], mx_s[1][row]);
    float M1 = fmaxf(mx_s[0][row + 8], mx_s[1][row + 8]);

    float s0 = 0.f, s1 = 0.f;
#pragma unroll
    for (int nt = 0; nt < 16; nt++) {
        int lb = wn * 128 + nt * 8 + 2 * (lane & 3);
        float e0 = (lb     < LL) ? __expf(acc[nt][0] - M0) : 0.f;
        float e1 = (lb + 1 < LL) ? __expf(acc[nt][1] - M0) : 0.f;
        float e2 = (lb     < LL) ? __expf(acc[nt][2] - M1) : 0.f;
        float e3 = (lb + 1 < LL) ? __expf(acc[nt][3] - M1) : 0.f;
        s0 += e0 + e1; s1 += e2 + e3;
        __half2 h01 = __floats2half2_rn(e0, e1);
        __half2 h23 = __floats2half2_rn(e2, e3);
        *(__half2*)&ph_s[row * 264 + lb]       = h01;
        *(__half2*)&ph_s[(row + 8) * 264 + lb] = h23;
    }
    s0 += __shfl_xor_sync(~0u, s0, 1); s0 += __shfl_xor_sync(~0u, s0, 2);
    s1 += __shfl_xor_sync(~0u, s1, 1); s1 += __shfl_xor_sync(~0u, s1, 2);
    if ((lane & 3) == 0) {
        sm_s[wn][row] = s0;
        sm_s[wn][row + 8] = s1;
    }
    __syncthreads();
    float inv0 = 1.f / (sm_s[0][row] + sm_s[1][row]);
    float inv1 = 1.f / (sm_s[0][row + 8] + sm_s[1][row + 8]);

    float acc2[8][4];
#pragma unroll
    for (int ft = 0; ft < 8; ft++)
#pragma unroll
        for (int j = 0; j < 4; j++) acc2[ft][j] = 0.f;

    const __half* vg = g_v16 + (size_t)b * CC * LPAD;
#pragma unroll
    for (int ks = 0; ks < 16; ks++) {
        int k0 = ks * 16;
        uint4 a;
        a.x = *(const uint32_t*)&ph_s[row * 264 + k0 + 2 * (lane & 3)];
        a.y = *(const uint32_t*)&ph_s[(row + 8) * 264 + k0 + 2 * (lane & 3)];
        a.z = *(const uint32_t*)&ph_s[row * 264 + k0 + 8 + 2 * (lane & 3)];
        a.w = *(const uint32_t*)&ph_s[(row + 8) * 264 + k0 + 8 + 2 * (lane & 3)];
#pragma unroll
        for (int ft = 0; ft < 8; ft++) {
            int f = wn * 64 + ft * 8 + (lane >> 2);
            const __half* vr = vg + (size_t)f * LPAD + k0 + 2 * (lane & 3);
            uint32_t b0 = *(const uint32_t*)vr;
            uint32_t b1 = *(const uint32_t*)(vr + 8);
            mma_f16(acc2[ft], a, b0, b1);
        }
    }

    int gp0 = p0g + row, gp1 = gp0 + 8;
    float gw0 = gate_w[gp0], gb0 = gate_b[gp0];
    float gw1 = gate_w[gp1], gb1 = gate_b[gp1];
#pragma unroll
    for (int ft = 0; ft < 8; ft++) {
        int fb = wn * 64 + ft * 8 + 2 * (lane & 3);
        size_t o0 = ((size_t)b * NP + gp0) * 128 + fb;
        size_t o1 = ((size_t)b * NP + gp1) * 128 + fb;
        float c00 = g_roi[o0]     + fmaf(acc2[ft][0] * inv0, gw0, gb0);
        float c01 = g_roi[o0 + 1] + fmaf(acc2[ft][1] * inv0, gw0, gb0);
        float c10 = g_roi[o1]     + fmaf(acc2[ft][2] * inv1, gw1, gb1);
        float c11 = g_roi[o1 + 1] + fmaf(acc2[ft][3] * inv1, gw1, gb1);
        *(float2*)(out + o0) = make_float2(c00, c01);
        *(float2*)(out + o1) = make_float2(c10, c11);
    }
}

// ---------------- host launcher ----------------------------------------------
extern "C" void kernel_launch(void* const* d_in, const int* in_sizes, int n_in,
                              void* d_out, int out_size) {
    (void)in_sizes; (void)n_in; (void)out_size;
    const float* roi0   = (const float*)d_in[0];
    const float* roi1   = (const float*)d_in[1];
    const float* roi2   = (const float*)d_in[2];
    const float* fmap   = (const float*)d_in[3];
    const float* conv_w = (const float*)d_in[4];
    const float* conv_g = (const float*)d_in[5];
    const float* conv_b = (const float*)d_in[6];
    const float* conv_m = (const float*)d_in[7];
    const float* conv_v = (const float*)d_in[8];
    const float* cat_w  = (const float*)d_in[9];
    const float* cat_g  = (const float*)d_in[10];
    const float* cat_b  = (const float*)d_in[11];
    const float* cat_m  = (const float*)d_in[12];
    const float* cat_v  = (const float*)d_in[13];
    const float* fc_w   = (const float*)d_in[14];
    const float* fc_b   = (const float*)d_in[15];
    const float* ln_g   = (const float*)d_in[16];
    const float* ln_b   = (const float*)d_in[17];
    const float* key_w  = (const float*)d_in[18];
    const float* key_g  = (const float*)d_in[19];
    const float* key_bt = (const float*)d_in[20];
    const float* key_m  = (const float*)d_in[21];
    const float* key_v  = (const float*)d_in[22];
    const float* q_w    = (const float*)d_in[23];
    const float* q_b    = (const float*)d_in[24];
    const float* val_w  = (const float*)d_in[25];
    const float* val_b  = (const float*)d_in[26];
    const float* gate_w = (const float*)d_in[27];
    const float* gate_b = (const float*)d_in[28];
    float* out = (float*)d_out;

    __half *x16, *cat1, *cat2, *wfL, *wfC;
    cudaGetSymbolAddress((void**)&x16,  g_x16);
    cudaGetSymbolAddress((void**)&cat1, g_cat1);
    cudaGetSymbolAddress((void**)&cat2, g_cat2);
    cudaGetSymbolAddress((void**)&wfL,  g_wfL);
    cudaGetSymbolAddress((void**)&wfC,  g_wfC);

    // (1) prep (weights, transposes), (2) kv, (3) input transpose
    const int PREP_TOTAL = 3 * TL + TC + TFC + 2 * TKV;
    prep_all<<<(PREP_TOTAL + 255) / 256, 256>>>(conv_w, cat_w, fc_w, key_w, val_w);
    kv_kernel<<<dim3(BB, 10), 256>>>(fmap, key_g, key_bt, key_m, key_v, val_b);
    cvt_roi<<<dim3(NTOT, 3), 256>>>(roi0, roi1, roi2);

    // (4) level convs <- profiled slot, (5) cat conv
    conv_mma<128, 64, 8, 192, 256><<<dim3(NTOT / 8, 3), 256>>>(
        x16, wfL, conv_g, conv_b, conv_m, conv_v, cat1);
    conv_mma<192, 128, 4, 128, 256><<<dim3(NTOT / 4, 1), 256>>>(
        cat1, wfC, cat_g, cat_b, cat_m, cat_v, cat2);

    // (6) FC+LN, (7) attention
    fc_ln_relu<<<192, 128>>>(fc_b, ln_g, ln_b);
    attn_mma<<<dim3(BB, NP / 32), 128>>>(q_w, q_b, gate_w, gate_b, out);
}

// round 13
// speedup vs baseline: 7.1987x; 1.0676x over previous
#include <cuda_runtime.h>
#include <cuda_fp16.h>
#include <cstdint>

#define BB    32
#define NP    192
#define CC    128
#define NSS   36
#define FCH   128
#define EPS   1e-5f
#define NTOT  (BB*NP)      // 6144
#define LL    250
#define LPAD  256
#define KFC   (CC*NSS)     // 4608

// ---------------- scratch (device globals; no runtime allocation) -------------
__device__ __align__(16) __half g_x16 [3 * NTOT * CC * NSS];  // fp16 roi, [n][s][ci]
__device__ __align__(16) __half g_cat1[NTOT * NSS * 192];     // level out, [n][s][c]
__device__ __align__(16) __half g_cat2[NTOT * NSS * CC];      // cat out,  [n][s][c]
__device__ float  g_roi [BB * NP * FCH];                      // fc+LN+ReLU (fp32)
__device__ __align__(16) __half g_k16[BB * LPAD * CC];        // keys  [b][l][f]
__device__ __align__(16) __half g_v16[BB * CC * LPAD];        // vals  [b][f][l]
__device__ __align__(16) __half g_fcw16[FCH * KFC];           // fc_w fp16 [f][k']
__device__ __align__(16) __half g_wfL [3 * 8 * 9 * 4 * 32 * 8];   // level weight frags
__device__ __align__(16) __half g_wfC [2 * 12 * 9 * 4 * 32 * 8];  // cat frags, 2 halves
__device__ float g_kwT[CC * CC];                              // key_w transposed [c][o]
__device__ float g_vwT[CC * CC];                              // val_w transposed [c][o]

// ---------------- helpers ----------------------------------------------------
__device__ __forceinline__ uint32_t smem_u32(const void* p) {
    uint32_t a;
    asm("{ .reg .u64 t; cvta.to.shared.u64 t, %1; cvt.u32.u64 %0, t; }"
        : "=r"(a) : "l"(p));
    return a;
}
__device__ __forceinline__ void cp16(uint32_t s, const void* g) {
    asm volatile("cp.async.cg.shared.global [%0], [%1], 16;" :: "r"(s), "l"(g));
}
__device__ __forceinline__ void mma_f16(float* c, const uint4& a,
                                        uint32_t b0, uint32_t b1) {
    asm volatile("mma.sync.aligned.m16n8k16.row.col.f32.f16.f16.f32 "
                 "{%0,%1,%2,%3}, {%4,%5,%6,%7}, {%8,%9}, {%0,%1,%2,%3};"
                 : "+f"(c[0]), "+f"(c[1]), "+f"(c[2]), "+f"(c[3])
                 : "r"(a.x), "r"(a.y), "r"(a.z), "r"(a.w), "r"(b0), "r"(b1));
}
__device__ __forceinline__ void ldsm_x2(uint32_t& b0, uint32_t& b1, uint32_t addr) {
    asm volatile("ldmatrix.sync.aligned.m8n8.x2.shared.b16 {%0,%1}, [%2];"
                 : "=r"(b0), "=r"(b1) : "r"(addr));
}
__device__ __forceinline__ __half relu_h(float v) {
    return __float2half_rn(v > 0.f ? v : 0.f);
}

// ---------------- input transpose + fp16: x[n][ci][s] -> g_x16[n][s][ci] ------
__global__ __launch_bounds__(256)
void cvt_roi(const float* __restrict__ r0, const float* __restrict__ r1,
             const float* __restrict__ r2) {
    __shared__ float t_s[128 * 37];
    const int n = blockIdx.x, lvl = blockIdx.y, tid = threadIdx.x;
    const float* src = ((lvl == 0) ? r0 : (lvl == 1) ? r1 : r2) + (size_t)n * CC * NSS;
    __half* dst = g_x16 + ((size_t)lvl * NTOT + n) * NSS * CC;
    for (int i = tid; i < 128 * 36; i += 256) {
        int ci = i / 36, s = i % 36;
        t_s[ci * 37 + s] = src[i];
    }
    __syncthreads();
    for (int i = tid; i < 128 * 36; i += 256) {
        int s = i >> 7, ci = i & 127;
        dst[i] = __float2half_rn(t_s[ci * 37 + s]);
    }
}

// ---------------- merged prep: weight frags + fc_w + kv weight transpose -----
// frag layout per block: [cb][g][mt(4)][lane][8]; virtual COUT=64 everywhere.
__device__ __forceinline__ void prep_w_elem(const float* __restrict__ w,
                                            __half* __restrict__ dst,
                                            int idx, int CIN,
                                            int blk, int wstride, int total) {
    int hh = idx & 7, lane = (idx >> 3) & 31;
    int t3 = idx >> 8;
    int mt = t3 % 4, g = (t3 / 4) % 9, cb = t3 / 36;
    int j = hh >> 1, inner = hh & 1;
    int r  = (lane >> 2) + 8 * (j & 1);
    int kk = 2 * (lane & 3) + inner + 8 * (j >> 1);
    int m  = mt * 16 + r;
    int ci = cb * 16 + kk;
    dst[(size_t)blk * total + idx] =
        __float2half_rn(w[(size_t)blk * wstride + (size_t)m * (CIN * 9) + ci * 9 + g]);
}

#define TLV (8*9*4*32*8)     // 73728 per level block
#define THC (12*9*4*32*8)    // 110592 per cat half block
#define TFC (FCH*KFC)
#define TKV (CC*CC)

__global__ void prep_all(const float* __restrict__ conv_w,
                         const float* __restrict__ cat_w,
                         const float* __restrict__ fc_w,
                         const float* __restrict__ key_w,
                         const float* __restrict__ val_w) {
    int idx = blockIdx.x * 256 + threadIdx.x;
    if (idx < 3 * TLV) {
        prep_w_elem(conv_w, g_wfL, idx % TLV, 128, idx / TLV, 64 * 128 * 9, TLV);
    } else if (idx < 3 * TLV + 2 * THC) {
        int i = idx - 3 * TLV;
        prep_w_elem(cat_w, g_wfC, i % THC, 192, i / THC, 64 * 192 * 9, THC);
    } else if (idx < 3 * TLV + 2 * THC + TFC) {
        int i = idx - 3 * TLV - 2 * THC;
        int f = i / KFC, kp = i % KFC;
        int s = kp >> 7, c = kp & 127;
        g_fcw16[i] = __float2half_rn(fc_w[(size_t)f * KFC + c * NSS + s]);
    } else if (idx < 3 * TLV + 2 * THC + TFC + 2 * TKV) {
        int i = idx - 3 * TLV - 2 * THC - TFC;
        int which = i / TKV; i %= TKV;
        int c = i >> 7, o = i & 127;
        if (which == 0) g_kwT[i] = key_w[o * 128 + c];
        else            g_vwT[i] = val_w[o * 128 + c];
    }
}

// ---------------- conv9 + folded BN + ReLU via fp16 mma.sync -----------------
// Barrier-free: each warp owns one sample; private cp.async staging + commit
// groups; only __syncwarp for intra-warp ordering. COUT=64/CTA (MT=4).
// blockIdx.y selects level (3) or cat channel-half (2); c0 = y*64.
template<int CIN, int CSTRIDE>
__global__ __launch_bounds__(256, 2)
void conv_mma(const __half* __restrict__ xg, const __half* __restrict__ wfrag_,
              const float* __restrict__ bng, const float* __restrict__ bnb,
              const float* __restrict__ bnm, const float* __restrict__ bnv,
              __half* __restrict__ out, int x_blkstride) {
    constexpr int NCH  = CIN / 16;
    constexpr int SSTR = 44 * 24;                    // halves per sample window
    constexpr int CHF  = 9 * 4 * 32;                 // uint4 frags per chunk

    __shared__ __align__(16) __half x_s[2][8 * SSTR];

    const int tid  = threadIdx.x;
    const int wid  = tid >> 5, lane = tid & 31;
    const int yb   = blockIdx.y;
    const __half* x = xg + (size_t)yb * x_blkstride;
    const uint4* wf4 = (const uint4*)(wfrag_ + (size_t)yb * NCH * CHF * 8);
    const int c0   = yb * 64;
    bng += c0; bnb += c0; bnm += c0; bnv += c0;

    const int samp = wid;
    const int n0   = blockIdx.x * 8;
    const int nidx = n0 + samp;
    const __half* xsrc = x + (size_t)nidx * 36 * CIN;

    uint32_t xsu[2];
#pragma unroll
    for (int s = 0; s < 2; s++) xsu[s] = smem_u32(&x_s[s][samp * SSTR]);

    // zero own buffers (pads stay zero; data region rewritten by cp.async)
    {
        uint4 z = make_uint4(0, 0, 0, 0);
#pragma unroll 4
        for (int i = lane; i < SSTR / 8; i += 32) {      // 132 uint4 per stage
            *(uint4*)&x_s[0][samp * SSTR + i * 8] = z;
            *(uint4*)&x_s[1][samp * SSTR + i * 8] = z;
        }
    }

    // ldmatrix per-lane row address offsets (bytes)
    uint32_t aoff[5];
#pragma unroll
    for (int nt = 0; nt < 5; nt++) {
        int n = nt * 8 + (lane & 7);
        if (n > 35) n = 35;
        aoff[nt] = (uint32_t)n * 48 + (((lane >> 3) & 1) ? 16u : 0u);
    }

    float acc[4][5][4];
#pragma unroll
    for (int mt = 0; mt < 4; mt++)
#pragma unroll
        for (int nt = 0; nt < 5; nt++)
#pragma unroll
            for (int j = 0; j < 4; j++) acc[mt][nt][j] = 0.f;

    // warp-private stage of chunk cb into buffer cb%2 (72 cp16, own group)
    auto stage = [&](int cb) {
        const uint32_t base = xsu[cb & 1];
#pragma unroll 3
        for (int i = lane; i < 72; i += 32) {
            int hh = i & 1, s = i >> 1;
            cp16(base + (uint32_t)((s + 4) * 24 + hh * 8) * 2,
                 xsrc + (size_t)s * CIN + cb * 16 + hh * 8);
        }
        asm volatile("cp.async.commit_group;");
    };

    __syncwarp();            // zeros visible warp-wide before cp.async overlap
    stage(0);

    for (int cb = 0; cb < NCH; cb++) {
        if (cb) __syncwarp();            // prev compute done before overwrite
        if (cb + 1 < NCH) {
            stage(cb + 1);
            asm volatile("cp.async.wait_group 1;");
        } else {
            asm volatile("cp.async.wait_group 0;");
        }
        __syncwarp();                    // staged data visible warp-wide

        const uint32_t xb = xsu[cb & 1];
        const uint4* wfc = wf4 + (size_t)cb * CHF;
#pragma unroll
        for (int g = 0; g < 9; g++) {
            uint4 af[4];
#pragma unroll
            for (int mt = 0; mt < 4; mt++)
                af[mt] = __ldg(&wfc[(g * 4 + mt) * 32 + lane]);
#pragma unroll
            for (int nt = 0; nt < 5; nt++) {
                uint32_t b0, b1;
                ldsm_x2(b0, b1, xb + aoff[nt] + g * 48);
#pragma unroll
                for (int mt = 0; mt < 4; mt++)
                    mma_f16(acc[mt][nt], af[mt], b0, b1);
            }
        }
    }

    // epilogue: folded BN + ReLU -> fp16 [n][s][c]
#pragma unroll
    for (int mt = 0; mt < 4; mt++) {
        int cobase = mt * 16 + (lane >> 2);
#pragma unroll
        for (int h = 0; h < 2; h++) {
            int co = cobase + 8 * h;
            float sc = bng[co] * rsqrtf(bnv[co] + EPS);
            float bi = bnb[co] - bnm[co] * sc;
#pragma unroll
            for (int nt = 0; nt < 5; nt++) {
                int s0 = nt * 8 + 2 * (lane & 3);
                if (s0 < 36) {
                    out[((size_t)nidx * 36 + s0) * CSTRIDE + c0 + co] =
                        relu_h(fmaf(acc[mt][nt][2 * h], sc, bi));
                    out[((size_t)nidx * 36 + s0 + 1) * CSTRIDE + c0 + co] =
                        relu_h(fmaf(acc[mt][nt][2 * h + 1], sc, bi));
                }
            }
        }
    }
}

// ---------------- FC via fp16 mma.sync, fused LayerNorm + ReLU ---------------
__global__ __launch_bounds__(128, 1)
void fc_ln_relu(const float* __restrict__ fc_b, const float* __restrict__ ln_g,
                const float* __restrict__ ln_b) {
    __shared__ __align__(16) __half A_s[2][32][40];
    __shared__ __align__(16) __half B_s[2][128][40];

    const int tid = threadIdx.x, lane = tid & 31, wid = tid >> 5;
    const int mw = wid & 1, kw = wid >> 1;
    const int n0 = blockIdx.x * 32;
    const int r0 = mw * 16 + (lane >> 2);
    const int q2 = 2 * (lane & 3);

    float acc[16][4];
#pragma unroll
    for (int nt = 0; nt < 16; nt++)
#pragma unroll
        for (int j = 0; j < 4; j++) acc[nt][j] = 0.f;

    for (int ch = 0; ch < 72; ch++) {
        const int k0 = ch * 64;
        __syncthreads();
#pragma unroll
        for (int it = 0; it < 2; it++) {
            int i = tid + it * 128;
            int q = i & 3, r = (i >> 2) & 31, s = i >> 7;
            *(uint4*)&A_s[s][r][q * 8] =
                *(const uint4*)(g_cat2 + (size_t)(n0 + r) * KFC + k0 + s * 32 + q * 8);
        }
#pragma unroll
        for (int it = 0; it < 8; it++) {
            int i = tid + it * 128;
            int q = i & 3, f = (i >> 2) & 127, s = i >> 9;
            *(uint4*)&B_s[s][f][q * 8] =
                *(const uint4*)(g_fcw16 + (size_t)f * KFC + k0 + s * 32 + q * 8);
        }
        __syncthreads();

#pragma unroll
        for (int g = 0; g < 2; g++) {
            int kk = g * 16 + q2;
            uint4 a;
            a.x = *(const uint32_t*)&A_s[kw][r0][kk];
            a.y = *(const uint32_t*)&A_s[kw][r0 + 8][kk];
            a.z = *(const uint32_t*)&A_s[kw][r0][kk + 8];
            a.w = *(const uint32_t*)&A_s[kw][r0 + 8][kk + 8];
#pragma unroll
            for (int nt = 0; nt < 16; nt++) {
                int f = nt * 8 + (lane >> 2);
                uint32_t b0 = *(const uint32_t*)&B_s[kw][f][kk];
                uint32_t b1 = *(const uint32_t*)&B_s[kw][f][kk + 8];
                mma_f16(acc[nt], a, b0, b1);
            }
        }
    }

    __syncthreads();
    float* red = (float*)&B_s[0][0][0];
    if (kw == 1) {
#pragma unroll
        for (int nt = 0; nt < 16; nt++)
#pragma unroll
            for (int j = 0; j < 4; j++) {
                int r = mw * 16 + (lane >> 2) + 8 * (j >> 1);
                int c = nt * 8 + 2 * (lane & 3) + (j & 1);
                red[r * 130 + c] = acc[nt][j];
            }
    }
    __syncthreads();
    if (kw == 0) {
#pragma unroll
        for (int nt = 0; nt < 16; nt++) {
            int cb = nt * 8 + 2 * (lane & 3);
            int rA = mw * 16 + (lane >> 2), rB = rA + 8;
            acc[nt][0] += red[rA * 130 + cb]     + fc_b[cb];
            acc[nt][1] += red[rA * 130 + cb + 1] + fc_b[cb + 1];
            acc[nt][2] += red[rB * 130 + cb]     + fc_b[cb];
            acc[nt][3] += red[rB * 130 + cb + 1] + fc_b[cb + 1];
        }
        float s0 = 0.f, s1 = 0.f;
#pragma unroll
        for (int nt = 0; nt < 16; nt++) {
            s0 += acc[nt][0] + acc[nt][1];
            s1 += acc[nt][2] + acc[nt][3];
        }
        s0 += __shfl_xor_sync(~0u, s0, 1); s0 += __shfl_xor_sync(~0u, s0, 2);
        s1 += __shfl_xor_sync(~0u, s1, 1); s1 += __shfl_xor_sync(~0u, s1, 2);
        float m0 = s0 * (1.f / 128.f), m1 = s1 * (1.f / 128.f);
        float q0 = 0.f, q1 = 0.f;
#pragma unroll
        for (int nt = 0; nt < 16; nt++) {
            float d0 = acc[nt][0] - m0, d1 = acc[nt][1] - m0;
            float d2 = acc[nt][2] - m1, d3 = acc[nt][3] - m1;
            q0 += d0 * d0 + d1 * d1;
            q1 += d2 * d2 + d3 * d3;
        }
        q0 += __shfl_xor_sync(~0u, q0, 1); q0 += __shfl_xor_sync(~0u, q0, 2);
        q1 += __shfl_xor_sync(~0u, q1, 1); q1 += __shfl_xor_sync(~0u, q1, 2);
        float rs0 = rsqrtf(q0 * (1.f / 128.f) + EPS);
        float rs1 = rsqrtf(q1 * (1.f / 128.f) + EPS);
        int gr0 = n0 + mw * 16 + (lane >> 2), gr1 = gr0 + 8;
#pragma unroll
        for (int nt = 0; nt < 16; nt++) {
            int c = nt * 8 + 2 * (lane & 3);
            float g0 = ln_g[c], g1 = ln_g[c + 1], bb0 = ln_b[c], bb1 = ln_b[c + 1];
            float v0 = fmaxf((acc[nt][0] - m0) * rs0 * g0 + bb0, 0.f);
            float v1 = fmaxf((acc[nt][1] - m0) * rs0 * g1 + bb1, 0.f);
            float v2 = fmaxf((acc[nt][2] - m1) * rs1 * g0 + bb0, 0.f);
            float v3 = fmaxf((acc[nt][3] - m1) * rs1 * g1 + bb1, 0.f);
            *(float2*)(g_roi + (size_t)gr0 * 128 + c) = make_float2(v0, v1);
            *(float2*)(g_roi + (size_t)gr1 * 128 + c) = make_float2(v2, v3);
        }
    }
}

// ---------------- k/v at the 250 sample points (coalesced weights) ------------
__global__ __launch_bounds__(256)
void kv_kernel(const float* __restrict__ fmap,
               const float* __restrict__ key_g, const float* __restrict__ key_beta,
               const float* __restrict__ key_m, const float* __restrict__ key_v,
               const float* __restrict__ val_b) {
    __shared__ float fc_s[25 * 129];
    const int b = blockIdx.x, r = blockIdx.y;
    const int tid = threadIdx.x;
    for (int i = tid; i < 25 * 128; i += 256) {
        int c = i / 25, pos = i % 25;
        fc_s[pos * 129 + c] = fmap[((b * 128 + c) * 40 + 4 * r) * 100 + 4 * pos];
    }
    __syncthreads();
    for (int i = tid; i < 25 * 128; i += 256) {
        int o = i & 127, pos = i >> 7;
        float ka = 0.f, va = 0.f;
#pragma unroll 4
        for (int c = 0; c < 128; c++) {
            float xv = fc_s[pos * 129 + c];
            ka = fmaf(g_kwT[c * 128 + o], xv, ka);
            va = fmaf(g_vwT[c * 128 + o], xv, va);
        }
        float sc = key_g[o] * rsqrtf(key_v[o] + EPS);
        float kb = key_beta[o] - key_m[o] * sc;
        float kk = fmaf(ka, sc, kb);
        int l = r * 25 + pos;
        g_k16[((size_t)b * LPAD + l) * CC + o] = relu_h(kk);
        g_v16[((size_t)b * CC + o) * LPAD + l] = __float2half_rn(va + val_b[o]);
    }
}

// ---------------- attention via fp16 mma: CTA = (b, 32 priors) ----------------
__global__ __launch_bounds__(128)
void attn_mma(const float* __restrict__ q_w, const float* __restrict__ q_b,
              const float* __restrict__ gate_w, const float* __restrict__ gate_b,
              float* __restrict__ out) {
    __shared__ __align__(16) __half q_s[32 * 136];
    __shared__ __align__(16) __half ph_s[32 * 264];
    __shared__ float mx_s[2][32];
    __shared__ float sm_s[2][32];

    const int b = blockIdx.x, p0g = blockIdx.y * 32;
    const int tid = threadIdx.x, lane = tid & 31, wid = tid >> 5;
    const int wm = wid & 1, wn = wid >> 1;
    const int row = wm * 16 + (lane >> 2);

    for (int i = tid; i < 32 * 128; i += 128) {
        int p = i >> 7, f = i & 127;
        float qq = fmaf(g_roi[((size_t)b * NP + p0g + p) * 128 + f],
                        q_w[p0g + p], q_b[p0g + p]);
        q_s[p * 136 + f] = relu_h(qq);
    }
    __syncthreads();

    float acc[16][4];
#pragma unroll
    for (int nt = 0; nt < 16; nt++)
#pragma unroll
        for (int j = 0; j < 4; j++) acc[nt][j] = 0.f;

    const __half* kg = g_k16 + (size_t)b * LPAD * CC;
#pragma unroll
    for (int k8 = 0; k8 < 8; k8++) {
        int k0 = k8 * 16;
        uint4 a;
        a.x = *(const uint32_t*)&q_s[row * 136 + k0 + 2 * (lane & 3)];
        a.y = *(const uint32_t*)&q_s[(row + 8) * 136 + k0 + 2 * (lane & 3)];
        a.z = *(const uint32_t*)&q_s[row * 136 + k0 + 8 + 2 * (lane & 3)];
        a.w = *(const uint32_t*)&q_s[(row + 8) * 136 + k0 + 8 + 2 * (lane & 3)];
#pragma unroll
        for (int nt = 0; nt < 16; nt++) {
            int l = wn * 128 + nt * 8 + (lane >> 2);
            const __half* kr = kg + (size_t)l * CC + k0 + 2 * (lane & 3);
            uint32_t b0 = *(const uint32_t*)kr;
            uint32_t b1 = *(const uint32_t*)(kr + 8);
            mma_f16(acc[nt], a, b0, b1);
        }
    }

    const float scale = 0.08838834764831845f;
    float m0 = -1e30f, m1 = -1e30f;
#pragma unroll
    for (int nt = 0; nt < 16; nt++) {
#pragma unroll
        for (int j = 0; j < 4; j++) acc[nt][j] *= scale;
        m0 = fmaxf(m0, fmaxf(acc[nt][0], acc[nt][1]));
        m1 = fmaxf(m1, fmaxf(acc[nt][2], acc[nt][3]));
    }
    m0 = fmaxf(m0, __shfl_xor_sync(~0u, m0, 1)); m0 = fmaxf(m0, __shfl_xor_sync(~0u, m0, 2));
    m1 = fmaxf(m1, __shfl_xor_sync(~0u, m1, 1)); m1 = fmaxf(m1, __shfl_xor_sync(~0u, m1, 2));
    if ((lane & 3) == 0) {
        mx_s[wn][row] = m0;
        mx_s[wn][row + 8] = m1;
    }
    __syncthreads();
    float M0 = fmaxf(mx_s[0][row], mx_s[1][row]);
    float M1 = fmaxf(mx_s[0][row + 8], mx_s[1][row + 8]);

    float s0 = 0.f, s1 = 0.f;
#pragma unroll
    for (int nt = 0; nt < 16; nt++) {
        int lb = wn * 128 + nt * 8 + 2 * (lane & 3);
        float e0 = (lb     < LL) ? __expf(acc[nt][0] - M0) : 0.f;
        float e1 = (lb + 1 < LL) ? __expf(acc[nt][1] - M0) : 0.f;
        float e2 = (lb     < LL) ? __expf(acc[nt][2] - M1) : 0.f;
        float e3 = (lb + 1 < LL) ? __expf(acc[nt][3] - M1) : 0.f;
        s0 += e0 + e1; s1 += e2 + e3;
        __half2 h01 = __floats2half2_rn(e0, e1);
        __half2 h23 = __floats2half2_rn(e2, e3);
        *(__half2*)&ph_s[row * 264 + lb]       = h01;
        *(__half2*)&ph_s[(row + 8) * 264 + lb] = h23;
    }
    s0 += __shfl_xor_sync(~0u, s0, 1); s0 += __shfl_xor_sync(~0u, s0, 2);
    s1 += __shfl_xor_sync(~0u, s1, 1); s1 += __shfl_xor_sync(~0u, s1, 2);
    if ((lane & 3) == 0) {
        sm_s[wn][row] = s0;
        sm_s[wn][row + 8] = s1;
    }
    __syncthreads();
    float inv0 = 1.f / (sm_s[0][row] + sm_s[1][row]);
    float inv1 = 1.f / (sm_s[0][row + 8] + sm_s[1][row + 8]);

    float acc2[8][4];
#pragma unroll
    for (int ft = 0; ft < 8; ft++)
#pragma unroll
        for (int j = 0; j < 4; j++) acc2[ft][j] = 0.f;

    const __half* vg = g_v16 + (size_t)b * CC * LPAD;
#pragma unroll
    for (int ks = 0; ks < 16; ks++) {
        int k0 = ks * 16;
        uint4 a;
        a.x = *(const uint32_t*)&ph_s[row * 264 + k0 + 2 * (lane & 3)];
        a.y = *(const uint32_t*)&ph_s[(row + 8) * 264 + k0 + 2 * (lane & 3)];
        a.z = *(const uint32_t*)&ph_s[row * 264 + k0 + 8 + 2 * (lane & 3)];
        a.w = *(const uint32_t*)&ph_s[(row + 8) * 264 + k0 + 8 + 2 * (lane & 3)];
#pragma unroll
        for (int ft = 0; ft < 8; ft++) {
            int f = wn * 64 + ft * 8 + (lane >> 2);
            const __half* vr = vg + (size_t)f * LPAD + k0 + 2 * (lane & 3);
            uint32_t b0 = *(const uint32_t*)vr;
            uint32_t b1 = *(const uint32_t*)(vr + 8);
            mma_f16(acc2[ft], a, b0, b1);
        }
    }

    int gp0 = p0g + row, gp1 = gp0 + 8;
    float gw0 = gate_w[gp0], gb0 = gate_b[gp0];
    float gw1 = gate_w[gp1], gb1 = gate_b[gp1];
#pragma unroll
    for (int ft = 0; ft < 8; ft++) {
        int fb = wn * 64 + ft * 8 + 2 * (lane & 3);
        size_t o0 = ((size_t)b * NP + gp0) * 128 + fb;
        size_t o1 = ((size_t)b * NP + gp1) * 128 + fb;
        float c00 = g_roi[o0]     + fmaf(acc2[ft][0] * inv0, gw0, gb0);
        float c01 = g_roi[o0 + 1] + fmaf(acc2[ft][1] * inv0, gw0, gb0);
        float c10 = g_roi[o1]     + fmaf(acc2[ft][2] * inv1, gw1, gb1);
        float c11 = g_roi[o1 + 1] + fmaf(acc2[ft][3] * inv1, gw1, gb1);
        *(float2*)(out + o0) = make_float2(c00, c01);
        *(float2*)(out + o1) = make_float2(c10, c11);
    }
}

// ---------------- host launcher ----------------------------------------------
extern "C" void kernel_launch(void* const* d_in, const int* in_sizes, int n_in,
                              void* d_out, int out_size) {
    (void)in_sizes; (void)n_in; (void)out_size;
    const float* roi0   = (const float*)d_in[0];
    const float* roi1   = (const float*)d_in[1];
    const float* roi2   = (const float*)d_in[2];
    const float* fmap   = (const float*)d_in[3];
    const float* conv_w = (const float*)d_in[4];
    const float* conv_g = (const float*)d_in[5];
    const float* conv_b = (const float*)d_in[6];
    const float* conv_m = (const float*)d_in[7];
    const float* conv_v = (const float*)d_in[8];
    const float* cat_w  = (const float*)d_in[9];
    const float* cat_g  = (const float*)d_in[10];
    const float* cat_b  = (const float*)d_in[11];
    const float* cat_m  = (const float*)d_in[12];
    const float* cat_v  = (const float*)d_in[13];
    const float* fc_w   = (const float*)d_in[14];
    const float* fc_b   = (const float*)d_in[15];
    const float* ln_g   = (const float*)d_in[16];
    const float* ln_b   = (const float*)d_in[17];
    const float* key_w  = (const float*)d_in[18];
    const float* key_g  = (const float*)d_in[19];
    const float* key_bt = (const float*)d_in[20];
    const float* key_m  = (const float*)d_in[21];
    const float* key_v  = (const float*)d_in[22];
    const float* q_w    = (const float*)d_in[23];
    const float* q_b    = (const float*)d_in[24];
    const float* val_w  = (const float*)d_in[25];
    const float* val_b  = (const float*)d_in[26];
    const float* gate_w = (const float*)d_in[27];
    const float* gate_b = (const float*)d_in[28];
    float* out = (float*)d_out;

    __half *x16, *cat1, *cat2, *wfL, *wfC;
    cudaGetSymbolAddress((void**)&x16,  g_x16);
    cudaGetSymbolAddress((void**)&cat1, g_cat1);
    cudaGetSymbolAddress((void**)&cat2, g_cat2);
    cudaGetSymbolAddress((void**)&wfL,  g_wfL);
    cudaGetSymbolAddress((void**)&wfC,  g_wfC);

    // (1) prep, (2) kv, (3) input transpose
    const int PREP_TOTAL = 3 * TLV + 2 * THC + TFC + 2 * TKV;
    prep_all<<<(PREP_TOTAL + 255) / 256, 256>>>(conv_w, cat_w, fc_w, key_w, val_w);
    kv_kernel<<<dim3(BB, 10), 256>>>(fmap, key_g, key_bt, key_m, key_v, val_b);
    cvt_roi<<<dim3(NTOT, 3), 256>>>(roi0, roi1, roi2);

    // (4) level convs (y = level), (5) cat conv (y = channel half)
    conv_mma<128, 192><<<dim3(NTOT / 8, 3), 256>>>(
        x16, wfL, conv_g, conv_b, conv_m, conv_v, cat1, NTOT * CC * NSS);
    conv_mma<192, 128><<<dim3(NTOT / 8, 2), 256>>>(
        cat1, wfC, cat_g, cat_b, cat_m, cat_v, cat2, 0);

    // (6) FC+LN, (7) attention
    fc_ln_relu<<<192, 128>>>(fc_b, ln_g, ln_b);
    attn_mma<<<dim3(BB, NP / 32), 128>>>(q_w, q_b, gate_w, gate_b, out);
}

// round 14
// speedup vs baseline: 7.3444x; 1.0202x over previous
#include <cuda_runtime.h>
#include <cuda_fp16.h>
#include <cstdint>

#define BB    32
#define NP    192
#define CC    128
#define NSS   36
#define FCH   128
#define EPS   1e-5f
#define NTOT  (BB*NP)      // 6144
#define LL    250
#define LPAD  256
#define KFC   (CC*NSS)     // 4608

// ---------------- scratch (device globals; no runtime allocation) -------------
__device__ __align__(16) __half g_x16 [3 * NTOT * CC * NSS];  // fp16 roi, [n][s][ci]
__device__ __align__(16) __half g_cat1[NTOT * NSS * 192];     // level out, [n][s][c]
__device__ __align__(16) __half g_cat2[NTOT * NSS * CC];      // cat out,  [n][s][c]
__device__ float  g_roi [BB * NP * FCH];                      // fc+LN+ReLU (fp32)
__device__ __align__(16) __half g_k16[BB * LPAD * CC];        // keys  [b][l][f]
__device__ __align__(16) __half g_v16[BB * CC * LPAD];        // vals  [b][f][l]
__device__ __align__(16) __half g_fcw16[FCH * KFC];           // fc_w fp16 [f][k']
__device__ __align__(16) __half g_wfL [3 * 8 * 9 * 4 * 32 * 8];   // level weight frags
__device__ __align__(16) __half g_wfC [2 * 12 * 9 * 4 * 32 * 8];  // cat frags, 2 halves
__device__ float g_kwT[CC * CC];                              // key_w transposed [c][o]
__device__ float g_vwT[CC * CC];                              // val_w transposed [c][o]

// ---------------- helpers ----------------------------------------------------
__device__ __forceinline__ uint32_t smem_u32(const void* p) {
    uint32_t a;
    asm("{ .reg .u64 t; cvta.to.shared.u64 t, %1; cvt.u32.u64 %0, t; }"
        : "=r"(a) : "l"(p));
    return a;
}
__device__ __forceinline__ void cp16(uint32_t s, const void* g) {
    asm volatile("cp.async.cg.shared.global [%0], [%1], 16;" :: "r"(s), "l"(g));
}
__device__ __forceinline__ void mma_f16(float* c, const uint4& a,
                                        uint32_t b0, uint32_t b1) {
    asm volatile("mma.sync.aligned.m16n8k16.row.col.f32.f16.f16.f32 "
                 "{%0,%1,%2,%3}, {%4,%5,%6,%7}, {%8,%9}, {%0,%1,%2,%3};"
                 : "+f"(c[0]), "+f"(c[1]), "+f"(c[2]), "+f"(c[3])
                 : "r"(a.x), "r"(a.y), "r"(a.z), "r"(a.w), "r"(b0), "r"(b1));
}
__device__ __forceinline__ void ldsm_x2(uint32_t& b0, uint32_t& b1, uint32_t addr) {
    asm volatile("ldmatrix.sync.aligned.m8n8.x2.shared.b16 {%0,%1}, [%2];"
                 : "=r"(b0), "=r"(b1) : "r"(addr));
}
__device__ __forceinline__ void ldsm_x4(uint32_t& b0, uint32_t& b1,
                                        uint32_t& b2, uint32_t& b3, uint32_t addr) {
    asm volatile("ldmatrix.sync.aligned.m8n8.x4.shared.b16 {%0,%1,%2,%3}, [%4];"
                 : "=r"(b0), "=r"(b1), "=r"(b2), "=r"(b3) : "r"(addr));
}
__device__ __forceinline__ __half relu_h(float v) {
    return __float2half_rn(v > 0.f ? v : 0.f);
}

// ---------------- input transpose + fp16: x[n][ci][s] -> g_x16[n][s][ci] ------
__global__ __launch_bounds__(256)
void cvt_roi(const float* __restrict__ r0, const float* __restrict__ r1,
             const float* __restrict__ r2) {
    __shared__ float t_s[128 * 37];
    const int n = blockIdx.x, lvl = blockIdx.y, tid = threadIdx.x;
    const float* src = ((lvl == 0) ? r0 : (lvl == 1) ? r1 : r2) + (size_t)n * CC * NSS;
    __half* dst = g_x16 + ((size_t)lvl * NTOT + n) * NSS * CC;
    for (int i = tid; i < 128 * 36; i += 256) {
        int ci = i / 36, s = i % 36;
        t_s[ci * 37 + s] = src[i];
    }
    __syncthreads();
    for (int i = tid; i < 128 * 36; i += 256) {
        int s = i >> 7, ci = i & 127;
        dst[i] = __float2half_rn(t_s[ci * 37 + s]);
    }
}

// ---------------- merged prep: weight frags + fc_w + kv weight transpose -----
__device__ __forceinline__ void prep_w_elem(const float* __restrict__ w,
                                            __half* __restrict__ dst,
                                            int idx, int CIN,
                                            int blk, int wstride, int total) {
    int hh = idx & 7, lane = (idx >> 3) & 31;
    int t3 = idx >> 8;
    int mt = t3 % 4, g = (t3 / 4) % 9, cb = t3 / 36;
    int j = hh >> 1, inner = hh & 1;
    int r  = (lane >> 2) + 8 * (j & 1);
    int kk = 2 * (lane & 3) + inner + 8 * (j >> 1);
    int m  = mt * 16 + r;
    int ci = cb * 16 + kk;
    dst[(size_t)blk * total + idx] =
        __float2half_rn(w[(size_t)blk * wstride + (size_t)m * (CIN * 9) + ci * 9 + g]);
}

#define TLV (8*9*4*32*8)     // 73728 per level block
#define THC (12*9*4*32*8)    // 110592 per cat half block
#define TFC (FCH*KFC)
#define TKV (CC*CC)

__global__ void prep_all(const float* __restrict__ conv_w,
                         const float* __restrict__ cat_w,
                         const float* __restrict__ fc_w,
                         const float* __restrict__ key_w,
                         const float* __restrict__ val_w) {
    int idx = blockIdx.x * 256 + threadIdx.x;
    if (idx < 3 * TLV) {
        prep_w_elem(conv_w, g_wfL, idx % TLV, 128, idx / TLV, 64 * 128 * 9, TLV);
    } else if (idx < 3 * TLV + 2 * THC) {
        int i = idx - 3 * TLV;
        prep_w_elem(cat_w, g_wfC, i % THC, 192, i / THC, 64 * 192 * 9, THC);
    } else if (idx < 3 * TLV + 2 * THC + TFC) {
        int i = idx - 3 * TLV - 2 * THC;
        int f = i / KFC, kp = i % KFC;
        int s = kp >> 7, c = kp & 127;
        g_fcw16[i] = __float2half_rn(fc_w[(size_t)f * KFC + c * NSS + s]);
    } else if (idx < 3 * TLV + 2 * THC + TFC + 2 * TKV) {
        int i = idx - 3 * TLV - 2 * THC - TFC;
        int which = i / TKV; i %= TKV;
        int c = i >> 7, o = i & 127;
        if (which == 0) g_kwT[i] = key_w[o * 128 + c];
        else            g_vwT[i] = val_w[o * 128 + c];
    }
}

// ---------------- conv9 + folded BN + ReLU via fp16 mma.sync -----------------
// Barrier-free per-warp pipeline; B-frags via ldmatrix.x4 pairs (+x2 tail).
template<int CIN, int CSTRIDE>
__global__ __launch_bounds__(256, 2)
void conv_mma(const __half* __restrict__ xg, const __half* __restrict__ wfrag_,
              const float* __restrict__ bng, const float* __restrict__ bnb,
              const float* __restrict__ bnm, const float* __restrict__ bnv,
              __half* __restrict__ out, int x_blkstride) {
    constexpr int NCH  = CIN / 16;
    constexpr int SSTR = 44 * 24;                    // halves per sample window
    constexpr int CHF  = 9 * 4 * 32;                 // uint4 frags per chunk

    __shared__ __align__(16) __half x_s[2][8 * SSTR];

    const int tid  = threadIdx.x;
    const int wid  = tid >> 5, lane = tid & 31;
    const int yb   = blockIdx.y;
    const __half* x = xg + (size_t)yb * x_blkstride;
    const uint4* wf4 = (const uint4*)(wfrag_ + (size_t)yb * NCH * CHF * 8);
    const int c0   = yb * 64;
    bng += c0; bnb += c0; bnm += c0; bnv += c0;

    const int samp = wid;
    const int n0   = blockIdx.x * 8;
    const int nidx = n0 + samp;
    const __half* xsrc = x + (size_t)nidx * 36 * CIN;

    uint32_t xsu[2];
#pragma unroll
    for (int s = 0; s < 2; s++) xsu[s] = smem_u32(&x_s[s][samp * SSTR]);

    // zero own buffers (pads stay zero; data region rewritten by cp.async)
    {
        uint4 z = make_uint4(0, 0, 0, 0);
#pragma unroll 4
        for (int i = lane; i < SSTR / 8; i += 32) {
            *(uint4*)&x_s[0][samp * SSTR + i * 8] = z;
            *(uint4*)&x_s[1][samp * SSTR + i * 8] = z;
        }
    }

    // ldmatrix.x4 addresses for nt-pairs (0,1) and (2,3):
    // lanes 0-7: tileA k-lo rows; 8-15: tileA k-hi; 16-23: tileB k-lo; 24-31: tileB k-hi
    uint32_t aoff4[2];
#pragma unroll
    for (int p = 0; p < 2; p++) {
        int r = lane & 7, sel = (lane >> 3) & 3;
        int tile = 2 * p + (sel >> 1), khi = sel & 1;
        int pos = tile * 8 + r;                       // <= 31, no clamp needed
        aoff4[p] = (uint32_t)pos * 48 + (khi ? 16u : 0u);
    }
    // x2 tail for nt=4 (clamped rows; lanes 0-15 supply addresses)
    uint32_t aoff2;
    {
        int n = 32 + (lane & 7);
        if (n > 35) n = 35;
        aoff2 = (uint32_t)n * 48 + (((lane >> 3) & 1) ? 16u : 0u);
    }

    float acc[4][5][4];
#pragma unroll
    for (int mt = 0; mt < 4; mt++)
#pragma unroll
        for (int nt = 0; nt < 5; nt++)
#pragma unroll
            for (int j = 0; j < 4; j++) acc[mt][nt][j] = 0.f;

    // warp-private stage of chunk cb into buffer cb%2 (72 cp16, own group)
    auto stage = [&](int cb) {
        const uint32_t base = xsu[cb & 1];
#pragma unroll 3
        for (int i = lane; i < 72; i += 32) {
            int hh = i & 1, s = i >> 1;
            cp16(base + (uint32_t)((s + 4) * 24 + hh * 8) * 2,
                 xsrc + (size_t)s * CIN + cb * 16 + hh * 8);
        }
        asm volatile("cp.async.commit_group;");
    };

    __syncwarp();
    stage(0);

    for (int cb = 0; cb < NCH; cb++) {
        if (cb) __syncwarp();            // prev compute done before overwrite
        if (cb + 1 < NCH) {
            stage(cb + 1);
            asm volatile("cp.async.wait_group 1;");
        } else {
            asm volatile("cp.async.wait_group 0;");
        }
        __syncwarp();                    // staged data visible warp-wide

        const uint32_t xb = xsu[cb & 1];
        const uint4* wfc = wf4 + (size_t)cb * CHF;
#pragma unroll
        for (int g = 0; g < 9; g++) {
            uint4 af[4];
#pragma unroll
            for (int mt = 0; mt < 4; mt++)
                af[mt] = __ldg(&wfc[(g * 4 + mt) * 32 + lane]);

            uint32_t b[5][2];
            ldsm_x4(b[0][0], b[0][1], b[1][0], b[1][1], xb + aoff4[0] + g * 48);
            ldsm_x4(b[2][0], b[2][1], b[3][0], b[3][1], xb + aoff4[1] + g * 48);
            ldsm_x2(b[4][0], b[4][1], xb + aoff2 + g * 48);
#pragma unroll
            for (int nt = 0; nt < 5; nt++)
#pragma unroll
                for (int mt = 0; mt < 4; mt++)
                    mma_f16(acc[mt][nt], af[mt], b[nt][0], b[nt][1]);
        }
    }

    // epilogue: folded BN + ReLU -> fp16 [n][s][c]
#pragma unroll
    for (int mt = 0; mt < 4; mt++) {
        int cobase = mt * 16 + (lane >> 2);
#pragma unroll
        for (int h = 0; h < 2; h++) {
            int co = cobase + 8 * h;
            float sc = bng[co] * rsqrtf(bnv[co] + EPS);
            float bi = bnb[co] - bnm[co] * sc;
#pragma unroll
            for (int nt = 0; nt < 5; nt++) {
                int s0 = nt * 8 + 2 * (lane & 3);
                if (s0 < 36) {
                    out[((size_t)nidx * 36 + s0) * CSTRIDE + c0 + co] =
                        relu_h(fmaf(acc[mt][nt][2 * h], sc, bi));
                    out[((size_t)nidx * 36 + s0 + 1) * CSTRIDE + c0 + co] =
                        relu_h(fmaf(acc[mt][nt][2 * h + 1], sc, bi));
                }
            }
        }
    }
}

// ---------------- FC via fp16 mma.sync, fused LayerNorm + ReLU ---------------
__global__ __launch_bounds__(128, 1)
void fc_ln_relu(const float* __restrict__ fc_b, const float* __restrict__ ln_g,
                const float* __restrict__ ln_b) {
    __shared__ __align__(16) __half A_s[2][32][40];
    __shared__ __align__(16) __half B_s[2][128][40];

    const int tid = threadIdx.x, lane = tid & 31, wid = tid >> 5;
    const int mw = wid & 1, kw = wid >> 1;
    const int n0 = blockIdx.x * 32;
    const int r0 = mw * 16 + (lane >> 2);
    const int q2 = 2 * (lane & 3);

    float acc[16][4];
#pragma unroll
    for (int nt = 0; nt < 16; nt++)
#pragma unroll
        for (int j = 0; j < 4; j++) acc[nt][j] = 0.f;

    for (int ch = 0; ch < 72; ch++) {
        const int k0 = ch * 64;
        __syncthreads();
#pragma unroll
        for (int it = 0; it < 2; it++) {
            int i = tid + it * 128;
            int q = i & 3, r = (i >> 2) & 31, s = i >> 7;
            *(uint4*)&A_s[s][r][q * 8] =
                *(const uint4*)(g_cat2 + (size_t)(n0 + r) * KFC + k0 + s * 32 + q * 8);
        }
#pragma unroll
        for (int it = 0; it < 8; it++) {
            int i = tid + it * 128;
            int q = i & 3, f = (i >> 2) & 127, s = i >> 9;
            *(uint4*)&B_s[s][f][q * 8] =
                *(const uint4*)(g_fcw16 + (size_t)f * KFC + k0 + s * 32 + q * 8);
        }
        __syncthreads();

#pragma unroll
        for (int g = 0; g < 2; g++) {
            int kk = g * 16 + q2;
            uint4 a;
            a.x = *(const uint32_t*)&A_s[kw][r0][kk];
            a.y = *(const uint32_t*)&A_s[kw][r0 + 8][kk];
            a.z = *(const uint32_t*)&A_s[kw][r0][kk + 8];
            a.w = *(const uint32_t*)&A_s[kw][r0 + 8][kk + 8];
#pragma unroll
            for (int nt = 0; nt < 16; nt++) {
                int f = nt * 8 + (lane >> 2);
                uint32_t b0 = *(const uint32_t*)&B_s[kw][f][kk];
                uint32_t b1 = *(const uint32_t*)&B_s[kw][f][kk + 8];
                mma_f16(acc[nt], a, b0, b1);
            }
        }
    }

    __syncthreads();
    float* red = (float*)&B_s[0][0][0];
    if (kw == 1) {
#pragma unroll
        for (int nt = 0; nt < 16; nt++)
#pragma unroll
            for (int j = 0; j < 4; j++) {
                int r = mw * 16 + (lane >> 2) + 8 * (j >> 1);
                int c = nt * 8 + 2 * (lane & 3) + (j & 1);
                red[r * 130 + c] = acc[nt][j];
            }
    }
    __syncthreads();
    if (kw == 0) {
#pragma unroll
        for (int nt = 0; nt < 16; nt++) {
            int cb = nt * 8 + 2 * (lane & 3);
            int rA = mw * 16 + (lane >> 2), rB = rA + 8;
            acc[nt][0] += red[rA * 130 + cb]     + fc_b[cb];
            acc[nt][1] += red[rA * 130 + cb + 1] + fc_b[cb + 1];
            acc[nt][2] += red[rB * 130 + cb]     + fc_b[cb];
            acc[nt][3] += red[rB * 130 + cb + 1] + fc_b[cb + 1];
        }
        float s0 = 0.f, s1 = 0.f;
#pragma unroll
        for (int nt = 0; nt < 16; nt++) {
            s0 += acc[nt][0] + acc[nt][1];
            s1 += acc[nt][2] + acc[nt][3];
        }
        s0 += __shfl_xor_sync(~0u, s0, 1); s0 += __shfl_xor_sync(~0u, s0, 2);
        s1 += __shfl_xor_sync(~0u, s1, 1); s1 += __shfl_xor_sync(~0u, s1, 2);
        float m0 = s0 * (1.f / 128.f), m1 = s1 * (1.f / 128.f);
        float q0 = 0.f, q1 = 0.f;
#pragma unroll
        for (int nt = 0; nt < 16; nt++) {
            float d0 = acc[nt][0] - m0, d1 = acc[nt][1] - m0;
            float d2 = acc[nt][2] - m1, d3 = acc[nt][3] - m1;
            q0 += d0 * d0 + d1 * d1;
            q1 += d2 * d2 + d3 * d3;
        }
        q0 += __shfl_xor_sync(~0u, q0, 1); q0 += __shfl_xor_sync(~0u, q0, 2);
        q1 += __shfl_xor_sync(~0u, q1, 1); q1 += __shfl_xor_sync(~0u, q1, 2);
        float rs0 = rsqrtf(q0 * (1.f / 128.f) + EPS);
        float rs1 = rsqrtf(q1 * (1.f / 128.f) + EPS);
        int gr0 = n0 + mw * 16 + (lane >> 2), gr1 = gr0 + 8;
#pragma unroll
        for (int nt = 0; nt < 16; nt++) {
            int c = nt * 8 + 2 * (lane & 3);
            float g0 = ln_g[c], g1 = ln_g[c + 1], bb0 = ln_b[c], bb1 = ln_b[c + 1];
            float v0 = fmaxf((acc[nt][0] - m0) * rs0 * g0 + bb0, 0.f);
            float v1 = fmaxf((acc[nt][1] - m0) * rs0 * g1 + bb1, 0.f);
            float v2 = fmaxf((acc[nt][2] - m1) * rs1 * g0 + bb0, 0.f);
            float v3 = fmaxf((acc[nt][3] - m1) * rs1 * g1 + bb1, 0.f);
            *(float2*)(g_roi + (size_t)gr0 * 128 + c) = make_float2(v0, v1);
            *(float2*)(g_roi + (size_t)gr1 * 128 + c) = make_float2(v2, v3);
        }
    }
}

// ---------------- k/v at the 250 sample points (coalesced weights) ------------
__global__ __launch_bounds__(256)
void kv_kernel(const float* __restrict__ fmap,
               const float* __restrict__ key_g, const float* __restrict__ key_beta,
               const float* __restrict__ key_m, const float* __restrict__ key_v,
               const float* __restrict__ val_b) {
    __shared__ float fc_s[25 * 129];
    const int b = blockIdx.x, r = blockIdx.y;
    const int tid = threadIdx.x;
    for (int i = tid; i < 25 * 128; i += 256) {
        int c = i / 25, pos = i % 25;
        fc_s[pos * 129 + c] = fmap[((b * 128 + c) * 40 + 4 * r) * 100 + 4 * pos];
    }
    __syncthreads();
    for (int i = tid; i < 25 * 128; i += 256) {
        int o = i & 127, pos = i >> 7;
        float ka = 0.f, va = 0.f;
#pragma unroll 4
        for (int c = 0; c < 128; c++) {
            float xv = fc_s[pos * 129 + c];
            ka = fmaf(g_kwT[c * 128 + o], xv, ka);
            va = fmaf(g_vwT[c * 128 + o], xv, va);
        }
        float sc = key_g[o] * rsqrtf(key_v[o] + EPS);
        float kb = key_beta[o] - key_m[o] * sc;
        float kk = fmaf(ka, sc, kb);
        int l = r * 25 + pos;
        g_k16[((size_t)b * LPAD + l) * CC + o] = relu_h(kk);
        g_v16[((size_t)b * CC + o) * LPAD + l] = __float2half_rn(va + val_b[o]);
    }
}

// ---------------- attention via fp16 mma: CTA = (b, 32 priors) ----------------
__global__ __launch_bounds__(128)
void attn_mma(const float* __restrict__ q_w, const float* __restrict__ q_b,
              const float* __restrict__ gate_w, const float* __restrict__ gate_b,
              float* __restrict__ out) {
    __shared__ __align__(16) __half q_s[32 * 136];
    __shared__ __align__(16) __half ph_s[32 * 264];
    __shared__ float mx_s[2][32];
    __shared__ float sm_s[2][32];

    const int b = blockIdx.x, p0g = blockIdx.y * 32;
    const int tid = threadIdx.x, lane = tid & 31, wid = tid >> 5;
    const int wm = wid & 1, wn = wid >> 1;
    const int row = wm * 16 + (lane >> 2);

    for (int i = tid; i < 32 * 128; i += 128) {
        int p = i >> 7, f = i & 127;
        float qq = fmaf(g_roi[((size_t)b * NP + p0g + p) * 128 + f],
                        q_w[p0g + p], q_b[p0g + p]);
        q_s[p * 136 + f] = relu_h(qq);
    }
    __syncthreads();

    float acc[16][4];
#pragma unroll
    for (int nt = 0; nt < 16; nt++)
#pragma unroll
        for (int j = 0; j < 4; j++) acc[nt][j] = 0.f;

    const __half* kg = g_k16 + (size_t)b * LPAD * CC;
#pragma unroll
    for (int k8 = 0; k8 < 8; k8++) {
        int k0 = k8 * 16;
        uint4 a;
        a.x = *(const uint32_t*)&q_s[row * 136 + k0 + 2 * (lane & 3)];
        a.y = *(const uint32_t*)&q_s[(row + 8) * 136 + k0 + 2 * (lane & 3)];
        a.z = *(const uint32_t*)&q_s[row * 136 + k0 + 8 + 2 * (lane & 3)];
        a.w = *(const uint32_t*)&q_s[(row + 8) * 136 + k0 + 8 + 2 * (lane & 3)];
#pragma unroll
        for (int nt = 0; nt < 16; nt++) {
            int l = wn * 128 + nt * 8 + (lane >> 2);
            const __half* kr = kg + (size_t)l * CC + k0 + 2 * (lane & 3);
            uint32_t b0 = *(const uint32_t*)kr;
            uint32_t b1 = *(const uint32_t*)(kr + 8);
            mma_f16(acc[nt], a, b0, b1);
        }
    }

    const float scale = 0.08838834764831845f;
    float m0 = -1e30f, m1 = -1e30f;
#pragma unroll
    for (int nt = 0; nt < 16; nt++) {
#pragma unroll
        for (int j = 0; j < 4; j++) acc[nt][j] *= scale;
        m0 = fmaxf(m0, fmaxf(acc[nt][0], acc[nt][1]));
        m1 = fmaxf(m1, fmaxf(acc[nt][2], acc[nt][3]));
    }
    m0 = fmaxf(m0, __shfl_xor_sync(~0u, m0, 1)); m0 = fmaxf(m0, __shfl_xor_sync(~0u, m0, 2));
    m1 = fmaxf(m1, __shfl_xor_sync(~0u, m1, 1)); m1 = fmaxf(m1, __shfl_xor_sync(~0u, m1, 2));
    if ((lane & 3) == 0) {
        mx_s[wn][row] = m0;
        mx_s[wn][row + 8] = m1;
    }
    __syncthreads();
    float M0 = fmaxf(mx_s[0][row], mx_s[1][row]);
    float M1 = fmaxf(mx_s[0][row + 8], mx_s[1][row + 8]);

    float s0 = 0.f, s1 = 0.f;
#pragma unroll
    for (int nt = 0; nt < 16; nt++) {
        int lb = wn * 128 + nt * 8 + 2 * (lane & 3);
        float e0 = (lb     < LL) ? __expf(acc[nt][0] - M0) : 0.f;
        float e1 = (lb + 1 < LL) ? __expf(acc[nt][1] - M0) : 0.f;
        float e2 = (lb     < LL) ? __expf(acc[nt][2] - M1) : 0.f;
        float e3 = (lb + 1 < LL) ? __expf(acc[nt][3] - M1) : 0.f;
        s0 += e0 + e1; s1 += e2 + e3;
        __half2 h01 = __floats2half2_rn(e0, e1);
        __half2 h23 = __floats2half2_rn(e2, e3);
        *(__half2*)&ph_s[row * 264 + lb]       = h01;
        *(__half2*)&ph_s[(row + 8) * 264 + lb] = h23;
    }
    s0 += __shfl_xor_sync(~0u, s0, 1); s0 += __shfl_xor_sync(~0u, s0, 2);
    s1 += __shfl_xor_sync(~0u, s1, 1); s1 += __shfl_xor_sync(~0u, s1, 2);
    if ((lane & 3) == 0) {
        sm_s[wn][row] = s0;
        sm_s[wn][row + 8] = s1;
    }
    __syncthreads();
    float inv0 = 1.f / (sm_s[0][row] + sm_s[1][row]);
    float inv1 = 1.f / (sm_s[0][row + 8] + sm_s[1][row + 8]);

    float acc2[8][4];
#pragma unroll
    for (int ft = 0; ft < 8; ft++)
#pragma unroll
        for (int j = 0; j < 4; j++) acc2[ft][j] = 0.f;

    const __half* vg = g_v16 + (size_t)b * CC * LPAD;
#pragma unroll
    for (int ks = 0; ks < 16; ks++) {
        int k0 = ks * 16;
        uint4 a;
        a.x = *(const uint32_t*)&ph_s[row * 264 + k0 + 2 * (lane & 3)];
        a.y = *(const uint32_t*)&ph_s[(row + 8) * 264 + k0 + 2 * (lane & 3)];
        a.z = *(const uint32_t*)&ph_s[row * 264 + k0 + 8 + 2 * (lane & 3)];
        a.w = *(const uint32_t*)&ph_s[(row + 8) * 264 + k0 + 8 + 2 * (lane & 3)];
#pragma unroll
        for (int ft = 0; ft < 8; ft++) {
            int f = wn * 64 + ft * 8 + (lane >> 2);
            const __half* vr = vg + (size_t)f * LPAD + k0 + 2 * (lane & 3);
            uint32_t b0 = *(const uint32_t*)vr;
            uint32_t b1 = *(const uint32_t*)(vr + 8);
            mma_f16(acc2[ft], a, b0, b1);
        }
    }

    int gp0 = p0g + row, gp1 = gp0 + 8;
    float gw0 = gate_w[gp0], gb0 = gate_b[gp0];
    float gw1 = gate_w[gp1], gb1 = gate_b[gp1];
#pragma unroll
    for (int ft = 0; ft < 8; ft++) {
        int fb = wn * 64 + ft * 8 + 2 * (lane & 3);
        size_t o0 = ((size_t)b * NP + gp0) * 128 + fb;
        size_t o1 = ((size_t)b * NP + gp1) * 128 + fb;
        float c00 = g_roi[o0]     + fmaf(acc2[ft][0] * inv0, gw0, gb0);
        float c01 = g_roi[o0 + 1] + fmaf(acc2[ft][1] * inv0, gw0, gb0);
        float c10 = g_roi[o1]     + fmaf(acc2[ft][2] * inv1, gw1, gb1);
        float c11 = g_roi[o1 + 1] + fmaf(acc2[ft][3] * inv1, gw1, gb1);
        *(float2*)(out + o0) = make_float2(c00, c01);
        *(float2*)(out + o1) = make_float2(c10, c11);
    }
}

// ---------------- host launcher ----------------------------------------------
extern "C" void kernel_launch(void* const* d_in, const int* in_sizes, int n_in,
                              void* d_out, int out_size) {
    (void)in_sizes; (void)n_in; (void)out_size;
    const float* roi0   = (const float*)d_in[0];
    const float* roi1   = (const float*)d_in[1];
    const float* roi2   = (const float*)d_in[2];
    const float* fmap   = (const float*)d_in[3];
    const float* conv_w = (const float*)d_in[4];
    const float* conv_g = (const float*)d_in[5];
    const float* conv_b = (const float*)d_in[6];
    const float* conv_m = (const float*)d_in[7];
    const float* conv_v = (const float*)d_in[8];
    const float* cat_w  = (const float*)d_in[9];
    const float* cat_g  = (const float*)d_in[10];
    const float* cat_b  = (const float*)d_in[11];
    const float* cat_m  = (const float*)d_in[12];
    const float* cat_v  = (const float*)d_in[13];
    const float* fc_w   = (const float*)d_in[14];
    const float* fc_b   = (const float*)d_in[15];
    const float* ln_g   = (const float*)d_in[16];
    const float* ln_b   = (const float*)d_in[17];
    const float* key_w  = (const float*)d_in[18];
    const float* key_g  = (const float*)d_in[19];
    const float* key_bt = (const float*)d_in[20];
    const float* key_m  = (const float*)d_in[21];
    const float* key_v  = (const float*)d_in[22];
    const float* q_w    = (const float*)d_in[23];
    const float* q_b    = (const float*)d_in[24];
    const float* val_w  = (const float*)d_in[25];
    const float* val_b  = (const float*)d_in[26];
    const float* gate_w = (const float*)d_in[27];
    const float* gate_b = (const float*)d_in[28];
    float* out = (float*)d_out;

    __half *x16, *cat1, *cat2, *wfL, *wfC;
    cudaGetSymbolAddress((void**)&x16,  g_x16);
    cudaGetSymbolAddress((void**)&cat1, g_cat1);
    cudaGetSymbolAddress((void**)&cat2, g_cat2);
    cudaGetSymbolAddress((void**)&wfL,  g_wfL);
    cudaGetSymbolAddress((void**)&wfC,  g_wfC);

    // (1) prep, (2) kv, (3) input transpose
    const int PREP_TOTAL = 3 * TLV + 2 * THC + TFC + 2 * TKV;
    prep_all<<<(PREP_TOTAL + 255) / 256, 256>>>(conv_w, cat_w, fc_w, key_w, val_w);
    kv_kernel<<<dim3(BB, 10), 256>>>(fmap, key_g, key_bt, key_m, key_v, val_b);
    cvt_roi<<<dim3(NTOT, 3), 256>>>(roi0, roi1, roi2);

    // (4) level convs (y = level), (5) cat conv (y = channel half)
    conv_mma<128, 192><<<dim3(NTOT / 8, 3), 256>>>(
        x16, wfL, conv_g, conv_b, conv_m, conv_v, cat1, NTOT * CC * NSS);
    conv_mma<192, 128><<<dim3(NTOT / 8, 2), 256>>>(
        cat1, wfC, cat_g, cat_b, cat_m, cat_v, cat2, 0);

    // (6) FC+LN, (7) attention
    fc_ln_relu<<<192, 128>>>(fc_b, ln_g, ln_b);
    attn_mma<<<dim3(BB, NP / 32), 128>>>(q_w, q_b, gate_w, gate_b, out);
}

// round 16
// speedup vs baseline: 7.4768x; 1.0180x over previous
#include <cuda_runtime.h>
#include <cuda_fp16.h>
#include <cstdint>

#define BB    32
#define NP    192
#define CC    128
#define NSS   36
#define FCH   128
#define EPS   1e-5f
#define NTOT  (BB*NP)      // 6144
#define LL    250
#define LPAD  256
#define KFC   (CC*NSS)     // 4608

// ---------------- scratch (device globals; no runtime allocation) -------------
__device__ __align__(16) __half g_x16 [3 * NTOT * CC * NSS];  // fp16 roi, [n][s][ci]
__device__ __align__(16) __half g_cat1[NTOT * NSS * 192];     // level out, [n][s][c]
__device__ __align__(16) __half g_cat2[NTOT * NSS * CC];      // cat out,  [n][s][c]
__device__ float  g_roi [BB * NP * FCH];                      // fc+LN+ReLU (fp32)
__device__ __align__(16) __half g_k16[BB * LPAD * CC];        // keys  [b][l][f]
__device__ __align__(16) __half g_v16[BB * CC * LPAD];        // vals  [b][f][l]
__device__ __align__(16) __half g_fcw16[FCH * KFC];           // fc_w fp16 [f][k']
__device__ __align__(16) __half g_wfL [3 * 8 * 9 * 4 * 32 * 8];   // level weight frags
__device__ __align__(16) __half g_wfC [2 * 12 * 9 * 4 * 32 * 8];  // cat frags, 2 halves
__device__ float g_kwT[CC * CC];                              // key_w transposed [c][o]
__device__ float g_vwT[CC * CC];                              // val_w transposed [c][o]

// ---------------- helpers ----------------------------------------------------
__device__ __forceinline__ uint32_t smem_u32(const void* p) {
    uint32_t a;
    asm("{ .reg .u64 t; cvta.to.shared.u64 t, %1; cvt.u32.u64 %0, t; }"
        : "=r"(a) : "l"(p));
    return a;
}
__device__ __forceinline__ void cp16(uint32_t s, const void* g) {
    asm volatile("cp.async.cg.shared.global [%0], [%1], 16;" :: "r"(s), "l"(g));
}
__device__ __forceinline__ void mma_f16(float* c, const uint4& a,
                                        uint32_t b0, uint32_t b1) {
    asm volatile("mma.sync.aligned.m16n8k16.row.col.f32.f16.f16.f32 "
                 "{%0,%1,%2,%3}, {%4,%5,%6,%7}, {%8,%9}, {%0,%1,%2,%3};"
                 : "+f"(c[0]), "+f"(c[1]), "+f"(c[2]), "+f"(c[3])
                 : "r"(a.x), "r"(a.y), "r"(a.z), "r"(a.w), "r"(b0), "r"(b1));
}
__device__ __forceinline__ void ldsm_x2(uint32_t& b0, uint32_t& b1, uint32_t addr) {
    asm volatile("ldmatrix.sync.aligned.m8n8.x2.shared.b16 {%0,%1}, [%2];"
                 : "=r"(b0), "=r"(b1) : "r"(addr));
}
__device__ __forceinline__ void ldsm_x4(uint32_t& b0, uint32_t& b1,
                                        uint32_t& b2, uint32_t& b3, uint32_t addr) {
    asm volatile("ldmatrix.sync.aligned.m8n8.x4.shared.b16 {%0,%1,%2,%3}, [%4];"
                 : "=r"(b0), "=r"(b1), "=r"(b2), "=r"(b3) : "r"(addr));
}
__device__ __forceinline__ __half relu_h(float v) {
    return __float2half_rn(v > 0.f ? v : 0.f);
}

// ---------------- input transpose + fp16: x[n][ci][s] -> g_x16[n][s][ci] ------
__global__ __launch_bounds__(256)
void cvt_roi(const float* __restrict__ r0, const float* __restrict__ r1,
             const float* __restrict__ r2) {
    __shared__ float t_s[128 * 37];
    const int n = blockIdx.x, lvl = blockIdx.y, tid = threadIdx.x;
    const float* src = ((lvl == 0) ? r0 : (lvl == 1) ? r1 : r2) + (size_t)n * CC * NSS;
    __half* dst = g_x16 + ((size_t)lvl * NTOT + n) * NSS * CC;
    for (int i = tid; i < 128 * 36; i += 256) {
        int ci = i / 36, s = i % 36;
        t_s[ci * 37 + s] = src[i];
    }
    __syncthreads();
    for (int i = tid; i < 128 * 36; i += 256) {
        int s = i >> 7, ci = i & 127;
        dst[i] = __float2half_rn(t_s[ci * 37 + s]);
    }
}

// ---------------- merged prep: weight frags + fc_w + kv weight transpose -----
__device__ __forceinline__ void prep_w_elem(const float* __restrict__ w,
                                            __half* __restrict__ dst,
                                            int idx, int CIN,
                                            int blk, int wstride, int total) {
    int hh = idx & 7, lane = (idx >> 3) & 31;
    int t3 = idx >> 8;
    int mt = t3 % 4, g = (t3 / 4) % 9, cb = t3 / 36;
    int j = hh >> 1, inner = hh & 1;
    int r  = (lane >> 2) + 8 * (j & 1);
    int kk = 2 * (lane & 3) + inner + 8 * (j >> 1);
    int m  = mt * 16 + r;
    int ci = cb * 16 + kk;
    dst[(size_t)blk * total + idx] =
        __float2half_rn(w[(size_t)blk * wstride + (size_t)m * (CIN * 9) + ci * 9 + g]);
}

#define TLV (8*9*4*32*8)     // 73728 per level block
#define THC (12*9*4*32*8)    // 110592 per cat half block
#define TFC (FCH*KFC)
#define TKV (CC*CC)

__global__ void prep_all(const float* __restrict__ conv_w,
                         const float* __restrict__ cat_w,
                         const float* __restrict__ fc_w,
                         const float* __restrict__ key_w,
                         const float* __restrict__ val_w) {
    int idx = blockIdx.x * 256 + threadIdx.x;
    if (idx < 3 * TLV) {
        prep_w_elem(conv_w, g_wfL, idx % TLV, 128, idx / TLV, 64 * 128 * 9, TLV);
    } else if (idx < 3 * TLV + 2 * THC) {
        int i = idx - 3 * TLV;
        prep_w_elem(cat_w, g_wfC, i % THC, 192, i / THC, 64 * 192 * 9, THC);
    } else if (idx < 3 * TLV + 2 * THC + TFC) {
        int i = idx - 3 * TLV - 2 * THC;
        int f = i / KFC, kp = i % KFC;
        int s = kp >> 7, c = kp & 127;
        g_fcw16[i] = __float2half_rn(fc_w[(size_t)f * KFC + c * NSS + s]);
    } else if (idx < 3 * TLV + 2 * THC + TFC + 2 * TKV) {
        int i = idx - 3 * TLV - 2 * THC - TFC;
        int which = i / TKV; i %= TKV;
        int c = i >> 7, o = i & 127;
        if (which == 0) g_kwT[i] = key_w[o * 128 + c];
        else            g_vwT[i] = val_w[o * 128 + c];
    }
}

// ---------------- conv9 + folded BN + ReLU via fp16 mma.sync -----------------
// Barrier-free per-warp pipeline; B-frags via ldmatrix.x4 pairs (+x2 tail).
template<int CIN, int CSTRIDE>
__global__ __launch_bounds__(256, 2)
void conv_mma(const __half* __restrict__ xg, const __half* __restrict__ wfrag_,
              const float* __restrict__ bng, const float* __restrict__ bnb,
              const float* __restrict__ bnm, const float* __restrict__ bnv,
              __half* __restrict__ out, int x_blkstride) {
    constexpr int NCH  = CIN / 16;
    constexpr int SSTR = 44 * 24;                    // halves per sample window
    constexpr int CHF  = 9 * 4 * 32;                 // uint4 frags per chunk

    __shared__ __align__(16) __half x_s[2][8 * SSTR];

    const int tid  = threadIdx.x;
    const int wid  = tid >> 5, lane = tid & 31;
    const int yb   = blockIdx.y;
    const __half* x = xg + (size_t)yb * x_blkstride;
    const uint4* wf4 = (const uint4*)(wfrag_ + (size_t)yb * NCH * CHF * 8);
    const int c0   = yb * 64;
    bng += c0; bnb += c0; bnm += c0; bnv += c0;

    const int samp = wid;
    const int n0   = blockIdx.x * 8;
    const int nidx = n0 + samp;
    const __half* xsrc = x + (size_t)nidx * 36 * CIN;

    uint32_t xsu[2];
#pragma unroll
    for (int s = 0; s < 2; s++) xsu[s] = smem_u32(&x_s[s][samp * SSTR]);

    // zero own buffers
    {
        uint4 z = make_uint4(0, 0, 0, 0);
#pragma unroll 4
        for (int i = lane; i < SSTR / 8; i += 32) {
            *(uint4*)&x_s[0][samp * SSTR + i * 8] = z;
            *(uint4*)&x_s[1][samp * SSTR + i * 8] = z;
        }
    }

    // ldmatrix.x4 addresses for nt-pairs (0,1) and (2,3)
    uint32_t aoff4[2];
#pragma unroll
    for (int p = 0; p < 2; p++) {
        int r = lane & 7, sel = (lane >> 3) & 3;
        int tile = 2 * p + (sel >> 1), khi = sel & 1;
        int pos = tile * 8 + r;
        aoff4[p] = (uint32_t)pos * 48 + (khi ? 16u : 0u);
    }
    uint32_t aoff2;
    {
        int n = 32 + (lane & 7);
        if (n > 35) n = 35;
        aoff2 = (uint32_t)n * 48 + (((lane >> 3) & 1) ? 16u : 0u);
    }

    float acc[4][5][4];
#pragma unroll
    for (int mt = 0; mt < 4; mt++)
#pragma unroll
        for (int nt = 0; nt < 5; nt++)
#pragma unroll
            for (int j = 0; j < 4; j++) acc[mt][nt][j] = 0.f;

    auto stage = [&](int cb) {
        const uint32_t base = xsu[cb & 1];
#pragma unroll 3
        for (int i = lane; i < 72; i += 32) {
            int hh = i & 1, s = i >> 1;
            cp16(base + (uint32_t)((s + 4) * 24 + hh * 8) * 2,
                 xsrc + (size_t)s * CIN + cb * 16 + hh * 8);
        }
        asm volatile("cp.async.commit_group;");
    };

    __syncwarp();
    stage(0);

    for (int cb = 0; cb < NCH; cb++) {
        if (cb) __syncwarp();
        if (cb + 1 < NCH) {
            stage(cb + 1);
            asm volatile("cp.async.wait_group 1;");
        } else {
            asm volatile("cp.async.wait_group 0;");
        }
        __syncwarp();

        const uint32_t xb = xsu[cb & 1];
        const uint4* wfc = wf4 + (size_t)cb * CHF;
#pragma unroll
        for (int g = 0; g < 9; g++) {
            uint4 af[4];
#pragma unroll
            for (int mt = 0; mt < 4; mt++)
                af[mt] = __ldg(&wfc[(g * 4 + mt) * 32 + lane]);

            uint32_t b[5][2];
            ldsm_x4(b[0][0], b[0][1], b[1][0], b[1][1], xb + aoff4[0] + g * 48);
            ldsm_x4(b[2][0], b[2][1], b[3][0], b[3][1], xb + aoff4[1] + g * 48);
            ldsm_x2(b[4][0], b[4][1], xb + aoff2 + g * 48);
#pragma unroll
            for (int nt = 0; nt < 5; nt++)
#pragma unroll
                for (int mt = 0; mt < 4; mt++)
                    mma_f16(acc[mt][nt], af[mt], b[nt][0], b[nt][1]);
        }
    }

    // epilogue: folded BN + ReLU -> fp16 [n][s][c] (direct stores)
#pragma unroll
    for (int mt = 0; mt < 4; mt++) {
        int cobase = mt * 16 + (lane >> 2);
#pragma unroll
        for (int h = 0; h < 2; h++) {
            int co = cobase + 8 * h;
            float sc = bng[co] * rsqrtf(bnv[co] + EPS);
            float bi = bnb[co] - bnm[co] * sc;
#pragma unroll
            for (int nt = 0; nt < 5; nt++) {
                int s0 = nt * 8 + 2 * (lane & 3);
                if (s0 < 36) {
                    out[((size_t)nidx * 36 + s0) * CSTRIDE + c0 + co] =
                        relu_h(fmaf(acc[mt][nt][2 * h], sc, bi));
                    out[((size_t)nidx * 36 + s0 + 1) * CSTRIDE + c0 + co] =
                        relu_h(fmaf(acc[mt][nt][2 * h + 1], sc, bi));
                }
            }
        }
    }
}

// ---------------- FC via fp16 mma.sync + cp.async pipeline, fused LN+ReLU ----
// dyn smem: A[2][2][32][40] (5120 halves) then B[2][2][128][40] (20480 halves)
#define FC_A(buf, s, r)  ((((buf) * 2 + (s)) * 32 + (r)) * 40)
#define FC_B(buf, s, f)  (5120 + (((buf) * 2 + (s)) * 128 + (f)) * 40)
#define FC_SMEM_BYTES    ((5120 + 20480) * 2)

__global__ __launch_bounds__(128, 1)
void fc_ln_relu(const float* __restrict__ fc_b, const float* __restrict__ ln_g,
                const float* __restrict__ ln_b) {
    extern __shared__ __align__(16) __half fcsm[];
    const uint32_t smb = smem_u32(fcsm);

    const int tid = threadIdx.x, lane = tid & 31, wid = tid >> 5;
    const int mw = wid & 1, kw = wid >> 1;
    const int n0 = blockIdx.x * 32;
    const int r0 = mw * 16 + (lane >> 2);
    const int q2 = 2 * (lane & 3);

    float acc[16][4];
#pragma unroll
    for (int nt = 0; nt < 16; nt++)
#pragma unroll
        for (int j = 0; j < 4; j++) acc[nt][j] = 0.f;

    auto stage = [&](int ch) {
        int buf = ch & 1;
#pragma unroll
        for (int it = 0; it < 2; it++) {
            int i = tid + it * 128;
            int q = i & 3, r = (i >> 2) & 31, s = i >> 7;
            cp16(smb + (uint32_t)(FC_A(buf, s, r) + q * 8) * 2,
                 g_cat2 + (size_t)(n0 + r) * KFC + ch * 64 + s * 32 + q * 8);
        }
#pragma unroll
        for (int it = 0; it < 8; it++) {
            int i = tid + it * 128;
            int q = i & 3, f = (i >> 2) & 127, s = i >> 9;
            cp16(smb + (uint32_t)(FC_B(buf, s, f) + q * 8) * 2,
                 g_fcw16 + (size_t)f * KFC + ch * 64 + s * 32 + q * 8);
        }
        asm volatile("cp.async.commit_group;");
    };

    stage(0);
    for (int ch = 0; ch < 72; ch++) {
        if (ch + 1 < 72) {
            stage(ch + 1);
            asm volatile("cp.async.wait_group 1;");
        } else {
            asm volatile("cp.async.wait_group 0;");
        }
        __syncthreads();                  // chunk ch staged & visible

        int buf = ch & 1;
#pragma unroll
        for (int g = 0; g < 2; g++) {
            int kk = g * 16 + q2;
            uint4 a;
            a.x = *(const uint32_t*)&fcsm[FC_A(buf, kw, r0) + kk];
            a.y = *(const uint32_t*)&fcsm[FC_A(buf, kw, r0 + 8) + kk];
            a.z = *(const uint32_t*)&fcsm[FC_A(buf, kw, r0) + kk + 8];
            a.w = *(const uint32_t*)&fcsm[FC_A(buf, kw, r0 + 8) + kk + 8];
#pragma unroll
            for (int nt = 0; nt < 16; nt++) {
                int f = nt * 8 + (lane >> 2);
                uint32_t b0 = *(const uint32_t*)&fcsm[FC_B(buf, kw, f) + kk];
                uint32_t b1 = *(const uint32_t*)&fcsm[FC_B(buf, kw, f) + kk + 8];
                mma_f16(acc[nt], a, b0, b1);
            }
        }
        __syncthreads();                  // reads done before buf reuse at ch+2
    }

    // cross-kw reduce through smem (reuse fcsm as fp32 area)
    float* red = (float*)fcsm;            // 32 x 130 fp32 = 16.6KB < 51.2KB
    if (kw == 1) {
#pragma unroll
        for (int nt = 0; nt < 16; nt++)
#pragma unroll
            for (int j = 0; j < 4; j++) {
                int r = mw * 16 + (lane >> 2) + 8 * (j >> 1);
                int c = nt * 8 + 2 * (lane & 3) + (j & 1);
                red[r * 130 + c] = acc[nt][j];
            }
    }
    __syncthreads();
    if (kw == 0) {
#pragma unroll
        for (int nt = 0; nt < 16; nt++) {
            int cb = nt * 8 + 2 * (lane & 3);
            int rA = mw * 16 + (lane >> 2), rB = rA + 8;
            acc[nt][0] += red[rA * 130 + cb]     + fc_b[cb];
            acc[nt][1] += red[rA * 130 + cb + 1] + fc_b[cb + 1];
            acc[nt][2] += red[rB * 130 + cb]     + fc_b[cb];
            acc[nt][3] += red[rB * 130 + cb + 1] + fc_b[cb + 1];
        }
        float s0 = 0.f, s1 = 0.f;
#pragma unroll
        for (int nt = 0; nt < 16; nt++) {
            s0 += acc[nt][0] + acc[nt][1];
            s1 += acc[nt][2] + acc[nt][3];
        }
        s0 += __shfl_xor_sync(~0u, s0, 1); s0 += __shfl_xor_sync(~0u, s0, 2);
        s1 += __shfl_xor_sync(~0u, s1, 1); s1 += __shfl_xor_sync(~0u, s1, 2);
        float m0 = s0 * (1.f / 128.f), m1 = s1 * (1.f / 128.f);
        float q0 = 0.f, q1 = 0.f;
#pragma unroll
        for (int nt = 0; nt < 16; nt++) {
            float d0 = acc[nt][0] - m0, d1 = acc[nt][1] - m0;
            float d2 = acc[nt][2] - m1, d3 = acc[nt][3] - m1;
            q0 += d0 * d0 + d1 * d1;
            q1 += d2 * d2 + d3 * d3;
        }
        q0 += __shfl_xor_sync(~0u, q0, 1); q0 += __shfl_xor_sync(~0u, q0, 2);
        q1 += __shfl_xor_sync(~0u, q1, 1); q1 += __shfl_xor_sync(~0u, q1, 2);
        float rs0 = rsqrtf(q0 * (1.f / 128.f) + EPS);
        float rs1 = rsqrtf(q1 * (1.f / 128.f) + EPS);
        int gr0 = n0 + mw * 16 + (lane >> 2), gr1 = gr0 + 8;
#pragma unroll
        for (int nt = 0; nt < 16; nt++) {
            int c = nt * 8 + 2 * (lane & 3);
            float g0 = ln_g[c], g1 = ln_g[c + 1], bb0 = ln_b[c], bb1 = ln_b[c + 1];
            float v0 = fmaxf((acc[nt][0] - m0) * rs0 * g0 + bb0, 0.f);
            float v1 = fmaxf((acc[nt][1] - m0) * rs0 * g1 + bb1, 0.f);
            float v2 = fmaxf((acc[nt][2] - m1) * rs1 * g0 + bb0, 0.f);
            float v3 = fmaxf((acc[nt][3] - m1) * rs1 * g1 + bb1, 0.f);
            *(float2*)(g_roi + (size_t)gr0 * 128 + c) = make_float2(v0, v1);
            *(float2*)(g_roi + (size_t)gr1 * 128 + c) = make_float2(v2, v3);
        }
    }
}

// ---------------- k/v at the 250 sample points (coalesced weights) ------------
__global__ __launch_bounds__(256)
void kv_kernel(const float* __restrict__ fmap,
               const float* __restrict__ key_g, const float* __restrict__ key_beta,
               const float* __restrict__ key_m, const float* __restrict__ key_v,
               const float* __restrict__ val_b) {
    __shared__ float fc_s[25 * 129];
    const int b = blockIdx.x, r = blockIdx.y;
    const int tid = threadIdx.x;
    for (int i = tid; i < 25 * 128; i += 256) {
        int c = i / 25, pos = i % 25;
        fc_s[pos * 129 + c] = fmap[((b * 128 + c) * 40 + 4 * r) * 100 + 4 * pos];
    }
    __syncthreads();
    for (int i = tid; i < 25 * 128; i += 256) {
        int o = i & 127, pos = i >> 7;
        float ka = 0.f, va = 0.f;
#pragma unroll 4
        for (int c = 0; c < 128; c++) {
            float xv = fc_s[pos * 129 + c];
            ka = fmaf(g_kwT[c * 128 + o], xv, ka);
            va = fmaf(g_vwT[c * 128 + o], xv, va);
        }
        float sc = key_g[o] * rsqrtf(key_v[o] + EPS);
        float kb = key_beta[o] - key_m[o] * sc;
        float kk = fmaf(ka, sc, kb);
        int l = r * 25 + pos;
        g_k16[((size_t)b * LPAD + l) * CC + o] = relu_h(kk);
        g_v16[((size_t)b * CC + o) * LPAD + l] = __float2half_rn(va + val_b[o]);
    }
}

// ---------------- attention via fp16 mma: CTA = (b, 32 priors) ----------------
__global__ __launch_bounds__(128)
void attn_mma(const float* __restrict__ q_w, const float* __restrict__ q_b,
              const float* __restrict__ gate_w, const float* __restrict__ gate_b,
              float* __restrict__ out) {
    __shared__ __align__(16) __half q_s[32 * 136];
    __shared__ __align__(16) __half ph_s[32 * 264];
    __shared__ float mx_s[2][32];
    __shared__ float sm_s[2][32];

    const int b = blockIdx.x, p0g = blockIdx.y * 32;
    const int tid = threadIdx.x, lane = tid & 31, wid = tid >> 5;
    const int wm = wid & 1, wn = wid >> 1;
    const int row = wm * 16 + (lane >> 2);

    for (int i = tid; i < 32 * 128; i += 128) {
        int p = i >> 7, f = i & 127;
        float qq = fmaf(g_roi[((size_t)b * NP + p0g + p) * 128 + f],
                        q_w[p0g + p], q_b[p0g + p]);
        q_s[p * 136 + f] = relu_h(qq);
    }
    __syncthreads();

    float acc[16][4];
#pragma unroll
    for (int nt = 0; nt < 16; nt++)
#pragma unroll
        for (int j = 0; j < 4; j++) acc[nt][j] = 0.f;

    const __half* kg = g_k16 + (size_t)b * LPAD * CC;
#pragma unroll
    for (int k8 = 0; k8 < 8; k8++) {
        int k0 = k8 * 16;
        uint4 a;
        a.x = *(const uint32_t*)&q_s[row * 136 + k0 + 2 * (lane & 3)];
        a.y = *(const uint32_t*)&q_s[(row + 8) * 136 + k0 + 2 * (lane & 3)];
        a.z = *(const uint32_t*)&q_s[row * 136 + k0 + 8 + 2 * (lane & 3)];
        a.w = *(const uint32_t*)&q_s[(row + 8) * 136 + k0 + 8 + 2 * (lane & 3)];
#pragma unroll
        for (int nt = 0; nt < 16; nt++) {
            int l = wn * 128 + nt * 8 + (lane >> 2);
            const __half* kr = kg + (size_t)l * CC + k0 + 2 * (lane & 3);
            uint32_t b0 = *(const uint32_t*)kr;
            uint32_t b1 = *(const uint32_t*)(kr + 8);
            mma_f16(acc[nt], a, b0, b1);
        }
    }

    const float scale = 0.08838834764831845f;
    float m0 = -1e30f, m1 = -1e30f;
#pragma unroll
    for (int nt = 0; nt < 16; nt++) {
#pragma unroll
        for (int j = 0; j < 4; j++) acc[nt][j] *= scale;
        m0 = fmaxf(m0, fmaxf(acc[nt][0], acc[nt][1]));
        m1 = fmaxf(m1, fmaxf(acc[nt][2], acc[nt][3]));
    }
    m0 = fmaxf(m0, __shfl_xor_sync(~0u, m0, 1)); m0 = fmaxf(m0, __shfl_xor_sync(~0u, m0, 2));
    m1 = fmaxf(m1, __shfl_xor_sync(~0u, m1, 1)); m1 = fmaxf(m1, __shfl_xor_sync(~0u, m1, 2));
    if ((lane & 3) == 0) {
        mx_s[wn][row] = m0;
        mx_s[wn][row + 8] = m1;
    }
    __syncthreads();
    float M0 = fmaxf(mx_s[0][row], mx_s[1][row]);
    float M1 = fmaxf(mx_s[0][row + 8], mx_s[1][row + 8]);

    float s0 = 0.f, s1 = 0.f;
#pragma unroll
    for (int nt = 0; nt < 16; nt++) {
        int lb = wn * 128 + nt * 8 + 2 * (lane & 3);
        float e0 = (lb     < LL) ? __expf(acc[nt][0] - M0) : 0.f;
        float e1 = (lb + 1 < LL) ? __expf(acc[nt][1] - M0) : 0.f;
        float e2 = (lb     < LL) ? __expf(acc[nt][2] - M1) : 0.f;
        float e3 = (lb + 1 < LL) ? __expf(acc[nt][3] - M1) : 0.f;
        s0 += e0 + e1; s1 += e2 + e3;
        __half2 h01 = __floats2half2_rn(e0, e1);
        __half2 h23 = __floats2half2_rn(e2, e3);
        *(__half2*)&ph_s[row * 264 + lb]       = h01;
        *(__half2*)&ph_s[(row + 8) * 264 + lb] = h23;
    }
    s0 += __shfl_xor_sync(~0u, s0, 1); s0 += __shfl_xor_sync(~0u, s0, 2);
    s1 += __shfl_xor_sync(~0u, s1, 1); s1 += __shfl_xor_sync(~0u, s1, 2);
    if ((lane & 3) == 0) {
        sm_s[wn][row] = s0;
        sm_s[wn][row + 8] = s1;
    }
    __syncthreads();
    float inv0 = 1.f / (sm_s[0][row] + sm_s[1][row]);
    float inv1 = 1.f / (sm_s[0][row + 8] + sm_s[1][row + 8]);

    float acc2[8][4];
#pragma unroll
    for (int ft = 0; ft < 8; ft++)
#pragma unroll
        for (int j = 0; j < 4; j++) acc2[ft][j] = 0.f;

    const __half* vg = g_v16 + (size_t)b * CC * LPAD;
#pragma unroll
    for (int ks = 0; ks < 16; ks++) {
        int k0 = ks * 16;
        uint4 a;
        a.x = *(const uint32_t*)&ph_s[row * 264 + k0 + 2 * (lane & 3)];
        a.y = *(const uint32_t*)&ph_s[(row + 8) * 264 + k0 + 2 * (lane & 3)];
        a.z = *(const uint32_t*)&ph_s[row * 264 + k0 + 8 + 2 * (lane & 3)];
        a.w = *(const uint32_t*)&ph_s[(row + 8) * 264 + k0 + 8 + 2 * (lane & 3)];
#pragma unroll
        for (int ft = 0; ft < 8; ft++) {
            int f = wn * 64 + ft * 8 + (lane >> 2);
            const __half* vr = vg + (size_t)f * LPAD + k0 + 2 * (lane & 3);
            uint32_t b0 = *(const uint32_t*)vr;
            uint32_t b1 = *(const uint32_t*)(vr + 8);
            mma_f16(acc2[ft], a, b0, b1);
        }
    }

    int gp0 = p0g + row, gp1 = gp0 + 8;
    float gw0 = gate_w[gp0], gb0 = gate_b[gp0];
    float gw1 = gate_w[gp1], gb1 = gate_b[gp1];
#pragma unroll
    for (int ft = 0; ft < 8; ft++) {
        int fb = wn * 64 + ft * 8 + 2 * (lane & 3);
        size_t o0 = ((size_t)b * NP + gp0) * 128 + fb;
        size_t o1 = ((size_t)b * NP + gp1) * 128 + fb;
        float c00 = g_roi[o0]     + fmaf(acc2[ft][0] * inv0, gw0, gb0);
        float c01 = g_roi[o0 + 1] + fmaf(acc2[ft][1] * inv0, gw0, gb0);
        float c10 = g_roi[o1]     + fmaf(acc2[ft][2] * inv1, gw1, gb1);
        float c11 = g_roi[o1 + 1] + fmaf(acc2[ft][3] * inv1, gw1, gb1);
        *(float2*)(out + o0) = make_float2(c00, c01);
        *(float2*)(out + o1) = make_float2(c10, c11);
    }
}

// ---------------- host launcher ----------------------------------------------
extern "C" void kernel_launch(void* const* d_in, const int* in_sizes, int n_in,
                              void* d_out, int out_size) {
    (void)in_sizes; (void)n_in; (void)out_size;
    const float* roi0   = (const float*)d_in[0];
    const float* roi1   = (const float*)d_in[1];
    const float* roi2   = (const float*)d_in[2];
    const float* fmap   = (const float*)d_in[3];
    const float* conv_w = (const float*)d_in[4];
    const float* conv_g = (const float*)d_in[5];
    const float* conv_b = (const float*)d_in[6];
    const float* conv_m = (const float*)d_in[7];
    const float* conv_v = (const float*)d_in[8];
    const float* cat_w  = (const float*)d_in[9];
    const float* cat_g  = (const float*)d_in[10];
    const float* cat_b  = (const float*)d_in[11];
    const float* cat_m  = (const float*)d_in[12];
    const float* cat_v  = (const float*)d_in[13];
    const float* fc_w   = (const float*)d_in[14];
    const float* fc_b   = (const float*)d_in[15];
    const float* ln_g   = (const float*)d_in[16];
    const float* ln_b   = (const float*)d_in[17];
    const float* key_w  = (const float*)d_in[18];
    const float* key_g  = (const float*)d_in[19];
    const float* key_bt = (const float*)d_in[20];
    const float* key_m  = (const float*)d_in[21];
    const float* key_v  = (const float*)d_in[22];
    const float* q_w    = (const float*)d_in[23];
    const float* q_b    = (const float*)d_in[24];
    const float* val_w  = (const float*)d_in[25];
    const float* val_b  = (const float*)d_in[26];
    const float* gate_w = (const float*)d_in[27];
    const float* gate_b = (const float*)d_in[28];
    float* out = (float*)d_out;

    __half *x16, *cat1, *cat2, *wfL, *wfC;
    cudaGetSymbolAddress((void**)&x16,  g_x16);
    cudaGetSymbolAddress((void**)&cat1, g_cat1);
    cudaGetSymbolAddress((void**)&cat2, g_cat2);
    cudaGetSymbolAddress((void**)&wfL,  g_wfL);
    cudaGetSymbolAddress((void**)&wfC,  g_wfC);

    cudaFuncSetAttribute(fc_ln_relu, cudaFuncAttributeMaxDynamicSharedMemorySize,
                         FC_SMEM_BYTES);

    // (1) prep, (2) kv, (3) input transpose
    const int PREP_TOTAL = 3 * TLV + 2 * THC + TFC + 2 * TKV;
    prep_all<<<(PREP_TOTAL + 255) / 256, 256>>>(conv_w, cat_w, fc_w, key_w, val_w);
    kv_kernel<<<dim3(BB, 10), 256>>>(fmap, key_g, key_bt, key_m, key_v, val_b);
    cvt_roi<<<dim3(NTOT, 3), 256>>>(roi0, roi1, roi2);

    // (4) level convs (y = level), (5) cat conv (y = channel half)
    conv_mma<128, 192><<<dim3(NTOT / 8, 3), 256>>>(
        x16, wfL, conv_g, conv_b, conv_m, conv_v, cat1, NTOT * CC * NSS);
    conv_mma<192, 128><<<dim3(NTOT / 8, 2), 256>>>(
        cat1, wfC, cat_g, cat_b, cat_m, cat_v, cat2, 0);

    // (6) FC+LN, (7) attention
    fc_ln_relu<<<192, 128, FC_SMEM_BYTES>>>(fc_b, ln_g, ln_b);
    attn_mma<<<dim3(BB, NP / 32), 128>>>(q_w, q_b, gate_w, gate_b, out);
}

// round 17
// speedup vs baseline: 7.5705x; 1.0125x over previous
#include <cuda_runtime.h>
#include <cuda_fp16.h>
#include <cstdint>

#define BB    32
#define NP    192
#define CC    128
#define NSS   36
#define FCH   128
#define EPS   1e-5f
#define NTOT  (BB*NP)      // 6144
#define LL    250
#define LPAD  256
#define KFC   (CC*NSS)     // 4608

// ---------------- scratch (device globals; no runtime allocation) -------------
__device__ __align__(16) __half g_x16 [3 * NTOT * CC * NSS];  // fp16 roi, [n][s][ci]
__device__ __align__(16) __half g_cat1[NTOT * NSS * 192];     // level out, [n][s][c]
__device__ __align__(16) __half g_cat2[NTOT * NSS * CC];      // cat out,  [n][s][c]
__device__ float  g_roi [BB * NP * FCH];                      // fc+LN+ReLU (fp32)
__device__ __align__(16) __half g_k16[BB * LPAD * CC];        // keys  [b][l][f]
__device__ __align__(16) __half g_v16[BB * CC * LPAD];        // vals  [b][f][l]
__device__ __align__(16) __half g_fcw16[FCH * KFC];           // fc_w fp16 [f][k']
__device__ __align__(16) __half g_wfL [3 * 8 * 9 * 4 * 32 * 8];   // level weight frags
__device__ __align__(16) __half g_wfC [2 * 12 * 9 * 4 * 32 * 8];  // cat frags, 2 halves
__device__ float g_kwT[CC * CC];                              // key_w transposed [c][o]
__device__ float g_vwT[CC * CC];                              // val_w transposed [c][o]

// ---------------- helpers ----------------------------------------------------
__device__ __forceinline__ uint32_t smem_u32(const void* p) {
    uint32_t a;
    asm("{ .reg .u64 t; cvta.to.shared.u64 t, %1; cvt.u32.u64 %0, t; }"
        : "=r"(a) : "l"(p));
    return a;
}
__device__ __forceinline__ void cp16(uint32_t s, const void* g) {
    asm volatile("cp.async.cg.shared.global [%0], [%1], 16;" :: "r"(s), "l"(g));
}
__device__ __forceinline__ void mma_f16(float* c, const uint4& a,
                                        uint32_t b0, uint32_t b1) {
    asm volatile("mma.sync.aligned.m16n8k16.row.col.f32.f16.f16.f32 "
                 "{%0,%1,%2,%3}, {%4,%5,%6,%7}, {%8,%9}, {%0,%1,%2,%3};"
                 : "+f"(c[0]), "+f"(c[1]), "+f"(c[2]), "+f"(c[3])
                 : "r"(a.x), "r"(a.y), "r"(a.z), "r"(a.w), "r"(b0), "r"(b1));
}
__device__ __forceinline__ void ldsm_x2(uint32_t& b0, uint32_t& b1, uint32_t addr) {
    asm volatile("ldmatrix.sync.aligned.m8n8.x2.shared.b16 {%0,%1}, [%2];"
                 : "=r"(b0), "=r"(b1) : "r"(addr));
}
__device__ __forceinline__ void ldsm_x4(uint32_t& b0, uint32_t& b1,
                                        uint32_t& b2, uint32_t& b3, uint32_t addr) {
    asm volatile("ldmatrix.sync.aligned.m8n8.x4.shared.b16 {%0,%1,%2,%3}, [%4];"
                 : "=r"(b0), "=r"(b1), "=r"(b2), "=r"(b3) : "r"(addr));
}
__device__ __forceinline__ __half relu_h(float v) {
    return __float2half_rn(v > 0.f ? v : 0.f);
}

// ---------------- input transpose + fp16: x[n][ci][s] -> g_x16[n][s][ci] ------
__global__ __launch_bounds__(256)
void cvt_roi(const float* __restrict__ r0, const float* __restrict__ r1,
             const float* __restrict__ r2) {
    __shared__ float t_s[128 * 37];
    const int n = blockIdx.x, lvl = blockIdx.y, tid = threadIdx.x;
    const float* src = ((lvl == 0) ? r0 : (lvl == 1) ? r1 : r2) + (size_t)n * CC * NSS;
    __half* dst = g_x16 + ((size_t)lvl * NTOT + n) * NSS * CC;
    for (int i = tid; i < 128 * 36; i += 256) {
        int ci = i / 36, s = i % 36;
        t_s[ci * 37 + s] = src[i];
    }
    __syncthreads();
    // vectorized: 8 ci per thread -> STG.128
    for (int i = tid; i < 576; i += 256) {
        int s = i >> 4, cq = (i & 15) * 8;
        __half h[8];
#pragma unroll
        for (int j = 0; j < 8; j++)
            h[j] = __float2half_rn(t_s[(cq + j) * 37 + s]);
        *(uint4*)(dst + s * 128 + cq) = *(const uint4*)h;
    }
}

// ---------------- merged prep: weight frags + fc_w + kv weight transpose -----
__device__ __forceinline__ void prep_w_elem(const float* __restrict__ w,
                                            __half* __restrict__ dst,
                                            int idx, int CIN,
                                            int blk, int wstride, int total) {
    int hh = idx & 7, lane = (idx >> 3) & 31;
    int t3 = idx >> 8;
    int mt = t3 % 4, g = (t3 / 4) % 9, cb = t3 / 36;
    int j = hh >> 1, inner = hh & 1;
    int r  = (lane >> 2) + 8 * (j & 1);
    int kk = 2 * (lane & 3) + inner + 8 * (j >> 1);
    int m  = mt * 16 + r;
    int ci = cb * 16 + kk;
    dst[(size_t)blk * total + idx] =
        __float2half_rn(w[(size_t)blk * wstride + (size_t)m * (CIN * 9) + ci * 9 + g]);
}

#define TLV (8*9*4*32*8)     // 73728 per level block
#define THC (12*9*4*32*8)    // 110592 per cat half block
#define TFC (FCH*KFC)
#define TKV (CC*CC)

__global__ void prep_all(const float* __restrict__ conv_w,
                         const float* __restrict__ cat_w,
                         const float* __restrict__ fc_w,
                         const float* __restrict__ key_w,
                         const float* __restrict__ val_w) {
    int idx = blockIdx.x * 256 + threadIdx.x;
    if (idx < 3 * TLV) {
        prep_w_elem(conv_w, g_wfL, idx % TLV, 128, idx / TLV, 64 * 128 * 9, TLV);
    } else if (idx < 3 * TLV + 2 * THC) {
        int i = idx - 3 * TLV;
        prep_w_elem(cat_w, g_wfC, i % THC, 192, i / THC, 64 * 192 * 9, THC);
    } else if (idx < 3 * TLV + 2 * THC + TFC) {
        int i = idx - 3 * TLV - 2 * THC;
        int f = i / KFC, kp = i % KFC;
        int s = kp >> 7, c = kp & 127;
        g_fcw16[i] = __float2half_rn(fc_w[(size_t)f * KFC + c * NSS + s]);
    } else if (idx < 3 * TLV + 2 * THC + TFC + 2 * TKV) {
        int i = idx - 3 * TLV - 2 * THC - TFC;
        int which = i / TKV; i %= TKV;
        int c = i >> 7, o = i & 127;
        if (which == 0) g_kwT[i] = key_w[o * 128 + c];
        else            g_vwT[i] = val_w[o * 128 + c];
    }
}

// ---------------- conv9 + folded BN + ReLU via fp16 mma.sync -----------------
// Barrier-free per-warp pipeline; B-frags software-pipelined across g.
template<int CIN, int CSTRIDE>
__global__ __launch_bounds__(256, 2)
void conv_mma(const __half* __restrict__ xg, const __half* __restrict__ wfrag_,
              const float* __restrict__ bng, const float* __restrict__ bnb,
              const float* __restrict__ bnm, const float* __restrict__ bnv,
              __half* __restrict__ out, int x_blkstride) {
    constexpr int NCH  = CIN / 16;
    constexpr int SSTR = 44 * 24;                    // halves per sample window
    constexpr int CHF  = 9 * 4 * 32;                 // uint4 frags per chunk

    __shared__ __align__(16) __half x_s[2][8 * SSTR];

    const int tid  = threadIdx.x;
    const int wid  = tid >> 5, lane = tid & 31;
    const int yb   = blockIdx.y;
    const __half* x = xg + (size_t)yb * x_blkstride;
    const uint4* wf4 = (const uint4*)(wfrag_ + (size_t)yb * NCH * CHF * 8);
    const int c0   = yb * 64;
    bng += c0; bnb += c0; bnm += c0; bnv += c0;

    const int samp = wid;
    const int n0   = blockIdx.x * 8;
    const int nidx = n0 + samp;
    const __half* xsrc = x + (size_t)nidx * 36 * CIN;

    uint32_t xsu[2];
#pragma unroll
    for (int s = 0; s < 2; s++) xsu[s] = smem_u32(&x_s[s][samp * SSTR]);

    // zero own buffers
    {
        uint4 z = make_uint4(0, 0, 0, 0);
#pragma unroll 4
        for (int i = lane; i < SSTR / 8; i += 32) {
            *(uint4*)&x_s[0][samp * SSTR + i * 8] = z;
            *(uint4*)&x_s[1][samp * SSTR + i * 8] = z;
        }
    }

    // ldmatrix.x4 addresses for nt-pairs (0,1) and (2,3)
    uint32_t aoff4[2];
#pragma unroll
    for (int p = 0; p < 2; p++) {
        int r = lane & 7, sel = (lane >> 3) & 3;
        int tile = 2 * p + (sel >> 1), khi = sel & 1;
        int pos = tile * 8 + r;
        aoff4[p] = (uint32_t)pos * 48 + (khi ? 16u : 0u);
    }
    uint32_t aoff2;
    {
        int n = 32 + (lane & 7);
        if (n > 35) n = 35;
        aoff2 = (uint32_t)n * 48 + (((lane >> 3) & 1) ? 16u : 0u);
    }

    float acc[4][5][4];
#pragma unroll
    for (int mt = 0; mt < 4; mt++)
#pragma unroll
        for (int nt = 0; nt < 5; nt++)
#pragma unroll
            for (int j = 0; j < 4; j++) acc[mt][nt][j] = 0.f;

    auto stage = [&](int cb) {
        const uint32_t base = xsu[cb & 1];
#pragma unroll 3
        for (int i = lane; i < 72; i += 32) {
            int hh = i & 1, s = i >> 1;
            cp16(base + (uint32_t)((s + 4) * 24 + hh * 8) * 2,
                 xsrc + (size_t)s * CIN + cb * 16 + hh * 8);
        }
        asm volatile("cp.async.commit_group;");
    };

    __syncwarp();
    stage(0);

    for (int cb = 0; cb < NCH; cb++) {
        if (cb) __syncwarp();
        if (cb + 1 < NCH) {
            stage(cb + 1);
            asm volatile("cp.async.wait_group 1;");
        } else {
            asm volatile("cp.async.wait_group 0;");
        }
        __syncwarp();

        const uint32_t xb = xsu[cb & 1];
        const uint4* wfc = wf4 + (size_t)cb * CHF;

        uint32_t b[2][5][2];
        // preload g=0 B fragments
        ldsm_x4(b[0][0][0], b[0][0][1], b[0][1][0], b[0][1][1], xb + aoff4[0]);
        ldsm_x4(b[0][2][0], b[0][2][1], b[0][3][0], b[0][3][1], xb + aoff4[1]);
        ldsm_x2(b[0][4][0], b[0][4][1], xb + aoff2);
#pragma unroll
        for (int g = 0; g < 9; g++) {
            const int cur = g & 1, nxt = cur ^ 1;
            uint4 af[4];
#pragma unroll
            for (int mt = 0; mt < 4; mt++)
                af[mt] = __ldg(&wfc[(g * 4 + mt) * 32 + lane]);
            if (g < 8) {     // issue next-g LDSMs before this g's MMAs
                uint32_t o = (uint32_t)(g + 1) * 48;
                ldsm_x4(b[nxt][0][0], b[nxt][0][1], b[nxt][1][0], b[nxt][1][1],
                        xb + aoff4[0] + o);
                ldsm_x4(b[nxt][2][0], b[nxt][2][1], b[nxt][3][0], b[nxt][3][1],
                        xb + aoff4[1] + o);
                ldsm_x2(b[nxt][4][0], b[nxt][4][1], xb + aoff2 + o);
            }
#pragma unroll
            for (int nt = 0; nt < 5; nt++)
#pragma unroll
                for (int mt = 0; mt < 4; mt++)
                    mma_f16(acc[mt][nt], af[mt], b[cur][nt][0], b[cur][nt][1]);
        }
    }

    // epilogue: folded BN + ReLU -> fp16 [n][s][c] (direct stores)
#pragma unroll
    for (int mt = 0; mt < 4; mt++) {
        int cobase = mt * 16 + (lane >> 2);
#pragma unroll
        for (int h = 0; h < 2; h++) {
            int co = cobase + 8 * h;
            float sc = bng[co] * rsqrtf(bnv[co] + EPS);
            float bi = bnb[co] - bnm[co] * sc;
#pragma unroll
            for (int nt = 0; nt < 5; nt++) {
                int s0 = nt * 8 + 2 * (lane & 3);
                if (s0 < 36) {
                    out[((size_t)nidx * 36 + s0) * CSTRIDE + c0 + co] =
                        relu_h(fmaf(acc[mt][nt][2 * h], sc, bi));
                    out[((size_t)nidx * 36 + s0 + 1) * CSTRIDE + c0 + co] =
                        relu_h(fmaf(acc[mt][nt][2 * h + 1], sc, bi));
                }
            }
        }
    }
}

// ---------------- FC via fp16 mma.sync + cp.async pipeline, fused LN+ReLU ----
#define FC_A(buf, s, r)  ((((buf) * 2 + (s)) * 32 + (r)) * 40)
#define FC_B(buf, s, f)  (5120 + (((buf) * 2 + (s)) * 128 + (f)) * 40)
#define FC_SMEM_BYTES    ((5120 + 20480) * 2)

__global__ __launch_bounds__(128, 1)
void fc_ln_relu(const float* __restrict__ fc_b, const float* __restrict__ ln_g,
                const float* __restrict__ ln_b) {
    extern __shared__ __align__(16) __half fcsm[];
    const uint32_t smb = smem_u32(fcsm);

    const int tid = threadIdx.x, lane = tid & 31, wid = tid >> 5;
    const int mw = wid & 1, kw = wid >> 1;
    const int n0 = blockIdx.x * 32;
    const int r0 = mw * 16 + (lane >> 2);
    const int q2 = 2 * (lane & 3);

    float acc[16][4];
#pragma unroll
    for (int nt = 0; nt < 16; nt++)
#pragma unroll
        for (int j = 0; j < 4; j++) acc[nt][j] = 0.f;

    auto stage = [&](int ch) {
        int buf = ch & 1;
#pragma unroll
        for (int it = 0; it < 2; it++) {
            int i = tid + it * 128;
            int q = i & 3, r = (i >> 2) & 31, s = i >> 7;
            cp16(smb + (uint32_t)(FC_A(buf, s, r) + q * 8) * 2,
                 g_cat2 + (size_t)(n0 + r) * KFC + ch * 64 + s * 32 + q * 8);
        }
#pragma unroll
        for (int it = 0; it < 8; it++) {
            int i = tid + it * 128;
            int q = i & 3, f = (i >> 2) & 127, s = i >> 9;
            cp16(smb + (uint32_t)(FC_B(buf, s, f) + q * 8) * 2,
                 g_fcw16 + (size_t)f * KFC + ch * 64 + s * 32 + q * 8);
        }
        asm volatile("cp.async.commit_group;");
    };

    stage(0);
    for (int ch = 0; ch < 72; ch++) {
        if (ch + 1 < 72) {
            stage(ch + 1);
            asm volatile("cp.async.wait_group 1;");
        } else {
            asm volatile("cp.async.wait_group 0;");
        }
        __syncthreads();

        int buf = ch & 1;
#pragma unroll
        for (int g = 0; g < 2; g++) {
            int kk = g * 16 + q2;
            uint4 a;
            a.x = *(const uint32_t*)&fcsm[FC_A(buf, kw, r0) + kk];
            a.y = *(const uint32_t*)&fcsm[FC_A(buf, kw, r0 + 8) + kk];
            a.z = *(const uint32_t*)&fcsm[FC_A(buf, kw, r0) + kk + 8];
            a.w = *(const uint32_t*)&fcsm[FC_A(buf, kw, r0 + 8) + kk + 8];
#pragma unroll
            for (int nt = 0; nt < 16; nt++) {
                int f = nt * 8 + (lane >> 2);
                uint32_t b0 = *(const uint32_t*)&fcsm[FC_B(buf, kw, f) + kk];
                uint32_t b1 = *(const uint32_t*)&fcsm[FC_B(buf, kw, f) + kk + 8];
                mma_f16(acc[nt], a, b0, b1);
            }
        }
        __syncthreads();
    }

    float* red = (float*)fcsm;
    if (kw == 1) {
#pragma unroll
        for (int nt = 0; nt < 16; nt++)
#pragma unroll
            for (int j = 0; j < 4; j++) {
                int r = mw * 16 + (lane >> 2) + 8 * (j >> 1);
                int c = nt * 8 + 2 * (lane & 3) + (j & 1);
                red[r * 130 + c] = acc[nt][j];
            }
    }
    __syncthreads();
    if (kw == 0) {
#pragma unroll
        for (int nt = 0; nt < 16; nt++) {
            int cb = nt * 8 + 2 * (lane & 3);
            int rA = mw * 16 + (lane >> 2), rB = rA + 8;
            acc[nt][0] += red[rA * 130 + cb]     + fc_b[cb];
            acc[nt][1] += red[rA * 130 + cb + 1] + fc_b[cb + 1];
            acc[nt][2] += red[rB * 130 + cb]     + fc_b[cb];
            acc[nt][3] += red[rB * 130 + cb + 1] + fc_b[cb + 1];
        }
        float s0 = 0.f, s1 = 0.f;
#pragma unroll
        for (int nt = 0; nt < 16; nt++) {
            s0 += acc[nt][0] + acc[nt][1];
            s1 += acc[nt][2] + acc[nt][3];
        }
        s0 += __shfl_xor_sync(~0u, s0, 1); s0 += __shfl_xor_sync(~0u, s0, 2);
        s1 += __shfl_xor_sync(~0u, s1, 1); s1 += __shfl_xor_sync(~0u, s1, 2);
        float m0 = s0 * (1.f / 128.f), m1 = s1 * (1.f / 128.f);
        float q0 = 0.f, q1 = 0.f;
#pragma unroll
        for (int nt = 0; nt < 16; nt++) {
            float d0 = acc[nt][0] - m0, d1 = acc[nt][1] - m0;
            float d2 = acc[nt][2] - m1, d3 = acc[nt][3] - m1;
            q0 += d0 * d0 + d1 * d1;
            q1 += d2 * d2 + d3 * d3;
        }
        q0 += __shfl_xor_sync(~0u, q0, 1); q0 += __shfl_xor_sync(~0u, q0, 2);
        q1 += __shfl_xor_sync(~0u, q1, 1); q1 += __shfl_xor_sync(~0u, q1, 2);
        float rs0 = rsqrtf(q0 * (1.f / 128.f) + EPS);
        float rs1 = rsqrtf(q1 * (1.f / 128.f) + EPS);
        int gr0 = n0 + mw * 16 + (lane >> 2), gr1 = gr0 + 8;
#pragma unroll
        for (int nt = 0; nt < 16; nt++) {
            int c = nt * 8 + 2 * (lane & 3);
            float g0 = ln_g[c], g1 = ln_g[c + 1], bb0 = ln_b[c], bb1 = ln_b[c + 1];
            float v0 = fmaxf((acc[nt][0] - m0) * rs0 * g0 + bb0, 0.f);
            float v1 = fmaxf((acc[nt][1] - m0) * rs0 * g1 + bb1, 0.f);
            float v2 = fmaxf((acc[nt][2] - m1) * rs1 * g0 + bb0, 0.f);
            float v3 = fmaxf((acc[nt][3] - m1) * rs1 * g1 + bb1, 0.f);
            *(float2*)(g_roi + (size_t)gr0 * 128 + c) = make_float2(v0, v1);
            *(float2*)(g_roi + (size_t)gr1 * 128 + c) = make_float2(v2, v3);
        }
    }
}

// ---------------- k/v at the 250 sample points (coalesced weights) ------------
__global__ __launch_bounds__(256)
void kv_kernel(const float* __restrict__ fmap,
               const float* __restrict__ key_g, const float* __restrict__ key_beta,
               const float* __restrict__ key_m, const float* __restrict__ key_v,
               const float* __restrict__ val_b) {
    __shared__ float fc_s[25 * 129];
    const int b = blockIdx.x, r = blockIdx.y;
    const int tid = threadIdx.x;
    for (int i = tid; i < 25 * 128; i += 256) {
        int c = i / 25, pos = i % 25;
        fc_s[pos * 129 + c] = fmap[((b * 128 + c) * 40 + 4 * r) * 100 + 4 * pos];
    }
    __syncthreads();
    for (int i = tid; i < 25 * 128; i += 256) {
        int o = i & 127, pos = i >> 7;
        float ka = 0.f, va = 0.f;
#pragma unroll 4
        for (int c = 0; c < 128; c++) {
            float xv = fc_s[pos * 129 + c];
            ka = fmaf(g_kwT[c * 128 + o], xv, ka);
            va = fmaf(g_vwT[c * 128 + o], xv, va);
        }
        float sc = key_g[o] * rsqrtf(key_v[o] + EPS);
        float kb = key_beta[o] - key_m[o] * sc;
        float kk = fmaf(ka, sc, kb);
        int l = r * 25 + pos;
        g_k16[((size_t)b * LPAD + l) * CC + o] = relu_h(kk);
        g_v16[((size_t)b * CC + o) * LPAD + l] = __float2half_rn(va + val_b[o]);
    }
}

// ---------------- attention via fp16 mma: CTA = (b, 32 priors) ----------------
__global__ __launch_bounds__(128)
void attn_mma(const float* __restrict__ q_w, const float* __restrict__ q_b,
              const float* __restrict__ gate_w, const float* __restrict__ gate_b,
              float* __restrict__ out) {
    __shared__ __align__(16) __half q_s[32 * 136];
    __shared__ __align__(16) __half ph_s[32 * 264];
    __shared__ float mx_s[2][32];
    __shared__ float sm_s[2][32];

    const int b = blockIdx.x, p0g = blockIdx.y * 32;
    const int tid = threadIdx.x, lane = tid & 31, wid = tid >> 5;
    const int wm = wid & 1, wn = wid >> 1;
    const int row = wm * 16 + (lane >> 2);

    for (int i = tid; i < 32 * 128; i += 128) {
        int p = i >> 7, f = i & 127;
        float qq = fmaf(g_roi[((size_t)b * NP + p0g + p) * 128 + f],
                        q_w[p0g + p], q_b[p0g + p]);
        q_s[p * 136 + f] = relu_h(qq);
    }
    __syncthreads();

    float acc[16][4];
#pragma unroll
    for (int nt = 0; nt < 16; nt++)
#pragma unroll
        for (int j = 0; j < 4; j++) acc[nt][j] = 0.f;

    const __half* kg = g_k16 + (size_t)b * LPAD * CC;
#pragma unroll
    for (int k8 = 0; k8 < 8; k8++) {
        int k0 = k8 * 16;
        uint4 a;
        a.x = *(const uint32_t*)&q_s[row * 136 + k0 + 2 * (lane & 3)];
        a.y = *(const uint32_t*)&q_s[(row + 8) * 136 + k0 + 2 * (lane & 3)];
        a.z = *(const uint32_t*)&q_s[row * 136 + k0 + 8 + 2 * (lane & 3)];
        a.w = *(const uint32_t*)&q_s[(row + 8) * 136 + k0 + 8 + 2 * (lane & 3)];
#pragma unroll
        for (int nt = 0; nt < 16; nt++) {
            int l = wn * 128 + nt * 8 + (lane >> 2);
            const __half* kr = kg + (size_t)l * CC + k0 + 2 * (lane & 3);
            uint32_t b0 = *(const uint32_t*)kr;
            uint32_t b1 = *(const uint32_t*)(kr + 8);
            mma_f16(acc[nt], a, b0, b1);
        }
    }

    const float scale = 0.08838834764831845f;
    float m0 = -1e30f, m1 = -1e30f;
#pragma unroll
    for (int nt = 0; nt < 16; nt++) {
#pragma unroll
        for (int j = 0; j < 4; j++) acc[nt][j] *= scale;
        m0 = fmaxf(m0, fmaxf(acc[nt][0], acc[nt][1]));
        m1 = fmaxf(m1, fmaxf(acc[nt][2], acc[nt][3]));
    }
    m0 = fmaxf(m0, __shfl_xor_sync(~0u, m0, 1)); m0 = fmaxf(m0, __shfl_xor_sync(~0u, m0, 2));
    m1 = fmaxf(m1, __shfl_xor_sync(~0u, m1, 1)); m1 = fmaxf(m1, __shfl_xor_sync(~0u, m1, 2));
    if ((lane & 3) == 0) {
        mx_s[wn][row] = m0;
        mx_s[wn][row + 8] = m1;
    }
    __syncthreads();
    float M0 = fmaxf(mx_s[0][row], mx_s[1][row]);
    float M1 = fmaxf(mx_s[0][row + 8], mx_s[1][row + 8]);

    float s0 = 0.f, s1 = 0.f;
#pragma unroll
    for (int nt = 0; nt < 16; nt++) {
        int lb = wn * 128 + nt * 8 + 2 * (lane & 3);
        float e0 = (lb     < LL) ? __expf(acc[nt][0] - M0) : 0.f;
        float e1 = (lb + 1 < LL) ? __expf(acc[nt][1] - M0) : 0.f;
        float e2 = (lb     < LL) ? __expf(acc[nt][2] - M1) : 0.f;
        float e3 = (lb + 1 < LL) ? __expf(acc[nt][3] - M1) : 0.f;
        s0 += e0 + e1; s1 += e2 + e3;
        __half2 h01 = __floats2half2_rn(e0, e1);
        __half2 h23 = __floats2half2_rn(e2, e3);
        *(__half2*)&ph_s[row * 264 + lb]       = h01;
        *(__half2*)&ph_s[(row + 8) * 264 + lb] = h23;
    }
    s0 += __shfl_xor_sync(~0u, s0, 1); s0 += __shfl_xor_sync(~0u, s0, 2);
    s1 += __shfl_xor_sync(~0u, s1, 1); s1 += __shfl_xor_sync(~0u, s1, 2);
    if ((lane & 3) == 0) {
        sm_s[wn][row] = s0;
        sm_s[wn][row + 8] = s1;
    }
    __syncthreads();
    float inv0 = 1.f / (sm_s[0][row] + sm_s[1][row]);
    float inv1 = 1.f / (sm_s[0][row + 8] + sm_s[1][row + 8]);

    float acc2[8][4];
#pragma unroll
    for (int ft = 0; ft < 8; ft++)
#pragma unroll
        for (int j = 0; j < 4; j++) acc2[ft][j] = 0.f;

    const __half* vg = g_v16 + (size_t)b * CC * LPAD;
#pragma unroll
    for (int ks = 0; ks < 16; ks++) {
        int k0 = ks * 16;
        uint4 a;
        a.x = *(const uint32_t*)&ph_s[row * 264 + k0 + 2 * (lane & 3)];
        a.y = *(const uint32_t*)&ph_s[(row + 8) * 264 + k0 + 2 * (lane & 3)];
        a.z = *(const uint32_t*)&ph_s[row * 264 + k0 + 8 + 2 * (lane & 3)];
        a.w = *(const uint32_t*)&ph_s[(row + 8) * 264 + k0 + 8 + 2 * (lane & 3)];
#pragma unroll
        for (int ft = 0; ft < 8; ft++) {
            int f = wn * 64 + ft * 8 + (lane >> 2);
            const __half* vr = vg + (size_t)f * LPAD + k0 + 2 * (lane & 3);
            uint32_t b0 = *(const uint32_t*)vr;
            uint32_t b1 = *(const uint32_t*)(vr + 8);
            mma_f16(acc2[ft], a, b0, b1);
        }
    }

    int gp0 = p0g + row, gp1 = gp0 + 8;
    float gw0 = gate_w[gp0], gb0 = gate_b[gp0];
    float gw1 = gate_w[gp1], gb1 = gate_b[gp1];
#pragma unroll
    for (int ft = 0; ft < 8; ft++) {
        int fb = wn * 64 + ft * 8 + 2 * (lane & 3);
        size_t o0 = ((size_t)b * NP + gp0) * 128 + fb;
        size_t o1 = ((size_t)b * NP + gp1) * 128 + fb;
        float c00 = g_roi[o0]     + fmaf(acc2[ft][0] * inv0, gw0, gb0);
        float c01 = g_roi[o0 + 1] + fmaf(acc2[ft][1] * inv0, gw0, gb0);
        float c10 = g_roi[o1]     + fmaf(acc2[ft][2] * inv1, gw1, gb1);
        float c11 = g_roi[o1 + 1] + fmaf(acc2[ft][3] * inv1, gw1, gb1);
        *(float2*)(out + o0) = make_float2(c00, c01);
        *(float2*)(out + o1) = make_float2(c10, c11);
    }
}

// ---------------- host launcher ----------------------------------------------
extern "C" void kernel_launch(void* const* d_in, const int* in_sizes, int n_in,
                              void* d_out, int out_size) {
    (void)in_sizes; (void)n_in; (void)out_size;
    const float* roi0   = (const float*)d_in[0];
    const float* roi1   = (const float*)d_in[1];
    const float* roi2   = (const float*)d_in[2];
    const float* fmap   = (const float*)d_in[3];
    const float* conv_w = (const float*)d_in[4];
    const float* conv_g = (const float*)d_in[5];
    const float* conv_b = (const float*)d_in[6];
    const float* conv_m = (const float*)d_in[7];
    const float* conv_v = (const float*)d_in[8];
    const float* cat_w  = (const float*)d_in[9];
    const float* cat_g  = (const float*)d_in[10];
    const float* cat_b  = (const float*)d_in[11];
    const float* cat_m  = (const float*)d_in[12];
    const float* cat_v  = (const float*)d_in[13];
    const float* fc_w   = (const float*)d_in[14];
    const float* fc_b   = (const float*)d_in[15];
    const float* ln_g   = (const float*)d_in[16];
    const float* ln_b   = (const float*)d_in[17];
    const float* key_w  = (const float*)d_in[18];
    const float* key_g  = (const float*)d_in[19];
    const float* key_bt = (const float*)d_in[20];
    const float* key_m  = (const float*)d_in[21];
    const float* key_v  = (const float*)d_in[22];
    const float* q_w    = (const float*)d_in[23];
    const float* q_b    = (const float*)d_in[24];
    const float* val_w  = (const float*)d_in[25];
    const float* val_b  = (const float*)d_in[26];
    const float* gate_w = (const float*)d_in[27];
    const float* gate_b = (const float*)d_in[28];
    float* out = (float*)d_out;

    __half *x16, *cat1, *cat2, *wfL, *wfC;
    cudaGetSymbolAddress((void**)&x16,  g_x16);
    cudaGetSymbolAddress((void**)&cat1, g_cat1);
    cudaGetSymbolAddress((void**)&cat2, g_cat2);
    cudaGetSymbolAddress((void**)&wfL,  g_wfL);
    cudaGetSymbolAddress((void**)&wfC,  g_wfC);

    cudaFuncSetAttribute(fc_ln_relu, cudaFuncAttributeMaxDynamicSharedMemorySize,
                         FC_SMEM_BYTES);

    // (1) prep, (2) kv, (3) input transpose
    const int PREP_TOTAL = 3 * TLV + 2 * THC + TFC + 2 * TKV;
    prep_all<<<(PREP_TOTAL + 255) / 256, 256>>>(conv_w, cat_w, fc_w, key_w, val_w);
    kv_kernel<<<dim3(BB, 10), 256>>>(fmap, key_g, key_bt, key_m, key_v, val_b);
    cvt_roi<<<dim3(NTOT, 3), 256>>>(roi0, roi1, roi2);

    // (4) level convs (y = level), (5) cat conv (y = channel half)
    conv_mma<128, 192><<<dim3(NTOT / 8, 3), 256>>>(
        x16, wfL, conv_g, conv_b, conv_m, conv_v, cat1, NTOT * CC * NSS);
    conv_mma<192, 128><<<dim3(NTOT / 8, 2), 256>>>(
        cat1, wfC, cat_g, cat_b, cat_m, cat_v, cat2, 0);

    // (6) FC+LN, (7) attention
    fc_ln_relu<<<192, 128, FC_SMEM_BYTES>>>(fc_b, ln_g, ln_b);
    attn_mma<<<dim3(BB, NP / 32), 128>>>(q_w, q_b, gate_w, gate_b, out);
}